// round 1
// baseline (speedup 1.0000x reference)
#include <cuda_runtime.h>
#include <math_constants.h>

// Problem constants (validated against runtime sizes in kernel_launch)
#define N_MAX 50000
#define E_MAX 800000
#define F1 128        // IN and H1*D1
#define F2 16         // H2*D2
#define SLOPE 0.2f

// ---------------- scratch (device globals; no allocation allowed) ----------
__device__ float g_ft1[N_MAX * F1];      // layer-1 features per node [N,2,64] flat
__device__ float g_num1[N_MAX * F1];     // layer-1 softmax-weighted numerator
__device__ float g_el1[N_MAX * 2];
__device__ float g_er1[N_MAX * 2];
__device__ float g_max1[N_MAX * 2];
__device__ float g_sum1[N_MAX * 2];
__device__ float g_ft2res[N_MAX * 32];   // [N][0:16]=ft2, [N][16:32]=res
__device__ float g_el2[N_MAX];
__device__ float g_er2[N_MAX];
__device__ float g_max2[N_MAX];
__device__ float g_sum2[N_MAX];
__device__ float g_num2[N_MAX * F2];
__device__ float g_Wc[F1 * 32];          // [W2 | Wres] packed, [128][32]

__device__ __forceinline__ float lrelu(float x) { return x > 0.f ? x : SLOPE * x; }
__device__ __forceinline__ float eluf(float x)  { return x > 0.f ? x : expf(x) - 1.f; }

// float atomic max; destination must be initialized to -inf
__device__ __forceinline__ void atomicMaxF(float* addr, float v) {
    if (v >= 0.f) atomicMax((int*)addr, __float_as_int(v));
    else          atomicMin((unsigned int*)addr, __float_as_uint(v));
}

// ---------------- kernels ----------------

__global__ void init_kernel(int n) {
    int i = blockIdx.x * blockDim.x + threadIdx.x;
    if (i < n * F1) g_num1[i] = 0.f;
    if (i < n * F2) g_num2[i] = 0.f;
    if (i < n * 2) { g_max1[i] = -CUDART_INF_F; g_sum1[i] = 0.f; }
    if (i < n)     { g_max2[i] = -CUDART_INF_F; g_sum2[i] = 0.f; }
}

__global__ void pack_wc_kernel(const float* __restrict__ W2,
                               const float* __restrict__ Wres) {
    int i = blockIdx.x * blockDim.x + threadIdx.x;  // 0 .. 128*32-1
    if (i >= F1 * 32) return;
    int k = i >> 5, c = i & 31;
    g_Wc[i] = (c < 16) ? W2[k * 16 + c] : Wres[k * 16 + (c - 16)];
}

// ft1 = h @ W1   (N x 128 @ 128 x 128). 8 rows per 128-thread block.
__global__ void gemm1_kernel(const float* __restrict__ h,
                             const float* __restrict__ W1, int n) {
    __shared__ float hs[8][F1];
    int t = threadIdx.x;
    int row0 = blockIdx.x * 8;
    for (int i = t; i < 8 * F1; i += 128) {
        int r = i >> 7, j = i & 127;
        int row = row0 + r;
        hs[r][j] = (row < n) ? h[row * F1 + j] : 0.f;
    }
    __syncthreads();
    float acc[8];
#pragma unroll
    for (int r = 0; r < 8; r++) acc[r] = 0.f;
    for (int k = 0; k < F1; k++) {
        float w = __ldg(&W1[k * F1 + t]);
#pragma unroll
        for (int r = 0; r < 8; r++) acc[r] += hs[r][k] * w;
    }
#pragma unroll
    for (int r = 0; r < 8; r++) {
        int row = row0 + r;
        if (row < n) g_ft1[row * F1 + t] = acc[r];
    }
}

// el1/er1 per node per head. One warp per node.
__global__ void eler1_kernel(const float* __restrict__ al1,
                             const float* __restrict__ ar1, int n) {
    int warp = (blockIdx.x * blockDim.x + threadIdx.x) >> 5;
    int lane = threadIdx.x & 31;
    if (warp >= n) return;
    const float* ft = g_ft1 + warp * F1;
    float f0 = ft[lane], f1 = ft[lane + 32], f2 = ft[lane + 64], f3 = ft[lane + 96];
    float el0 = f0 * al1[lane]      + f1 * al1[lane + 32];
    float er0 = f0 * ar1[lane]      + f1 * ar1[lane + 32];
    float el1v = f2 * al1[lane + 64] + f3 * al1[lane + 96];
    float er1v = f2 * ar1[lane + 64] + f3 * ar1[lane + 96];
#pragma unroll
    for (int o = 16; o; o >>= 1) {
        el0  += __shfl_xor_sync(0xffffffffu, el0, o);
        er0  += __shfl_xor_sync(0xffffffffu, er0, o);
        el1v += __shfl_xor_sync(0xffffffffu, el1v, o);
        er1v += __shfl_xor_sync(0xffffffffu, er1v, o);
    }
    if (lane == 0) {
        g_el1[warp * 2]     = el0;
        g_er1[warp * 2]     = er0;
        g_el1[warp * 2 + 1] = el1v;
        g_er1[warp * 2 + 1] = er1v;
    }
}

__global__ void edge_max1_kernel(const int* __restrict__ src,
                                 const int* __restrict__ dst, int e) {
    int i = blockIdx.x * blockDim.x + threadIdx.x;
    if (i >= e) return;
    int s = src[i], d = dst[i];
    atomicMaxF(&g_max1[d * 2],     lrelu(g_el1[s * 2]     + g_er1[d * 2]));
    atomicMaxF(&g_max1[d * 2 + 1], lrelu(g_el1[s * 2 + 1] + g_er1[d * 2 + 1]));
}

// one warp per edge: accumulate sum1 and num1 (128 features)
__global__ void edge_acc1_kernel(const int* __restrict__ src,
                                 const int* __restrict__ dst, int e) {
    int gw = (blockIdx.x * blockDim.x + threadIdx.x) >> 5;
    int lane = threadIdx.x & 31;
    if (gw >= e) return;
    int s = src[gw], d = dst[gw];
    float ex0 = expf(lrelu(g_el1[s * 2]     + g_er1[d * 2])     - g_max1[d * 2]);
    float ex1 = expf(lrelu(g_el1[s * 2 + 1] + g_er1[d * 2 + 1]) - g_max1[d * 2 + 1]);
    if (lane == 0) atomicAdd(&g_sum1[d * 2],     ex0);
    if (lane == 1) atomicAdd(&g_sum1[d * 2 + 1], ex1);
    const float* fts = g_ft1 + s * F1;
    float* nd = g_num1 + d * F1;
#pragma unroll
    for (int i2 = 0; i2 < 4; i2++) {
        int j = lane + i2 * 32;
        float exv = (j < 64) ? ex0 : ex1;
        atomicAdd(&nd[j], exv * fts[j]);
    }
}

// Fused: h1 = ELU(num1/sum1 + b1), then [ft2 | res] = h1 @ [W2 | Wres]
// 16 rows per 128-thread block; thread t -> col t&31, row group t>>5.
__global__ void gemm2_kernel(const float* __restrict__ b1, int n) {
    __shared__ float hs[16][F1];
    int t = threadIdx.x;
    int row0 = blockIdx.x * 16;
    for (int i = t; i < 16 * F1; i += 128) {
        int r = i >> 7, j = i & 127;
        int row = row0 + r;
        float v = 0.f;
        if (row < n) {
            float s = g_sum1[row * 2 + (j >> 6)];
            float x = (s > 0.f) ? g_num1[row * F1 + j] / s : 0.f;
            v = eluf(x + b1[j]);
        }
        hs[r][j] = v;
    }
    __syncthreads();
    int c = t & 31, g = t >> 5;
    float acc[4] = {0.f, 0.f, 0.f, 0.f};
    for (int k = 0; k < F1; k++) {
        float w = g_Wc[k * 32 + c];
#pragma unroll
        for (int rr = 0; rr < 4; rr++) acc[rr] += hs[g * 4 + rr][k] * w;
    }
#pragma unroll
    for (int rr = 0; rr < 4; rr++) {
        int row = row0 + g * 4 + rr;
        if (row < n) g_ft2res[row * 32 + c] = acc[rr];
    }
}

__global__ void eler2_kernel(const float* __restrict__ al2,
                             const float* __restrict__ ar2, int n) {
    int i = blockIdx.x * blockDim.x + threadIdx.x;
    if (i >= n) return;
    const float4* f = (const float4*)(g_ft2res + i * 32);
    float el = 0.f, er = 0.f;
#pragma unroll
    for (int q = 0; q < 4; q++) {
        float4 v = f[q];
        el += v.x * al2[q * 4] + v.y * al2[q * 4 + 1] + v.z * al2[q * 4 + 2] + v.w * al2[q * 4 + 3];
        er += v.x * ar2[q * 4] + v.y * ar2[q * 4 + 1] + v.z * ar2[q * 4 + 2] + v.w * ar2[q * 4 + 3];
    }
    g_el2[i] = el;
    g_er2[i] = er;
}

__global__ void edge_max2_kernel(const int* __restrict__ src,
                                 const int* __restrict__ dst, int e) {
    int i = blockIdx.x * blockDim.x + threadIdx.x;
    if (i >= e) return;
    int s = src[i], d = dst[i];
    atomicMaxF(&g_max2[d], lrelu(g_el2[s] + g_er2[d]));
}

// thread per (edge, feature j<16)
__global__ void edge_acc2_kernel(const int* __restrict__ src,
                                 const int* __restrict__ dst, int e) {
    int idx = blockIdx.x * blockDim.x + threadIdx.x;
    if (idx >= e * 16) return;
    int ed = idx >> 4, j = idx & 15;
    int s = src[ed], d = dst[ed];
    float ex = expf(lrelu(g_el2[s] + g_er2[d]) - g_max2[d]);
    if (j == 0) atomicAdd(&g_sum2[d], ex);
    atomicAdd(&g_num2[d * 16 + j], ex * g_ft2res[s * 32 + j]);
}

__global__ void finalize2_kernel(const float* __restrict__ b2,
                                 float* __restrict__ out, int n) {
    int idx = blockIdx.x * blockDim.x + threadIdx.x;
    if (idx >= n * 16) return;
    int row = idx >> 4, j = idx & 15;
    float s = g_sum2[row];
    float x = (s > 0.f) ? g_num2[idx] / s : 0.f;
    out[idx] = x + b2[j] + g_ft2res[row * 32 + 16 + j];
}

__global__ void alpha2_kernel(const int* __restrict__ src,
                              const int* __restrict__ dst,
                              float* __restrict__ out_alpha, int e) {
    int i = blockIdx.x * blockDim.x + threadIdx.x;
    if (i >= e) return;
    int s = src[i], d = dst[i];
    float ex = expf(lrelu(g_el2[s] + g_er2[d]) - g_max2[d]);
    out_alpha[i] = ex / g_sum2[d];
}

// ---------------- launcher ----------------
extern "C" void kernel_launch(void* const* d_in, const int* in_sizes, int n_in,
                              void* d_out, int out_size) {
    const float* h    = (const float*)d_in[0];
    const int*   src  = (const int*)  d_in[1];
    const int*   dst  = (const int*)  d_in[2];
    const float* W1   = (const float*)d_in[3];
    const float* al1  = (const float*)d_in[4];
    const float* ar1  = (const float*)d_in[5];
    const float* b1   = (const float*)d_in[6];
    const float* W2   = (const float*)d_in[7];
    const float* al2  = (const float*)d_in[8];
    const float* ar2  = (const float*)d_in[9];
    const float* b2   = (const float*)d_in[10];
    const float* Wres = (const float*)d_in[11];
    float* out = (float*)d_out;

    int n = in_sizes[0] / F1;   // 50000
    int e = in_sizes[1];        // 800000
    if (n > N_MAX || e > E_MAX) return;

    const int T = 256;

    init_kernel<<<(n * F1 + T - 1) / T, T>>>(n);
    pack_wc_kernel<<<(F1 * 32 + T - 1) / T, T>>>(W2, Wres);
    gemm1_kernel<<<(n + 7) / 8, 128>>>(h, W1, n);
    eler1_kernel<<<((long long)n * 32 + T - 1) / T, T>>>(al1, ar1, n);
    edge_max1_kernel<<<(e + T - 1) / T, T>>>(src, dst, e);
    edge_acc1_kernel<<<((long long)e * 32 + T - 1) / T, T>>>(src, dst, e);
    gemm2_kernel<<<(n + 15) / 16, 128>>>(b1, n);
    eler2_kernel<<<(n + T - 1) / T, T>>>(al2, ar2, n);
    edge_max2_kernel<<<(e + T - 1) / T, T>>>(src, dst, e);
    edge_acc2_kernel<<<(e * 16 + T - 1) / T, T>>>(src, dst, e);
    finalize2_kernel<<<(n * 16 + T - 1) / T, T>>>(b2, out, n);
    if (out_size >= n * 16 + e) {
        alpha2_kernel<<<(e + T - 1) / T, T>>>(src, dst, out + n * 16, e);
    }
}

// round 2
// speedup vs baseline: 1.1556x; 1.1556x over previous
#include <cuda_runtime.h>
#include <math_constants.h>

#define N_MAX 50000
#define E_MAX 800000
#define F1 128
#define SLOPE 0.2f
#define FULL 0xffffffffu

// ---------------- scratch ----------------
__device__ float g_ft1[N_MAX * F1];      // layer-1 per-node features
__device__ float g_h1[N_MAX * F1];       // post-softmax, post-ELU layer-1 output
__device__ float g_el1[N_MAX * 2];
__device__ float g_er1[N_MAX * 2];
__device__ float g_ft2res[N_MAX * 32];   // [0:16]=ft2, [16:32]=res
__device__ float g_el2[N_MAX];
__device__ float g_er2[N_MAX];
__device__ float g_Wc[F1 * 32];          // [W2 | Wres]
// CSR build
__device__ int g_deg[N_MAX];
__device__ int g_rowptr[N_MAX + 1];
__device__ int g_cursor[N_MAX];
__device__ int g_srcs[E_MAX];            // src node of edges sorted by dst
__device__ int g_eorig[E_MAX];           // original edge index

__device__ __forceinline__ float lrelu(float x) { return x > 0.f ? x : SLOPE * x; }
__device__ __forceinline__ float eluf(float x)  { return x > 0.f ? x : expf(x) - 1.f; }

// ---------------- CSR build ----------------

// zero degree + pack [W2|Wres]
__global__ void prep_kernel(const float* __restrict__ W2,
                            const float* __restrict__ Wres, int n) {
    int i = blockIdx.x * blockDim.x + threadIdx.x;
    if (i < n) g_deg[i] = 0;
    if (i < F1 * 32) {
        int k = i >> 5, c = i & 31;
        g_Wc[i] = (c < 16) ? W2[k * 16 + c] : Wres[k * 16 + (c - 16)];
    }
}

__global__ void deg_kernel(const int* __restrict__ dst, int e) {
    int i = blockIdx.x * blockDim.x + threadIdx.x;
    if (i < e) atomicAdd(&g_deg[dst[i]], 1);
}

// single-block exclusive scan of g_deg -> g_rowptr / g_cursor
__global__ void scan_kernel(int n) {
    __shared__ int part[1024];
    int t = threadIdx.x;
    int chunk = (n + 1023) >> 10;
    int beg = t * chunk, end = min(beg + chunk, n);
    int s = 0;
    for (int i = beg; i < end; i++) s += g_deg[i];
    part[t] = s;
    __syncthreads();
    // inclusive Hillis-Steele scan
    for (int off = 1; off < 1024; off <<= 1) {
        int v = (t >= off) ? part[t - off] : 0;
        __syncthreads();
        part[t] += v;
        __syncthreads();
    }
    int run = (t == 0) ? 0 : part[t - 1];
    for (int i = beg; i < end; i++) {
        g_rowptr[i] = run;
        g_cursor[i] = run;
        run += g_deg[i];
    }
    if (t == 1023) g_rowptr[n] = part[1023];
}

__global__ void scatter_kernel(const int* __restrict__ src,
                               const int* __restrict__ dst, int e) {
    int i = blockIdx.x * blockDim.x + threadIdx.x;
    if (i >= e) return;
    int pos = atomicAdd(&g_cursor[dst[i]], 1);
    g_srcs[pos] = src[i];
    g_eorig[pos] = i;
}

// ---------------- GEMM1 (+ fused el1/er1) ----------------
// ft1 = h @ W1, 16 rows per 128-thread block.
__global__ void gemm1_kernel(const float* __restrict__ h,
                             const float* __restrict__ W1,
                             const float* __restrict__ al1,
                             const float* __restrict__ ar1, int n) {
    __shared__ float hs[16][F1];
    int t = threadIdx.x;
    int row0 = blockIdx.x * 16;
    for (int i = t; i < 16 * F1; i += 128) {
        int r = i >> 7, j = i & 127;
        int row = row0 + r;
        hs[r][j] = (row < n) ? h[row * F1 + j] : 0.f;
    }
    __syncthreads();
    float acc[16];
#pragma unroll
    for (int r = 0; r < 16; r++) acc[r] = 0.f;
    for (int k = 0; k < F1; k++) {
        float w = __ldg(&W1[k * F1 + t]);
#pragma unroll
        for (int r = 0; r < 16; r++) acc[r] += hs[r][k] * w;
    }
    __syncthreads();  // done reading hs
#pragma unroll
    for (int r = 0; r < 16; r++) {
        int row = row0 + r;
        if (row < n) g_ft1[row * F1 + t] = acc[r];
        hs[r][t] = acc[r];
    }
    __syncthreads();
    // fused eler1: 4 warps x 4 rows each
    int lane = t & 31, w = t >> 5;
    float a0 = al1[lane], a1 = al1[lane + 32], a2 = al1[lane + 64], a3 = al1[lane + 96];
    float r0 = ar1[lane], r1 = ar1[lane + 32], r2 = ar1[lane + 64], r3 = ar1[lane + 96];
#pragma unroll
    for (int rr = 0; rr < 4; rr++) {
        int r = w * 4 + rr;
        int row = row0 + r;
        float f0 = hs[r][lane], f1 = hs[r][lane + 32];
        float f2 = hs[r][lane + 64], f3 = hs[r][lane + 96];
        float el0 = f0 * a0 + f1 * a1, er0 = f0 * r0 + f1 * r1;
        float el1v = f2 * a2 + f3 * a3, er1v = f2 * r2 + f3 * r3;
#pragma unroll
        for (int o = 16; o; o >>= 1) {
            el0  += __shfl_xor_sync(FULL, el0, o);
            er0  += __shfl_xor_sync(FULL, er0, o);
            el1v += __shfl_xor_sync(FULL, el1v, o);
            er1v += __shfl_xor_sync(FULL, er1v, o);
        }
        if (lane == 0 && row < n) {
            g_el1[row * 2]     = el0;
            g_er1[row * 2]     = er0;
            g_el1[row * 2 + 1] = el1v;
            g_er1[row * 2 + 1] = er1v;
        }
    }
}

// ---------------- layer-1 aggregation: one warp per dst node ----------------
__global__ void agg1_kernel(const float* __restrict__ b1, int n) {
    int node = (blockIdx.x * blockDim.x + threadIdx.x) >> 5;
    int lane = threadIdx.x & 31;
    if (node >= n) return;
    int beg = g_rowptr[node], end = g_rowptr[node + 1];
    float er0 = g_er1[node * 2], er1v = g_er1[node * 2 + 1];

    // pass 1: segment max
    float m0 = -CUDART_INF_F, m1 = -CUDART_INF_F;
    for (int k = beg + lane; k < end; k += 32) {
        int s = g_srcs[k];
        m0 = fmaxf(m0, lrelu(g_el1[s * 2]     + er0));
        m1 = fmaxf(m1, lrelu(g_el1[s * 2 + 1] + er1v));
    }
#pragma unroll
    for (int o = 16; o; o >>= 1) {
        m0 = fmaxf(m0, __shfl_xor_sync(FULL, m0, o));
        m1 = fmaxf(m1, __shfl_xor_sync(FULL, m1, o));
    }

    // pass 2: exp + sum + feature accumulation
    float acc0 = 0.f, acc1 = 0.f, acc2 = 0.f, acc3 = 0.f;
    float s0 = 0.f, s1 = 0.f;
    for (int base = beg; base < end; base += 32) {
        int k = base + lane;
        int sidx = 0;
        float ex0 = 0.f, ex1 = 0.f;
        if (k < end) {
            sidx = g_srcs[k];
            ex0 = expf(lrelu(g_el1[sidx * 2]     + er0)  - m0);
            ex1 = expf(lrelu(g_el1[sidx * 2 + 1] + er1v) - m1);
            s0 += ex0;
            s1 += ex1;
        }
        int cnt = min(32, end - base);
        for (int j = 0; j < cnt; j++) {
            float x0 = __shfl_sync(FULL, ex0, j);
            float x1 = __shfl_sync(FULL, ex1, j);
            int   sj = __shfl_sync(FULL, sidx, j);
            const float* f = g_ft1 + sj * F1;
            acc0 += x0 * f[lane];
            acc1 += x0 * f[lane + 32];
            acc2 += x1 * f[lane + 64];
            acc3 += x1 * f[lane + 96];
        }
    }
#pragma unroll
    for (int o = 16; o; o >>= 1) {
        s0 += __shfl_xor_sync(FULL, s0, o);
        s1 += __shfl_xor_sync(FULL, s1, o);
    }
    float inv0 = (s0 > 0.f) ? 1.f / s0 : 0.f;
    float inv1 = (s1 > 0.f) ? 1.f / s1 : 0.f;
    float* hp = g_h1 + node * F1;
    hp[lane]      = eluf(acc0 * inv0 + b1[lane]);
    hp[lane + 32] = eluf(acc1 * inv0 + b1[lane + 32]);
    hp[lane + 64] = eluf(acc2 * inv1 + b1[lane + 64]);
    hp[lane + 96] = eluf(acc3 * inv1 + b1[lane + 96]);
}

// ---------------- GEMM2 (+ fused el2/er2) ----------------
// [ft2 | res] = h1 @ [W2 | Wres], 16 rows per 128-thread block.
__global__ void gemm2_kernel(const float* __restrict__ al2,
                             const float* __restrict__ ar2, int n) {
    __shared__ float hs[16][F1];
    int t = threadIdx.x;
    int row0 = blockIdx.x * 16;
    for (int i = t; i < 16 * F1; i += 128) {
        int r = i >> 7, j = i & 127;
        int row = row0 + r;
        hs[r][j] = (row < n) ? g_h1[row * F1 + j] : 0.f;
    }
    __syncthreads();
    int c = t & 31, g = t >> 5;
    float acc[4] = {0.f, 0.f, 0.f, 0.f};
    for (int k = 0; k < F1; k++) {
        float w = g_Wc[k * 32 + c];
#pragma unroll
        for (int rr = 0; rr < 4; rr++) acc[rr] += hs[g * 4 + rr][k] * w;
    }
    float a2 = (c < 16) ? al2[c] : 0.f;
    float r2v = (c < 16) ? ar2[c] : 0.f;
#pragma unroll
    for (int rr = 0; rr < 4; rr++) {
        int row = row0 + g * 4 + rr;
        if (row < n) g_ft2res[row * 32 + c] = acc[rr];
        float el = acc[rr] * a2, er = acc[rr] * r2v;
#pragma unroll
        for (int o = 8; o; o >>= 1) {
            el += __shfl_xor_sync(FULL, el, o);
            er += __shfl_xor_sync(FULL, er, o);
        }
        if (c == 0 && row < n) {
            g_el2[row] = el;
            g_er2[row] = er;
        }
    }
}

// ---------------- layer-2 aggregation + finalize + alpha ----------------
__global__ void agg2_kernel(const float* __restrict__ b2,
                            float* __restrict__ out,
                            float* __restrict__ out_alpha,
                            int n, int write_alpha) {
    int node = (blockIdx.x * blockDim.x + threadIdx.x) >> 5;
    int lane = threadIdx.x & 31;
    if (node >= n) return;
    int beg = g_rowptr[node], end = g_rowptr[node + 1];
    float er = g_er2[node];

    float m = -CUDART_INF_F;
    for (int k = beg + lane; k < end; k += 32)
        m = fmaxf(m, lrelu(g_el2[g_srcs[k]] + er));
#pragma unroll
    for (int o = 16; o; o >>= 1) m = fmaxf(m, __shfl_xor_sync(FULL, m, o));

    float acc = 0.f, ssum = 0.f;
    for (int base = beg; base < end; base += 32) {
        int k = base + lane;
        int sidx = 0;
        float ex = 0.f;
        if (k < end) {
            sidx = g_srcs[k];
            ex = expf(lrelu(g_el2[sidx] + er) - m);
            ssum += ex;
        }
        int cnt = min(32, end - base);
        for (int j = 0; j < cnt; j++) {
            float x = __shfl_sync(FULL, ex, j);
            int  sj = __shfl_sync(FULL, sidx, j);
            if (lane < 16) acc += x * g_ft2res[sj * 32 + lane];
        }
    }
#pragma unroll
    for (int o = 16; o; o >>= 1) ssum += __shfl_xor_sync(FULL, ssum, o);
    float inv = (ssum > 0.f) ? 1.f / ssum : 0.f;
    if (lane < 16)
        out[node * 16 + lane] = acc * inv + b2[lane] + g_ft2res[node * 32 + 16 + lane];
    if (write_alpha) {
        for (int k = beg + lane; k < end; k += 32) {
            int s = g_srcs[k];
            float ex = expf(lrelu(g_el2[s] + er) - m);
            out_alpha[g_eorig[k]] = ex * inv;
        }
    }
}

// ---------------- launcher ----------------
extern "C" void kernel_launch(void* const* d_in, const int* in_sizes, int n_in,
                              void* d_out, int out_size) {
    const float* h    = (const float*)d_in[0];
    const int*   src  = (const int*)  d_in[1];
    const int*   dst  = (const int*)  d_in[2];
    const float* W1   = (const float*)d_in[3];
    const float* al1  = (const float*)d_in[4];
    const float* ar1  = (const float*)d_in[5];
    const float* b1   = (const float*)d_in[6];
    const float* W2   = (const float*)d_in[7];
    const float* al2  = (const float*)d_in[8];
    const float* ar2  = (const float*)d_in[9];
    const float* b2   = (const float*)d_in[10];
    const float* Wres = (const float*)d_in[11];
    float* out = (float*)d_out;

    int n = in_sizes[0] / F1;
    int e = in_sizes[1];
    if (n > N_MAX || e > E_MAX) return;

    const int T = 256;
    int write_alpha = (out_size >= n * 16 + e) ? 1 : 0;

    prep_kernel<<<(max(n, F1 * 32) + T - 1) / T, T>>>(W2, Wres, n);
    deg_kernel<<<(e + T - 1) / T, T>>>(dst, e);
    scan_kernel<<<1, 1024>>>(n);
    scatter_kernel<<<(e + T - 1) / T, T>>>(src, dst, e);
    gemm1_kernel<<<(n + 15) / 16, 128>>>(h, W1, al1, ar1, n);
    agg1_kernel<<<((long long)n * 32 + T - 1) / T, T>>>(b1, n);
    gemm2_kernel<<<(n + 15) / 16, 128>>>(al2, ar2, n);
    agg2_kernel<<<((long long)n * 32 + T - 1) / T, T>>>(
        b2, out, out + n * 16, n, write_alpha);
}

// round 3
// speedup vs baseline: 1.2586x; 1.0892x over previous
#include <cuda_runtime.h>
#include <math_constants.h>

#define N_MAX 50000
#define E_MAX 800000
#define F1 128
#define SLOPE 0.2f
#define FULL 0xffffffffu

// ---------------- scratch ----------------
__device__ float g_ft1[N_MAX * F1];
__device__ float g_h1[N_MAX * F1];
__device__ float2 g_el1[N_MAX];          // both heads packed
__device__ float2 g_er1[N_MAX];
__device__ float g_ft2res[N_MAX * 32];   // [0:16]=ft2, [16:32]=res
__device__ float g_el2[N_MAX];
__device__ float g_er2[N_MAX];
__device__ float g_Wc[F1 * 32];          // [W2 | Wres]
__device__ int g_deg[N_MAX];
__device__ int g_rowptr[N_MAX + 1];
__device__ int g_cursor[N_MAX];
__device__ int g_srcs[E_MAX];
__device__ int g_eorig[E_MAX];

__device__ __forceinline__ float lrelu(float x) { return x > 0.f ? x : SLOPE * x; }
__device__ __forceinline__ float eluf(float x)  { return x > 0.f ? x : expf(x) - 1.f; }

// ---------------- CSR build ----------------
__global__ void prep_kernel(const float* __restrict__ W2,
                            const float* __restrict__ Wres, int n) {
    int i = blockIdx.x * blockDim.x + threadIdx.x;
    if (i < n) g_deg[i] = 0;
    if (i < F1 * 32) {
        int k = i >> 5, c = i & 31;
        g_Wc[i] = (c < 16) ? W2[k * 16 + c] : Wres[k * 16 + (c - 16)];
    }
}

__global__ void deg_kernel(const int* __restrict__ dst, int e) {
    int i = (blockIdx.x * blockDim.x + threadIdx.x) * 4;
    int d0 = (i < e) ? dst[i] : -1;
    int d1 = (i + 1 < e) ? dst[i + 1] : -1;
    int d2 = (i + 2 < e) ? dst[i + 2] : -1;
    int d3 = (i + 3 < e) ? dst[i + 3] : -1;
    if (d0 >= 0) atomicAdd(&g_deg[d0], 1);
    if (d1 >= 0) atomicAdd(&g_deg[d1], 1);
    if (d2 >= 0) atomicAdd(&g_deg[d2], 1);
    if (d3 >= 0) atomicAdd(&g_deg[d3], 1);
}

__global__ void scan_kernel(int n) {
    __shared__ int part[1024];
    int t = threadIdx.x;
    int chunk = (n + 1023) >> 10;
    int beg = t * chunk, end = min(beg + chunk, n);
    int s = 0;
    for (int i = beg; i < end; i++) s += g_deg[i];
    part[t] = s;
    __syncthreads();
    for (int off = 1; off < 1024; off <<= 1) {
        int v = (t >= off) ? part[t - off] : 0;
        __syncthreads();
        part[t] += v;
        __syncthreads();
    }
    int run = (t == 0) ? 0 : part[t - 1];
    for (int i = beg; i < end; i++) {
        g_rowptr[i] = run;
        g_cursor[i] = run;
        run += g_deg[i];
    }
    if (t == 1023) g_rowptr[n] = part[1023];
}

__global__ void scatter_kernel(const int* __restrict__ src,
                               const int* __restrict__ dst, int e) {
    int i = (blockIdx.x * blockDim.x + threadIdx.x) * 4;
#pragma unroll
    for (int j = 0; j < 4; j++) {
        int k = i + j;
        if (k < e) {
            int pos = atomicAdd(&g_cursor[dst[k]], 1);
            g_srcs[pos] = src[k];
            g_eorig[pos] = k;
        }
    }
}

// ---------------- GEMM1 + fused el1/er1 ----------------
__global__ void gemm1_kernel(const float* __restrict__ h,
                             const float* __restrict__ W1,
                             const float* __restrict__ al1,
                             const float* __restrict__ ar1, int n) {
    __shared__ float hs[16][F1];
    int t = threadIdx.x;
    int row0 = blockIdx.x * 16;
    // vectorized smem fill: 16*128 floats = 512 float4
    for (int i = t; i < 512; i += 128) {
        int r = i >> 5, j4 = i & 31;           // j4: float4 index within row
        int row = row0 + r;
        float4 v = make_float4(0.f, 0.f, 0.f, 0.f);
        if (row < n) v = *(const float4*)(h + row * F1 + j4 * 4);
        *(float4*)&hs[r][j4 * 4] = v;
    }
    __syncthreads();
    float acc[16];
#pragma unroll
    for (int r = 0; r < 16; r++) acc[r] = 0.f;
    for (int k = 0; k < F1; k += 4) {
        float w0 = __ldg(&W1[k * F1 + t]);
        float w1 = __ldg(&W1[(k + 1) * F1 + t]);
        float w2 = __ldg(&W1[(k + 2) * F1 + t]);
        float w3 = __ldg(&W1[(k + 3) * F1 + t]);
#pragma unroll
        for (int r = 0; r < 16; r++) {
            float4 hv = *(const float4*)&hs[r][k];
            acc[r] += hv.x * w0 + hv.y * w1 + hv.z * w2 + hv.w * w3;
        }
    }
    __syncthreads();
#pragma unroll
    for (int r = 0; r < 16; r++) {
        int row = row0 + r;
        if (row < n) g_ft1[row * F1 + t] = acc[r];
        hs[r][t] = acc[r];
    }
    __syncthreads();
    int lane = t & 31, w = t >> 5;
    float a0 = al1[lane], a1 = al1[lane + 32], a2 = al1[lane + 64], a3 = al1[lane + 96];
    float r0 = ar1[lane], r1 = ar1[lane + 32], r2 = ar1[lane + 64], r3 = ar1[lane + 96];
#pragma unroll
    for (int rr = 0; rr < 4; rr++) {
        int r = w * 4 + rr;
        int row = row0 + r;
        float f0 = hs[r][lane], f1 = hs[r][lane + 32];
        float f2 = hs[r][lane + 64], f3 = hs[r][lane + 96];
        float el0 = f0 * a0 + f1 * a1, er0 = f0 * r0 + f1 * r1;
        float el1v = f2 * a2 + f3 * a3, er1v = f2 * r2 + f3 * r3;
#pragma unroll
        for (int o = 16; o; o >>= 1) {
            el0  += __shfl_xor_sync(FULL, el0, o);
            er0  += __shfl_xor_sync(FULL, er0, o);
            el1v += __shfl_xor_sync(FULL, el1v, o);
            er1v += __shfl_xor_sync(FULL, er1v, o);
        }
        if (lane == 0 && row < n) {
            g_el1[row] = make_float2(el0, el1v);
            g_er1[row] = make_float2(er0, er1v);
        }
    }
}

// ---------------- layer-1 aggregation: warp per node, float4 lanes ----------
__global__ void agg1_kernel(const float* __restrict__ b1, int n) {
    int node = (blockIdx.x * blockDim.x + threadIdx.x) >> 5;
    int lane = threadIdx.x & 31;
    if (node >= n) return;
    int beg = g_rowptr[node], end = g_rowptr[node + 1];
    float2 er = g_er1[node];

    float m0 = -CUDART_INF_F, m1 = -CUDART_INF_F;
    for (int k = beg + lane; k < end; k += 32) {
        float2 el = g_el1[g_srcs[k]];
        m0 = fmaxf(m0, lrelu(el.x + er.x));
        m1 = fmaxf(m1, lrelu(el.y + er.y));
    }
#pragma unroll
    for (int o = 16; o; o >>= 1) {
        m0 = fmaxf(m0, __shfl_xor_sync(FULL, m0, o));
        m1 = fmaxf(m1, __shfl_xor_sync(FULL, m1, o));
    }

    float4 acc = make_float4(0.f, 0.f, 0.f, 0.f);
    float s0 = 0.f, s1 = 0.f;
    for (int base = beg; base < end; base += 32) {
        int k = base + lane;
        int sidx = 0;
        float ex0 = 0.f, ex1 = 0.f;
        if (k < end) {
            sidx = g_srcs[k];
            float2 el = g_el1[sidx];
            ex0 = expf(lrelu(el.x + er.x) - m0);
            ex1 = expf(lrelu(el.y + er.y) - m1);
            s0 += ex0;
            s1 += ex1;
        }
        int cnt = min(32, end - base);
        // lane covers features [4*lane, 4*lane+4); head 1 starts at feature 64
        float myex;
        for (int j = 0; j < cnt; j++) {
            float x0 = __shfl_sync(FULL, ex0, j);
            float x1 = __shfl_sync(FULL, ex1, j);
            int   sj = __shfl_sync(FULL, sidx, j);
            myex = (lane < 16) ? x0 : x1;
            float4 f = *(const float4*)(g_ft1 + sj * F1 + lane * 4);
            acc.x += myex * f.x;
            acc.y += myex * f.y;
            acc.z += myex * f.z;
            acc.w += myex * f.w;
        }
    }
#pragma unroll
    for (int o = 16; o; o >>= 1) {
        s0 += __shfl_xor_sync(FULL, s0, o);
        s1 += __shfl_xor_sync(FULL, s1, o);
    }
    float inv0 = (s0 > 0.f) ? 1.f / s0 : 0.f;
    float inv1 = (s1 > 0.f) ? 1.f / s1 : 0.f;
    float inv = (lane < 16) ? inv0 : inv1;
    float4 bv = *(const float4*)(b1 + lane * 4);
    float4 o4;
    o4.x = eluf(acc.x * inv + bv.x);
    o4.y = eluf(acc.y * inv + bv.y);
    o4.z = eluf(acc.z * inv + bv.z);
    o4.w = eluf(acc.w * inv + bv.w);
    *(float4*)(g_h1 + node * F1 + lane * 4) = o4;
}

// ---------------- GEMM2 + fused el2/er2 ----------------
__global__ void gemm2_kernel(const float* __restrict__ al2,
                             const float* __restrict__ ar2, int n) {
    __shared__ float hs[16][F1];
    int t = threadIdx.x;
    int row0 = blockIdx.x * 16;
    for (int i = t; i < 512; i += 128) {
        int r = i >> 5, j4 = i & 31;
        int row = row0 + r;
        float4 v = make_float4(0.f, 0.f, 0.f, 0.f);
        if (row < n) v = *(const float4*)(g_h1 + row * F1 + j4 * 4);
        *(float4*)&hs[r][j4 * 4] = v;
    }
    __syncthreads();
    int c = t & 31, g = t >> 5;
    float acc[4] = {0.f, 0.f, 0.f, 0.f};
    for (int k = 0; k < F1; k += 4) {
        float w0 = g_Wc[k * 32 + c];
        float w1 = g_Wc[(k + 1) * 32 + c];
        float w2 = g_Wc[(k + 2) * 32 + c];
        float w3 = g_Wc[(k + 3) * 32 + c];
#pragma unroll
        for (int rr = 0; rr < 4; rr++) {
            float4 hv = *(const float4*)&hs[g * 4 + rr][k];
            acc[rr] += hv.x * w0 + hv.y * w1 + hv.z * w2 + hv.w * w3;
        }
    }
    float a2 = (c < 16) ? al2[c] : 0.f;
    float r2v = (c < 16) ? ar2[c] : 0.f;
#pragma unroll
    for (int rr = 0; rr < 4; rr++) {
        int row = row0 + g * 4 + rr;
        if (row < n) g_ft2res[row * 32 + c] = acc[rr];
        float el = acc[rr] * a2, er = acc[rr] * r2v;
#pragma unroll
        for (int o = 8; o; o >>= 1) {
            el += __shfl_xor_sync(FULL, el, o);
            er += __shfl_xor_sync(FULL, er, o);
        }
        if (c == 0 && row < n) {
            g_el2[row] = el;
            g_er2[row] = er;
        }
    }
}

// ---------------- layer-2 agg: TWO nodes per warp (half-warp each) --------
__global__ void agg2_kernel(const float* __restrict__ b2,
                            float* __restrict__ out,
                            float* __restrict__ out_alpha,
                            int n, int write_alpha) {
    int warp = (blockIdx.x * blockDim.x + threadIdx.x) >> 5;
    int lane = threadIdx.x & 31;
    int half = lane >> 4;
    int l = lane & 15;
    int node = warp * 2 + half;
    if (node >= n) return;
    unsigned mask = 0xFFFFu << (half * 16);
    int beg = g_rowptr[node], end = g_rowptr[node + 1];
    float er = g_er2[node];

    float m = -CUDART_INF_F;
    for (int k = beg + l; k < end; k += 16)
        m = fmaxf(m, lrelu(g_el2[g_srcs[k]] + er));
#pragma unroll
    for (int o = 8; o; o >>= 1) m = fmaxf(m, __shfl_xor_sync(mask, m, o));

    float acc = 0.f, ssum = 0.f;
    for (int base = beg; base < end; base += 16) {
        int k = base + l;
        int sidx = 0;
        float ex = 0.f;
        if (k < end) {
            sidx = g_srcs[k];
            ex = expf(lrelu(g_el2[sidx] + er) - m);
            ssum += ex;
        }
        int cnt = min(16, end - base);
        for (int j = 0; j < cnt; j++) {
            float x = __shfl_sync(mask, ex, j, 16);
            int  sj = __shfl_sync(mask, sidx, j, 16);
            acc += x * g_ft2res[sj * 32 + l];
        }
    }
#pragma unroll
    for (int o = 8; o; o >>= 1) ssum += __shfl_xor_sync(mask, ssum, o);
    float inv = (ssum > 0.f) ? 1.f / ssum : 0.f;
    out[node * 16 + l] = acc * inv + b2[l] + g_ft2res[node * 32 + 16 + l];
    if (write_alpha) {
        for (int k = beg + l; k < end; k += 16) {
            int s = g_srcs[k];
            float ex = expf(lrelu(g_el2[s] + er) - m);
            out_alpha[g_eorig[k]] = ex * inv;
        }
    }
}

// ---------------- launcher ----------------
extern "C" void kernel_launch(void* const* d_in, const int* in_sizes, int n_in,
                              void* d_out, int out_size) {
    const float* h    = (const float*)d_in[0];
    const int*   src  = (const int*)  d_in[1];
    const int*   dst  = (const int*)  d_in[2];
    const float* W1   = (const float*)d_in[3];
    const float* al1  = (const float*)d_in[4];
    const float* ar1  = (const float*)d_in[5];
    const float* b1   = (const float*)d_in[6];
    const float* W2   = (const float*)d_in[7];
    const float* al2  = (const float*)d_in[8];
    const float* ar2  = (const float*)d_in[9];
    const float* b2   = (const float*)d_in[10];
    const float* Wres = (const float*)d_in[11];
    float* out = (float*)d_out;

    int n = in_sizes[0] / F1;
    int e = in_sizes[1];
    if (n > N_MAX || e > E_MAX) return;

    const int T = 256;
    int write_alpha = (out_size >= n * 16 + e) ? 1 : 0;

    prep_kernel<<<(max(n, F1 * 32) + T - 1) / T, T>>>(W2, Wres, n);
    deg_kernel<<<(e + 4 * T - 1) / (4 * T), T>>>(dst, e);
    scan_kernel<<<1, 1024>>>(n);
    scatter_kernel<<<(e + 4 * T - 1) / (4 * T), T>>>(src, dst, e);
    gemm1_kernel<<<(n + 15) / 16, 128>>>(h, W1, al1, ar1, n);
    agg1_kernel<<<((long long)n * 32 + T - 1) / T, T>>>(b1, n);
    gemm2_kernel<<<(n + 15) / 16, 128>>>(al2, ar2, n);
    agg2_kernel<<<((long long)((n + 1) / 2) * 32 + T - 1) / T, T>>>(
        b2, out, out + n * 16, n, write_alpha);
}

// round 4
// speedup vs baseline: 1.3089x; 1.0399x over previous
#include <cuda_runtime.h>
#include <cuda_fp16.h>
#include <math_constants.h>

#define N_MAX 50000
#define E_MAX 800000
#define F1 128
#define SLOPE 0.2f
#define FULL 0xffffffffu

// ---------------- scratch ----------------
__device__ __half2 g_ft1h[N_MAX * 64];   // layer-1 features, fp16 pairs
__device__ float g_h1[N_MAX * F1];
__device__ float2 g_el1[N_MAX];
__device__ float2 g_er1[N_MAX];
__device__ __half g_ft2h[N_MAX * 16];    // layer-2 features (gathered), fp16
__device__ float g_res[N_MAX * 16];      // residual (per-node access)
__device__ float g_el2[N_MAX];
__device__ float g_er2[N_MAX];
__device__ float g_Wc[F1 * 32];          // [W2 | Wres]
__device__ int g_deg[N_MAX];
__device__ int g_rowptr[N_MAX + 1];
__device__ int g_cursor[N_MAX];
__device__ int2 g_edge[E_MAX];           // (src, orig_edge_idx) sorted by dst

__device__ __forceinline__ float lrelu(float x) { return x > 0.f ? x : SLOPE * x; }
__device__ __forceinline__ float eluf(float x)  { return x > 0.f ? x : expf(x) - 1.f; }

// ---------------- CSR build ----------------
__global__ void prep_kernel(const float* __restrict__ W2,
                            const float* __restrict__ Wres, int n) {
    int i = blockIdx.x * blockDim.x + threadIdx.x;
    if (i < n) g_deg[i] = 0;
    if (i < F1 * 32) {
        int k = i >> 5, c = i & 31;
        g_Wc[i] = (c < 16) ? W2[k * 16 + c] : Wres[k * 16 + (c - 16)];
    }
}

__global__ void deg_kernel(const int* __restrict__ dst, int e) {
    int base = (blockIdx.x * blockDim.x + threadIdx.x) * 8;
    if (base + 8 <= e) {
        int4 a = *(const int4*)(dst + base);
        int4 b = *(const int4*)(dst + base + 4);
        atomicAdd(&g_deg[a.x], 1); atomicAdd(&g_deg[a.y], 1);
        atomicAdd(&g_deg[a.z], 1); atomicAdd(&g_deg[a.w], 1);
        atomicAdd(&g_deg[b.x], 1); atomicAdd(&g_deg[b.y], 1);
        atomicAdd(&g_deg[b.z], 1); atomicAdd(&g_deg[b.w], 1);
    } else {
        for (int k = base; k < e; k++) atomicAdd(&g_deg[dst[k]], 1);
    }
}

__global__ void scan_kernel(int n) {
    __shared__ int part[1024];
    int t = threadIdx.x;
    int chunk = (n + 1023) >> 10;
    int beg = t * chunk, end = min(beg + chunk, n);
    int s = 0;
    for (int i = beg; i < end; i++) s += g_deg[i];
    part[t] = s;
    __syncthreads();
    for (int off = 1; off < 1024; off <<= 1) {
        int v = (t >= off) ? part[t - off] : 0;
        __syncthreads();
        part[t] += v;
        __syncthreads();
    }
    int run = (t == 0) ? 0 : part[t - 1];
    for (int i = beg; i < end; i++) {
        g_rowptr[i] = run;
        g_cursor[i] = run;
        run += g_deg[i];
    }
    if (t == 1023) g_rowptr[n] = part[1023];
}

__global__ void scatter_kernel(const int* __restrict__ src,
                               const int* __restrict__ dst, int e) {
    int base = (blockIdx.x * blockDim.x + threadIdx.x) * 8;
    if (base + 8 <= e) {
        int4 d0 = *(const int4*)(dst + base);
        int4 d1 = *(const int4*)(dst + base + 4);
        int4 s0 = *(const int4*)(src + base);
        int4 s1 = *(const int4*)(src + base + 4);
        int p0 = atomicAdd(&g_cursor[d0.x], 1);
        int p1 = atomicAdd(&g_cursor[d0.y], 1);
        int p2 = atomicAdd(&g_cursor[d0.z], 1);
        int p3 = atomicAdd(&g_cursor[d0.w], 1);
        int p4 = atomicAdd(&g_cursor[d1.x], 1);
        int p5 = atomicAdd(&g_cursor[d1.y], 1);
        int p6 = atomicAdd(&g_cursor[d1.z], 1);
        int p7 = atomicAdd(&g_cursor[d1.w], 1);
        g_edge[p0] = make_int2(s0.x, base);
        g_edge[p1] = make_int2(s0.y, base + 1);
        g_edge[p2] = make_int2(s0.z, base + 2);
        g_edge[p3] = make_int2(s0.w, base + 3);
        g_edge[p4] = make_int2(s1.x, base + 4);
        g_edge[p5] = make_int2(s1.y, base + 5);
        g_edge[p6] = make_int2(s1.z, base + 6);
        g_edge[p7] = make_int2(s1.w, base + 7);
    } else {
        for (int k = base; k < e; k++) {
            int pos = atomicAdd(&g_cursor[dst[k]], 1);
            g_edge[pos] = make_int2(src[k], k);
        }
    }
}

// ---------------- GEMM1 + fused el1/er1, fp16 ft1 output ----------------
__global__ void gemm1_kernel(const float* __restrict__ h,
                             const float* __restrict__ W1,
                             const float* __restrict__ al1,
                             const float* __restrict__ ar1, int n) {
    __shared__ float hs[16][F1];
    int t = threadIdx.x;
    int row0 = blockIdx.x * 16;
    for (int i = t; i < 512; i += 128) {
        int r = i >> 5, j4 = i & 31;
        int row = row0 + r;
        float4 v = make_float4(0.f, 0.f, 0.f, 0.f);
        if (row < n) v = *(const float4*)(h + row * F1 + j4 * 4);
        *(float4*)&hs[r][j4 * 4] = v;
    }
    __syncthreads();
    float acc[16];
#pragma unroll
    for (int r = 0; r < 16; r++) acc[r] = 0.f;
    for (int k = 0; k < F1; k += 4) {
        float w0 = __ldg(&W1[k * F1 + t]);
        float w1 = __ldg(&W1[(k + 1) * F1 + t]);
        float w2 = __ldg(&W1[(k + 2) * F1 + t]);
        float w3 = __ldg(&W1[(k + 3) * F1 + t]);
#pragma unroll
        for (int r = 0; r < 16; r++) {
            float4 hv = *(const float4*)&hs[r][k];
            acc[r] += hv.x * w0 + hv.y * w1 + hv.z * w2 + hv.w * w3;
        }
    }
    __syncthreads();
#pragma unroll
    for (int r = 0; r < 16; r++) hs[r][t] = acc[r];
    __syncthreads();
    // fp16 feature store: 16 rows x 64 half2
    for (int i = t; i < 16 * 64; i += 128) {
        int r = i >> 6, c2 = i & 63;
        int row = row0 + r;
        if (row < n)
            g_ft1h[row * 64 + c2] = __floats2half2_rn(hs[r][c2 * 2], hs[r][c2 * 2 + 1]);
    }
    // fused eler1
    int lane = t & 31, w = t >> 5;
    float a0 = al1[lane], a1 = al1[lane + 32], a2 = al1[lane + 64], a3 = al1[lane + 96];
    float r0 = ar1[lane], r1 = ar1[lane + 32], r2 = ar1[lane + 64], r3 = ar1[lane + 96];
#pragma unroll
    for (int rr = 0; rr < 4; rr++) {
        int r = w * 4 + rr;
        int row = row0 + r;
        float f0 = hs[r][lane], f1 = hs[r][lane + 32];
        float f2 = hs[r][lane + 64], f3 = hs[r][lane + 96];
        float el0 = f0 * a0 + f1 * a1, er0 = f0 * r0 + f1 * r1;
        float el1v = f2 * a2 + f3 * a3, er1v = f2 * r2 + f3 * r3;
#pragma unroll
        for (int o = 16; o; o >>= 1) {
            el0  += __shfl_xor_sync(FULL, el0, o);
            er0  += __shfl_xor_sync(FULL, er0, o);
            el1v += __shfl_xor_sync(FULL, el1v, o);
            er1v += __shfl_xor_sync(FULL, er1v, o);
        }
        if (lane == 0 && row < n) {
            g_el1[row] = make_float2(el0, el1v);
            g_er1[row] = make_float2(er0, er1v);
        }
    }
}

// ---------------- layer-1 aggregation: warp per node ----------------
__global__ void agg1_kernel(const float* __restrict__ b1, int n) {
    int node = (blockIdx.x * blockDim.x + threadIdx.x) >> 5;
    int lane = threadIdx.x & 31;
    if (node >= n) return;
    int beg = g_rowptr[node], end = g_rowptr[node + 1];
    float2 er = g_er1[node];

    float m0 = -CUDART_INF_F, m1 = -CUDART_INF_F;
    for (int k = beg + lane; k < end; k += 32) {
        float2 el = g_el1[g_edge[k].x];
        m0 = fmaxf(m0, lrelu(el.x + er.x));
        m1 = fmaxf(m1, lrelu(el.y + er.y));
    }
#pragma unroll
    for (int o = 16; o; o >>= 1) {
        m0 = fmaxf(m0, __shfl_xor_sync(FULL, m0, o));
        m1 = fmaxf(m1, __shfl_xor_sync(FULL, m1, o));
    }

    float4 acc = make_float4(0.f, 0.f, 0.f, 0.f);
    float s0 = 0.f, s1 = 0.f;
    for (int base = beg; base < end; base += 32) {
        int k = base + lane;
        int sidx = 0;
        float ex0 = 0.f, ex1 = 0.f;
        if (k < end) {
            sidx = g_edge[k].x;
            float2 el = g_el1[sidx];
            ex0 = expf(lrelu(el.x + er.x) - m0);
            ex1 = expf(lrelu(el.y + er.y) - m1);
            s0 += ex0;
            s1 += ex1;
        }
        int cnt = min(32, end - base);
        for (int j = 0; j < cnt; j++) {
            float x0 = __shfl_sync(FULL, ex0, j);
            float x1 = __shfl_sync(FULL, ex1, j);
            int   sj = __shfl_sync(FULL, sidx, j);
            float myex = (lane < 16) ? x0 : x1;
            uint2 raw = *(const uint2*)(g_ft1h + sj * 64 + lane * 2);
            float2 f01 = __half22float2(*reinterpret_cast<__half2*>(&raw.x));
            float2 f23 = __half22float2(*reinterpret_cast<__half2*>(&raw.y));
            acc.x += myex * f01.x;
            acc.y += myex * f01.y;
            acc.z += myex * f23.x;
            acc.w += myex * f23.y;
        }
    }
#pragma unroll
    for (int o = 16; o; o >>= 1) {
        s0 += __shfl_xor_sync(FULL, s0, o);
        s1 += __shfl_xor_sync(FULL, s1, o);
    }
    float inv0 = (s0 > 0.f) ? 1.f / s0 : 0.f;
    float inv1 = (s1 > 0.f) ? 1.f / s1 : 0.f;
    float inv = (lane < 16) ? inv0 : inv1;
    float4 bv = *(const float4*)(b1 + lane * 4);
    float4 o4;
    o4.x = eluf(acc.x * inv + bv.x);
    o4.y = eluf(acc.y * inv + bv.y);
    o4.z = eluf(acc.z * inv + bv.z);
    o4.w = eluf(acc.w * inv + bv.w);
    *(float4*)(g_h1 + node * F1 + lane * 4) = o4;
}

// ---------------- GEMM2 + fused el2/er2 ----------------
__global__ void gemm2_kernel(const float* __restrict__ al2,
                             const float* __restrict__ ar2, int n) {
    __shared__ float hs[16][F1];
    int t = threadIdx.x;
    int row0 = blockIdx.x * 16;
    for (int i = t; i < 512; i += 128) {
        int r = i >> 5, j4 = i & 31;
        int row = row0 + r;
        float4 v = make_float4(0.f, 0.f, 0.f, 0.f);
        if (row < n) v = *(const float4*)(g_h1 + row * F1 + j4 * 4);
        *(float4*)&hs[r][j4 * 4] = v;
    }
    __syncthreads();
    int c = t & 31, g = t >> 5;
    float acc[4] = {0.f, 0.f, 0.f, 0.f};
    for (int k = 0; k < F1; k += 4) {
        float w0 = g_Wc[k * 32 + c];
        float w1 = g_Wc[(k + 1) * 32 + c];
        float w2 = g_Wc[(k + 2) * 32 + c];
        float w3 = g_Wc[(k + 3) * 32 + c];
#pragma unroll
        for (int rr = 0; rr < 4; rr++) {
            float4 hv = *(const float4*)&hs[g * 4 + rr][k];
            acc[rr] += hv.x * w0 + hv.y * w1 + hv.z * w2 + hv.w * w3;
        }
    }
    float a2 = (c < 16) ? al2[c] : 0.f;
    float r2v = (c < 16) ? ar2[c] : 0.f;
#pragma unroll
    for (int rr = 0; rr < 4; rr++) {
        int row = row0 + g * 4 + rr;
        if (row < n) {
            if (c < 16) g_ft2h[row * 16 + c] = __float2half(acc[rr]);
            else        g_res[row * 16 + (c - 16)] = acc[rr];
        }
        float el = acc[rr] * a2, er = acc[rr] * r2v;
#pragma unroll
        for (int o = 8; o; o >>= 1) {
            el += __shfl_xor_sync(FULL, el, o);
            er += __shfl_xor_sync(FULL, er, o);
        }
        if (c == 0 && row < n) {
            g_el2[row] = el;
            g_er2[row] = er;
        }
    }
}

// ---------------- layer-2 agg: two nodes per warp ----------------
__global__ void agg2_kernel(const float* __restrict__ b2,
                            float* __restrict__ out,
                            float* __restrict__ out_alpha,
                            int n, int write_alpha) {
    int warp = (blockIdx.x * blockDim.x + threadIdx.x) >> 5;
    int lane = threadIdx.x & 31;
    int half = lane >> 4;
    int l = lane & 15;
    int node = warp * 2 + half;
    if (node >= n) return;
    unsigned mask = 0xFFFFu << (half * 16);
    int beg = g_rowptr[node], end = g_rowptr[node + 1];
    float er = g_er2[node];

    float m = -CUDART_INF_F;
    for (int k = beg + l; k < end; k += 16)
        m = fmaxf(m, lrelu(g_el2[g_edge[k].x] + er));
#pragma unroll
    for (int o = 8; o; o >>= 1) m = fmaxf(m, __shfl_xor_sync(mask, m, o));

    float acc = 0.f, ssum = 0.f;
    for (int base = beg; base < end; base += 16) {
        int k = base + l;
        int sidx = 0;
        float ex = 0.f;
        if (k < end) {
            sidx = g_edge[k].x;
            ex = expf(lrelu(g_el2[sidx] + er) - m);
            ssum += ex;
        }
        int cnt = min(16, end - base);
        for (int j = 0; j < cnt; j++) {
            float x = __shfl_sync(mask, ex, j, 16);
            int  sj = __shfl_sync(mask, sidx, j, 16);
            acc += x * __half2float(g_ft2h[sj * 16 + l]);
        }
    }
#pragma unroll
    for (int o = 8; o; o >>= 1) ssum += __shfl_xor_sync(mask, ssum, o);
    float inv = (ssum > 0.f) ? 1.f / ssum : 0.f;
    out[node * 16 + l] = acc * inv + b2[l] + g_res[node * 16 + l];
    if (write_alpha) {
        for (int k = beg + l; k < end; k += 16) {
            int2 epk = g_edge[k];
            float ex = expf(lrelu(g_el2[epk.x] + er) - m);
            out_alpha[epk.y] = ex * inv;
        }
    }
}

// ---------------- launcher ----------------
extern "C" void kernel_launch(void* const* d_in, const int* in_sizes, int n_in,
                              void* d_out, int out_size) {
    const float* h    = (const float*)d_in[0];
    const int*   src  = (const int*)  d_in[1];
    const int*   dst  = (const int*)  d_in[2];
    const float* W1   = (const float*)d_in[3];
    const float* al1  = (const float*)d_in[4];
    const float* ar1  = (const float*)d_in[5];
    const float* b1   = (const float*)d_in[6];
    const float* W2   = (const float*)d_in[7];
    const float* al2  = (const float*)d_in[8];
    const float* ar2  = (const float*)d_in[9];
    const float* b2   = (const float*)d_in[10];
    const float* Wres = (const float*)d_in[11];
    float* out = (float*)d_out;

    int n = in_sizes[0] / F1;
    int e = in_sizes[1];
    if (n > N_MAX || e > E_MAX) return;

    const int T = 256;
    int write_alpha = (out_size >= n * 16 + e) ? 1 : 0;

    // lazily-created side stream + events (created on the pre-capture
    // correctness call; graph capture sees only record/wait/launch nodes)
    static cudaStream_t s_side = nullptr;
    static cudaEvent_t ev_fork = nullptr, ev_join = nullptr;
    if (s_side == nullptr) {
        cudaStreamCreateWithFlags(&s_side, cudaStreamNonBlocking);
        cudaEventCreateWithFlags(&ev_fork, cudaEventDisableTiming);
        cudaEventCreateWithFlags(&ev_join, cudaEventDisableTiming);
    }

    // fork: gemm1 (independent of CSR) runs on side stream
    cudaEventRecord(ev_fork, 0);
    cudaStreamWaitEvent(s_side, ev_fork, 0);
    gemm1_kernel<<<(n + 15) / 16, 128, 0, s_side>>>(h, W1, al1, ar1, n);
    cudaEventRecord(ev_join, s_side);

    // main chain: CSR build
    prep_kernel<<<(max(n, F1 * 32) + T - 1) / T, T>>>(W2, Wres, n);
    deg_kernel<<<(e + 8 * T - 1) / (8 * T), T>>>(dst, e);
    scan_kernel<<<1, 1024>>>(n);
    scatter_kernel<<<(e + 8 * T - 1) / (8 * T), T>>>(src, dst, e);

    // join, then dependent chain
    cudaStreamWaitEvent(0, ev_join, 0);
    agg1_kernel<<<((long long)n * 32 + T - 1) / T, T>>>(b1, n);
    gemm2_kernel<<<(n + 15) / 16, 128>>>(al2, ar2, n);
    agg2_kernel<<<((long long)((n + 1) / 2) * 32 + T - 1) / T, T>>>(
        b2, out, out + n * 16, n, write_alpha);
}

// round 5
// speedup vs baseline: 1.9445x; 1.4856x over previous
#include <cuda_runtime.h>
#include <cuda_fp16.h>
#include <math_constants.h>

#define N_MAX 50000
#define E_MAX 800000
#define F1 128
#define SLOPE 0.2f
#define FULL 0xffffffffu
#define SCAN_B 512

// ---------------- scratch ----------------
__device__ __half2 g_ft1h[N_MAX * 64];   // layer-1 features, fp16 pairs
__device__ float g_h1[N_MAX * F1];
__device__ float2 g_el1[N_MAX];
__device__ float2 g_er1[N_MAX];
__device__ __half g_ft2h[N_MAX * 16];    // layer-2 features (gathered), fp16
__device__ float g_res[N_MAX * 16];      // residual
__device__ float g_el2[N_MAX];
__device__ float g_er2[N_MAX];
__device__ float g_Wc[F1 * 32];          // [W2 | Wres]
__device__ int g_deg[N_MAX];
__device__ int g_rowptr[N_MAX + 1];
__device__ int g_cursor[N_MAX];
__device__ int g_blocksum[128];          // ceil(N_MAX/SCAN_B) <= 98
__device__ int2 g_edge[E_MAX];           // (src, orig_edge_idx) sorted by dst

__device__ __forceinline__ float lrelu(float x) { return x > 0.f ? x : SLOPE * x; }
__device__ __forceinline__ float eluf(float x)  { return x > 0.f ? x : expf(x) - 1.f; }

// ---------------- CSR build ----------------
__global__ void prep_kernel(const float* __restrict__ W2,
                            const float* __restrict__ Wres, int n) {
    int i = blockIdx.x * blockDim.x + threadIdx.x;
    if (i < n) g_deg[i] = 0;
    if (i < F1 * 32) {
        int k = i >> 5, c = i & 31;
        g_Wc[i] = (c < 16) ? W2[k * 16 + c] : Wres[k * 16 + (c - 16)];
    }
}

__global__ void deg_kernel(const int* __restrict__ dst, int e) {
    int base = (blockIdx.x * blockDim.x + threadIdx.x) * 8;
    if (base + 8 <= e) {
        int4 a = *(const int4*)(dst + base);
        int4 b = *(const int4*)(dst + base + 4);
        atomicAdd(&g_deg[a.x], 1); atomicAdd(&g_deg[a.y], 1);
        atomicAdd(&g_deg[a.z], 1); atomicAdd(&g_deg[a.w], 1);
        atomicAdd(&g_deg[b.x], 1); atomicAdd(&g_deg[b.y], 1);
        atomicAdd(&g_deg[b.z], 1); atomicAdd(&g_deg[b.w], 1);
    } else {
        for (int k = base; k < e; k++) atomicAdd(&g_deg[dst[k]], 1);
    }
}

// 3-phase scan
__global__ void scan_local(int n) {
    __shared__ int sm[SCAN_B];
    int t = threadIdx.x;
    int i = blockIdx.x * SCAN_B + t;
    int v = (i < n) ? g_deg[i] : 0;
    sm[t] = v;
    __syncthreads();
    for (int off = 1; off < SCAN_B; off <<= 1) {
        int u = (t >= off) ? sm[t - off] : 0;
        __syncthreads();
        sm[t] += u;
        __syncthreads();
    }
    if (i < n) g_rowptr[i] = sm[t] - v;              // exclusive, local
    if (t == SCAN_B - 1) g_blocksum[blockIdx.x] = sm[t];
}

__global__ void scan_tops(int nb) {
    __shared__ int sm[128];
    int t = threadIdx.x;
    int v = (t < nb) ? g_blocksum[t] : 0;
    sm[t] = v;
    __syncthreads();
    for (int off = 1; off < 128; off <<= 1) {
        int u = (t >= off) ? sm[t - off] : 0;
        __syncthreads();
        sm[t] += u;
        __syncthreads();
    }
    if (t < nb) g_blocksum[t] = sm[t] - v;           // exclusive block offsets
}

__global__ void scan_add(int n, int e) {
    int i = blockIdx.x * blockDim.x + threadIdx.x;
    if (i < n) {
        int v = g_rowptr[i] + g_blocksum[i / SCAN_B];
        g_rowptr[i] = v;
        g_cursor[i] = v;
    }
    if (i == n) g_rowptr[n] = e;
}

__global__ void scatter_kernel(const int* __restrict__ src,
                               const int* __restrict__ dst, int e) {
    int base = (blockIdx.x * blockDim.x + threadIdx.x) * 8;
    if (base + 8 <= e) {
        int4 d0 = *(const int4*)(dst + base);
        int4 d1 = *(const int4*)(dst + base + 4);
        int4 s0 = *(const int4*)(src + base);
        int4 s1 = *(const int4*)(src + base + 4);
        int p0 = atomicAdd(&g_cursor[d0.x], 1);
        int p1 = atomicAdd(&g_cursor[d0.y], 1);
        int p2 = atomicAdd(&g_cursor[d0.z], 1);
        int p3 = atomicAdd(&g_cursor[d0.w], 1);
        int p4 = atomicAdd(&g_cursor[d1.x], 1);
        int p5 = atomicAdd(&g_cursor[d1.y], 1);
        int p6 = atomicAdd(&g_cursor[d1.z], 1);
        int p7 = atomicAdd(&g_cursor[d1.w], 1);
        g_edge[p0] = make_int2(s0.x, base);
        g_edge[p1] = make_int2(s0.y, base + 1);
        g_edge[p2] = make_int2(s0.z, base + 2);
        g_edge[p3] = make_int2(s0.w, base + 3);
        g_edge[p4] = make_int2(s1.x, base + 4);
        g_edge[p5] = make_int2(s1.y, base + 5);
        g_edge[p6] = make_int2(s1.z, base + 6);
        g_edge[p7] = make_int2(s1.w, base + 7);
    } else {
        for (int k = base; k < e; k++) {
            int pos = atomicAdd(&g_cursor[dst[k]], 1);
            g_edge[pos] = make_int2(src[k], k);
        }
    }
}

// ---------------- GEMM1 + fused el1/er1, fp16 ft1 output ----------------
__global__ void gemm1_kernel(const float* __restrict__ h,
                             const float* __restrict__ W1,
                             const float* __restrict__ al1,
                             const float* __restrict__ ar1, int n) {
    __shared__ float hs[16][F1];
    int t = threadIdx.x;
    int row0 = blockIdx.x * 16;
    for (int i = t; i < 512; i += 128) {
        int r = i >> 5, j4 = i & 31;
        int row = row0 + r;
        float4 v = make_float4(0.f, 0.f, 0.f, 0.f);
        if (row < n) v = *(const float4*)(h + row * F1 + j4 * 4);
        *(float4*)&hs[r][j4 * 4] = v;
    }
    __syncthreads();
    float acc[16];
#pragma unroll
    for (int r = 0; r < 16; r++) acc[r] = 0.f;
    for (int k = 0; k < F1; k += 4) {
        float w0 = __ldg(&W1[k * F1 + t]);
        float w1 = __ldg(&W1[(k + 1) * F1 + t]);
        float w2 = __ldg(&W1[(k + 2) * F1 + t]);
        float w3 = __ldg(&W1[(k + 3) * F1 + t]);
#pragma unroll
        for (int r = 0; r < 16; r++) {
            float4 hv = *(const float4*)&hs[r][k];
            acc[r] += hv.x * w0 + hv.y * w1 + hv.z * w2 + hv.w * w3;
        }
    }
    __syncthreads();
#pragma unroll
    for (int r = 0; r < 16; r++) hs[r][t] = acc[r];
    __syncthreads();
    for (int i = t; i < 16 * 64; i += 128) {
        int r = i >> 6, c2 = i & 63;
        int row = row0 + r;
        if (row < n)
            g_ft1h[row * 64 + c2] = __floats2half2_rn(hs[r][c2 * 2], hs[r][c2 * 2 + 1]);
    }
    int lane = t & 31, w = t >> 5;
    float a0 = al1[lane], a1 = al1[lane + 32], a2 = al1[lane + 64], a3 = al1[lane + 96];
    float r0 = ar1[lane], r1 = ar1[lane + 32], r2 = ar1[lane + 64], r3 = ar1[lane + 96];
#pragma unroll
    for (int rr = 0; rr < 4; rr++) {
        int r = w * 4 + rr;
        int row = row0 + r;
        float f0 = hs[r][lane], f1 = hs[r][lane + 32];
        float f2 = hs[r][lane + 64], f3 = hs[r][lane + 96];
        float el0 = f0 * a0 + f1 * a1, er0 = f0 * r0 + f1 * r1;
        float el1v = f2 * a2 + f3 * a3, er1v = f2 * r2 + f3 * r3;
#pragma unroll
        for (int o = 16; o; o >>= 1) {
            el0  += __shfl_xor_sync(FULL, el0, o);
            er0  += __shfl_xor_sync(FULL, er0, o);
            el1v += __shfl_xor_sync(FULL, el1v, o);
            er1v += __shfl_xor_sync(FULL, er1v, o);
        }
        if (lane == 0 && row < n) {
            g_el1[row] = make_float2(el0, el1v);
            g_er1[row] = make_float2(er0, er1v);
        }
    }
}

// ---------------- layer-1 aggregation: warp per node ----------------
__global__ void agg1_kernel(const float* __restrict__ b1, int n) {
    int node = (blockIdx.x * blockDim.x + threadIdx.x) >> 5;
    int lane = threadIdx.x & 31;
    if (node >= n) return;
    int beg = g_rowptr[node], end = g_rowptr[node + 1];
    float2 er = g_er1[node];

    float m0 = -CUDART_INF_F, m1 = -CUDART_INF_F;
    for (int k = beg + lane; k < end; k += 32) {
        float2 el = g_el1[g_edge[k].x];
        m0 = fmaxf(m0, lrelu(el.x + er.x));
        m1 = fmaxf(m1, lrelu(el.y + er.y));
    }
#pragma unroll
    for (int o = 16; o; o >>= 1) {
        m0 = fmaxf(m0, __shfl_xor_sync(FULL, m0, o));
        m1 = fmaxf(m1, __shfl_xor_sync(FULL, m1, o));
    }

    float4 acc = make_float4(0.f, 0.f, 0.f, 0.f);
    float s0 = 0.f, s1 = 0.f;
    for (int base = beg; base < end; base += 32) {
        int k = base + lane;
        int sidx = 0;
        float ex0 = 0.f, ex1 = 0.f;
        if (k < end) {
            sidx = g_edge[k].x;
            float2 el = g_el1[sidx];
            ex0 = expf(lrelu(el.x + er.x) - m0);
            ex1 = expf(lrelu(el.y + er.y) - m1);
            s0 += ex0;
            s1 += ex1;
        }
        int cnt = min(32, end - base);
        for (int j = 0; j < cnt; j++) {
            float x0 = __shfl_sync(FULL, ex0, j);
            float x1 = __shfl_sync(FULL, ex1, j);
            int   sj = __shfl_sync(FULL, sidx, j);
            float myex = (lane < 16) ? x0 : x1;
            uint2 raw = *(const uint2*)(g_ft1h + sj * 64 + lane * 2);
            float2 f01 = __half22float2(*reinterpret_cast<__half2*>(&raw.x));
            float2 f23 = __half22float2(*reinterpret_cast<__half2*>(&raw.y));
            acc.x += myex * f01.x;
            acc.y += myex * f01.y;
            acc.z += myex * f23.x;
            acc.w += myex * f23.y;
        }
    }
#pragma unroll
    for (int o = 16; o; o >>= 1) {
        s0 += __shfl_xor_sync(FULL, s0, o);
        s1 += __shfl_xor_sync(FULL, s1, o);
    }
    float inv0 = (s0 > 0.f) ? 1.f / s0 : 0.f;
    float inv1 = (s1 > 0.f) ? 1.f / s1 : 0.f;
    float inv = (lane < 16) ? inv0 : inv1;
    float4 bv = *(const float4*)(b1 + lane * 4);
    float4 o4;
    o4.x = eluf(acc.x * inv + bv.x);
    o4.y = eluf(acc.y * inv + bv.y);
    o4.z = eluf(acc.z * inv + bv.z);
    o4.w = eluf(acc.w * inv + bv.w);
    *(float4*)(g_h1 + node * F1 + lane * 4) = o4;
}

// ---------------- GEMM2 + fused el2/er2 ----------------
__global__ void gemm2_kernel(const float* __restrict__ al2,
                             const float* __restrict__ ar2, int n) {
    __shared__ float hs[16][F1];
    int t = threadIdx.x;
    int row0 = blockIdx.x * 16;
    for (int i = t; i < 512; i += 128) {
        int r = i >> 5, j4 = i & 31;
        int row = row0 + r;
        float4 v = make_float4(0.f, 0.f, 0.f, 0.f);
        if (row < n) v = *(const float4*)(g_h1 + row * F1 + j4 * 4);
        *(float4*)&hs[r][j4 * 4] = v;
    }
    __syncthreads();
    int c = t & 31, g = t >> 5;
    float acc[4] = {0.f, 0.f, 0.f, 0.f};
    for (int k = 0; k < F1; k += 4) {
        float w0 = g_Wc[k * 32 + c];
        float w1 = g_Wc[(k + 1) * 32 + c];
        float w2 = g_Wc[(k + 2) * 32 + c];
        float w3 = g_Wc[(k + 3) * 32 + c];
#pragma unroll
        for (int rr = 0; rr < 4; rr++) {
            float4 hv = *(const float4*)&hs[g * 4 + rr][k];
            acc[rr] += hv.x * w0 + hv.y * w1 + hv.z * w2 + hv.w * w3;
        }
    }
    float a2 = (c < 16) ? al2[c] : 0.f;
    float r2v = (c < 16) ? ar2[c] : 0.f;
#pragma unroll
    for (int rr = 0; rr < 4; rr++) {
        int row = row0 + g * 4 + rr;
        if (row < n) {
            if (c < 16) g_ft2h[row * 16 + c] = __float2half(acc[rr]);
            else        g_res[row * 16 + (c - 16)] = acc[rr];
        }
        float el = acc[rr] * a2, er = acc[rr] * r2v;
#pragma unroll
        for (int o = 8; o; o >>= 1) {
            el += __shfl_xor_sync(FULL, el, o);
            er += __shfl_xor_sync(FULL, er, o);
        }
        if (c == 0 && row < n) {
            g_el2[row] = el;
            g_er2[row] = er;
        }
    }
}

// ---------------- layer-2 agg: two nodes per warp ----------------
__global__ void agg2_kernel(const float* __restrict__ b2,
                            float* __restrict__ out,
                            float* __restrict__ out_alpha,
                            int n, int write_alpha) {
    int warp = (blockIdx.x * blockDim.x + threadIdx.x) >> 5;
    int lane = threadIdx.x & 31;
    int half = lane >> 4;
    int l = lane & 15;
    int node = warp * 2 + half;
    if (node >= n) return;
    unsigned mask = 0xFFFFu << (half * 16);
    int beg = g_rowptr[node], end = g_rowptr[node + 1];
    float er = g_er2[node];

    float m = -CUDART_INF_F;
    for (int k = beg + l; k < end; k += 16)
        m = fmaxf(m, lrelu(g_el2[g_edge[k].x] + er));
#pragma unroll
    for (int o = 8; o; o >>= 1) m = fmaxf(m, __shfl_xor_sync(mask, m, o));

    float acc = 0.f, ssum = 0.f;
    for (int base = beg; base < end; base += 16) {
        int k = base + l;
        int sidx = 0;
        float ex = 0.f;
        if (k < end) {
            sidx = g_edge[k].x;
            ex = expf(lrelu(g_el2[sidx] + er) - m);
            ssum += ex;
        }
        int cnt = min(16, end - base);
        for (int j = 0; j < cnt; j++) {
            float x = __shfl_sync(mask, ex, j, 16);
            int  sj = __shfl_sync(mask, sidx, j, 16);
            acc += x * __half2float(g_ft2h[sj * 16 + l]);
        }
    }
#pragma unroll
    for (int o = 8; o; o >>= 1) ssum += __shfl_xor_sync(mask, ssum, o);
    float inv = (ssum > 0.f) ? 1.f / ssum : 0.f;
    out[node * 16 + l] = acc * inv + b2[l] + g_res[node * 16 + l];
    if (write_alpha) {
        for (int k = beg + l; k < end; k += 16) {
            int2 epk = g_edge[k];
            float ex = expf(lrelu(g_el2[epk.x] + er) - m);
            out_alpha[epk.y] = ex * inv;
        }
    }
}

// ---------------- launcher ----------------
extern "C" void kernel_launch(void* const* d_in, const int* in_sizes, int n_in,
                              void* d_out, int out_size) {
    const float* h    = (const float*)d_in[0];
    const int*   src  = (const int*)  d_in[1];
    const int*   dst  = (const int*)  d_in[2];
    const float* W1   = (const float*)d_in[3];
    const float* al1  = (const float*)d_in[4];
    const float* ar1  = (const float*)d_in[5];
    const float* b1   = (const float*)d_in[6];
    const float* W2   = (const float*)d_in[7];
    const float* al2  = (const float*)d_in[8];
    const float* ar2  = (const float*)d_in[9];
    const float* b2   = (const float*)d_in[10];
    const float* Wres = (const float*)d_in[11];
    float* out = (float*)d_out;

    int n = in_sizes[0] / F1;
    int e = in_sizes[1];
    if (n > N_MAX || e > E_MAX) return;

    const int T = 256;
    int write_alpha = (out_size >= n * 16 + e) ? 1 : 0;

    static cudaStream_t s_side = nullptr;
    static cudaEvent_t ev_fork = nullptr, ev_join = nullptr;
    if (s_side == nullptr) {
        cudaStreamCreateWithFlags(&s_side, cudaStreamNonBlocking);
        cudaEventCreateWithFlags(&ev_fork, cudaEventDisableTiming);
        cudaEventCreateWithFlags(&ev_join, cudaEventDisableTiming);
    }

    // fork: gemm1 on side stream (independent of CSR build)
    cudaEventRecord(ev_fork, 0);
    cudaStreamWaitEvent(s_side, ev_fork, 0);
    gemm1_kernel<<<(n + 15) / 16, 128, 0, s_side>>>(h, W1, al1, ar1, n);
    cudaEventRecord(ev_join, s_side);

    // main chain: CSR build
    int nb = (n + SCAN_B - 1) / SCAN_B;
    prep_kernel<<<(max(n, F1 * 32) + T - 1) / T, T>>>(W2, Wres, n);
    deg_kernel<<<(e + 8 * T - 1) / (8 * T), T>>>(dst, e);
    scan_local<<<nb, SCAN_B>>>(n);
    scan_tops<<<1, 128>>>(nb);
    scan_add<<<(n + 1 + T - 1) / T, T>>>(n, e);
    scatter_kernel<<<(e + 8 * T - 1) / (8 * T), T>>>(src, dst, e);

    // join, then dependent chain
    cudaStreamWaitEvent(0, ev_join, 0);
    agg1_kernel<<<((long long)n * 32 + T - 1) / T, T>>>(b1, n);
    gemm2_kernel<<<(n + 15) / 16, 128>>>(al2, ar2, n);
    agg2_kernel<<<((long long)((n + 1) / 2) * 32 + T - 1) / T, T>>>(
        b2, out, out + n * 16, n, write_alpha);
}

// round 7
// speedup vs baseline: 1.9827x; 1.0196x over previous
#include <cuda_runtime.h>
#include <cuda_fp16.h>
#include <math_constants.h>

#define N_MAX 50000
#define E_MAX 800000
#define F1 128
#define SLOPE 0.2f
#define FULL 0xffffffffu
#define SCAN_B 512

// ---------------- scratch ----------------
__device__ __half2 g_ft1h[N_MAX * 64];   // layer-1 features, fp16 pairs
__device__ float g_h1[N_MAX * F1];
__device__ float2 g_el1[N_MAX];
__device__ float2 g_er1[N_MAX];
__device__ __half g_ft2h[N_MAX * 16];    // layer-2 features (gathered), fp16
__device__ float g_res[N_MAX * 16];      // residual
__device__ float g_el2[N_MAX];
__device__ float g_er2[N_MAX];
__device__ float g_Wc[F1 * 32];          // [W2 | Wres]
__device__ int g_deg[N_MAX];
__device__ int g_rowptr[N_MAX + 1];
__device__ int g_cursor[N_MAX];
__device__ int g_blocksum[128];
__device__ int2 g_edge[E_MAX];           // (src, orig_edge_idx) sorted by dst

__device__ __forceinline__ float lrelu(float x) { return x > 0.f ? x : SLOPE * x; }
__device__ __forceinline__ float eluf(float x)  { return x > 0.f ? x : expf(x) - 1.f; }

// ---------------- CSR build ----------------
__global__ void prep_kernel(const float* __restrict__ W2,
                            const float* __restrict__ Wres, int n) {
    int i = blockIdx.x * blockDim.x + threadIdx.x;
    if (i < n) g_deg[i] = 0;
    if (i < F1 * 32) {
        int k = i >> 5, c = i & 31;
        g_Wc[i] = (c < 16) ? W2[k * 16 + c] : Wres[k * 16 + (c - 16)];
    }
}

__global__ void deg_kernel(const int* __restrict__ dst, int e) {
    int base = (blockIdx.x * blockDim.x + threadIdx.x) * 8;
    if (base + 8 <= e) {
        int4 a = *(const int4*)(dst + base);
        int4 b = *(const int4*)(dst + base + 4);
        atomicAdd(&g_deg[a.x], 1); atomicAdd(&g_deg[a.y], 1);
        atomicAdd(&g_deg[a.z], 1); atomicAdd(&g_deg[a.w], 1);
        atomicAdd(&g_deg[b.x], 1); atomicAdd(&g_deg[b.y], 1);
        atomicAdd(&g_deg[b.z], 1); atomicAdd(&g_deg[b.w], 1);
    } else {
        for (int k = base; k < e; k++) atomicAdd(&g_deg[dst[k]], 1);
    }
}

__global__ void scan_local(int n) {
    __shared__ int sm[SCAN_B];
    int t = threadIdx.x;
    int i = blockIdx.x * SCAN_B + t;
    int v = (i < n) ? g_deg[i] : 0;
    sm[t] = v;
    __syncthreads();
    for (int off = 1; off < SCAN_B; off <<= 1) {
        int u = (t >= off) ? sm[t - off] : 0;
        __syncthreads();
        sm[t] += u;
        __syncthreads();
    }
    if (i < n) g_rowptr[i] = sm[t] - v;
    if (t == SCAN_B - 1) g_blocksum[blockIdx.x] = sm[t];
}

__global__ void scan_tops(int nb) {
    __shared__ int sm[128];
    int t = threadIdx.x;
    int v = (t < nb) ? g_blocksum[t] : 0;
    sm[t] = v;
    __syncthreads();
    for (int off = 1; off < 128; off <<= 1) {
        int u = (t >= off) ? sm[t - off] : 0;
        __syncthreads();
        sm[t] += u;
        __syncthreads();
    }
    if (t < nb) g_blocksum[t] = sm[t] - v;
}

__global__ void scan_add(int n, int e) {
    int i = blockIdx.x * blockDim.x + threadIdx.x;
    if (i < n) {
        int v = g_rowptr[i] + g_blocksum[i / SCAN_B];
        g_rowptr[i] = v;
        g_cursor[i] = v;
    }
    if (i == n) g_rowptr[n] = e;
}

__global__ void scatter_kernel(const int* __restrict__ src,
                               const int* __restrict__ dst, int e) {
    int base = (blockIdx.x * blockDim.x + threadIdx.x) * 8;
    if (base + 8 <= e) {
        int4 d0 = *(const int4*)(dst + base);
        int4 d1 = *(const int4*)(dst + base + 4);
        int4 s0 = *(const int4*)(src + base);
        int4 s1 = *(const int4*)(src + base + 4);
        int p0 = atomicAdd(&g_cursor[d0.x], 1);
        int p1 = atomicAdd(&g_cursor[d0.y], 1);
        int p2 = atomicAdd(&g_cursor[d0.z], 1);
        int p3 = atomicAdd(&g_cursor[d0.w], 1);
        int p4 = atomicAdd(&g_cursor[d1.x], 1);
        int p5 = atomicAdd(&g_cursor[d1.y], 1);
        int p6 = atomicAdd(&g_cursor[d1.z], 1);
        int p7 = atomicAdd(&g_cursor[d1.w], 1);
        g_edge[p0] = make_int2(s0.x, base);
        g_edge[p1] = make_int2(s0.y, base + 1);
        g_edge[p2] = make_int2(s0.z, base + 2);
        g_edge[p3] = make_int2(s0.w, base + 3);
        g_edge[p4] = make_int2(s1.x, base + 4);
        g_edge[p5] = make_int2(s1.y, base + 5);
        g_edge[p6] = make_int2(s1.z, base + 6);
        g_edge[p7] = make_int2(s1.w, base + 7);
    } else {
        for (int k = base; k < e; k++) {
            int pos = atomicAdd(&g_cursor[dst[k]], 1);
            g_edge[pos] = make_int2(src[k], k);
        }
    }
}

// ---------------- GEMM1 + fused el1/er1, fp16 ft1 output ----------------
__global__ void gemm1_kernel(const float* __restrict__ h,
                             const float* __restrict__ W1,
                             const float* __restrict__ al1,
                             const float* __restrict__ ar1, int n) {
    __shared__ float hs[16][F1];
    int t = threadIdx.x;
    int row0 = blockIdx.x * 16;
    for (int i = t; i < 512; i += 128) {
        int r = i >> 5, j4 = i & 31;
        int row = row0 + r;
        float4 v = make_float4(0.f, 0.f, 0.f, 0.f);
        if (row < n) v = *(const float4*)(h + row * F1 + j4 * 4);
        *(float4*)&hs[r][j4 * 4] = v;
    }
    __syncthreads();
    float acc[16];
#pragma unroll
    for (int r = 0; r < 16; r++) acc[r] = 0.f;
    for (int k = 0; k < F1; k += 4) {
        float w0 = __ldg(&W1[k * F1 + t]);
        float w1 = __ldg(&W1[(k + 1) * F1 + t]);
        float w2 = __ldg(&W1[(k + 2) * F1 + t]);
        float w3 = __ldg(&W1[(k + 3) * F1 + t]);
#pragma unroll
        for (int r = 0; r < 16; r++) {
            float4 hv = *(const float4*)&hs[r][k];
            acc[r] += hv.x * w0 + hv.y * w1 + hv.z * w2 + hv.w * w3;
        }
    }
    __syncthreads();
#pragma unroll
    for (int r = 0; r < 16; r++) hs[r][t] = acc[r];
    __syncthreads();
    for (int i = t; i < 16 * 64; i += 128) {
        int r = i >> 6, c2 = i & 63;
        int row = row0 + r;
        if (row < n)
            g_ft1h[row * 64 + c2] = __floats2half2_rn(hs[r][c2 * 2], hs[r][c2 * 2 + 1]);
    }
    int lane = t & 31, w = t >> 5;
    float a0 = al1[lane], a1 = al1[lane + 32], a2 = al1[lane + 64], a3 = al1[lane + 96];
    float r0 = ar1[lane], r1 = ar1[lane + 32], r2 = ar1[lane + 64], r3 = ar1[lane + 96];
#pragma unroll
    for (int rr = 0; rr < 4; rr++) {
        int r = w * 4 + rr;
        int row = row0 + r;
        float f0 = hs[r][lane], f1 = hs[r][lane + 32];
        float f2 = hs[r][lane + 64], f3 = hs[r][lane + 96];
        float el0 = f0 * a0 + f1 * a1, er0 = f0 * r0 + f1 * r1;
        float el1v = f2 * a2 + f3 * a3, er1v = f2 * r2 + f3 * r3;
#pragma unroll
        for (int o = 16; o; o >>= 1) {
            el0  += __shfl_xor_sync(FULL, el0, o);
            er0  += __shfl_xor_sync(FULL, er0, o);
            el1v += __shfl_xor_sync(FULL, el1v, o);
            er1v += __shfl_xor_sync(FULL, er1v, o);
        }
        if (lane == 0 && row < n) {
            g_el1[row] = make_float2(el0, el1v);
            g_er1[row] = make_float2(er0, er1v);
        }
    }
}

// ------- layer-1 aggregation: warp per node, ONE pass (no max subtract) ----
__global__ void agg1_kernel(const float* __restrict__ b1, int n) {
    int node = (blockIdx.x * blockDim.x + threadIdx.x) >> 5;
    int lane = threadIdx.x & 31;
    if (node >= n) return;
    int beg = g_rowptr[node], end = g_rowptr[node + 1];
    float2 er = g_er1[node];

    float4 acc = make_float4(0.f, 0.f, 0.f, 0.f);
    float s0 = 0.f, s1 = 0.f;
    for (int base = beg; base < end; base += 32) {
        int k = base + lane;
        int sidx = 0;
        float ex0 = 0.f, ex1 = 0.f;
        if (k < end) {
            sidx = g_edge[k].x;
            float2 el = g_el1[sidx];
            ex0 = expf(lrelu(el.x + er.x));
            ex1 = expf(lrelu(el.y + er.y));
            s0 += ex0;
            s1 += ex1;
        }
        int cnt = min(32, end - base);
        if (cnt == 32) {
#pragma unroll 4
            for (int j = 0; j < 32; j++) {
                float x0 = __shfl_sync(FULL, ex0, j);
                float x1 = __shfl_sync(FULL, ex1, j);
                int   sj = __shfl_sync(FULL, sidx, j);
                float myex = (lane < 16) ? x0 : x1;
                uint2 raw = *(const uint2*)(g_ft1h + sj * 64 + lane * 2);
                float2 f01 = __half22float2(*reinterpret_cast<__half2*>(&raw.x));
                float2 f23 = __half22float2(*reinterpret_cast<__half2*>(&raw.y));
                acc.x += myex * f01.x;
                acc.y += myex * f01.y;
                acc.z += myex * f23.x;
                acc.w += myex * f23.y;
            }
        } else {
            for (int j = 0; j < cnt; j++) {
                float x0 = __shfl_sync(FULL, ex0, j);
                float x1 = __shfl_sync(FULL, ex1, j);
                int   sj = __shfl_sync(FULL, sidx, j);
                float myex = (lane < 16) ? x0 : x1;
                uint2 raw = *(const uint2*)(g_ft1h + sj * 64 + lane * 2);
                float2 f01 = __half22float2(*reinterpret_cast<__half2*>(&raw.x));
                float2 f23 = __half22float2(*reinterpret_cast<__half2*>(&raw.y));
                acc.x += myex * f01.x;
                acc.y += myex * f01.y;
                acc.z += myex * f23.x;
                acc.w += myex * f23.y;
            }
        }
    }
#pragma unroll
    for (int o = 16; o; o >>= 1) {
        s0 += __shfl_xor_sync(FULL, s0, o);
        s1 += __shfl_xor_sync(FULL, s1, o);
    }
    float inv0 = (s0 > 0.f) ? 1.f / s0 : 0.f;
    float inv1 = (s1 > 0.f) ? 1.f / s1 : 0.f;
    float inv = (lane < 16) ? inv0 : inv1;
    float4 bv = *(const float4*)(b1 + lane * 4);
    float4 o4;
    o4.x = eluf(acc.x * inv + bv.x);
    o4.y = eluf(acc.y * inv + bv.y);
    o4.z = eluf(acc.z * inv + bv.z);
    o4.w = eluf(acc.w * inv + bv.w);
    *(float4*)(g_h1 + node * F1 + lane * 4) = o4;
}

// ---------------- GEMM2 + fused el2/er2 ----------------
__global__ void gemm2_kernel(const float* __restrict__ al2,
                             const float* __restrict__ ar2, int n) {
    __shared__ float hs[16][F1];
    int t = threadIdx.x;
    int row0 = blockIdx.x * 16;
    for (int i = t; i < 512; i += 128) {
        int r = i >> 5, j4 = i & 31;
        int row = row0 + r;
        float4 v = make_float4(0.f, 0.f, 0.f, 0.f);
        if (row < n) v = *(const float4*)(g_h1 + row * F1 + j4 * 4);
        *(float4*)&hs[r][j4 * 4] = v;
    }
    __syncthreads();
    int c = t & 31, g = t >> 5;
    float acc[4] = {0.f, 0.f, 0.f, 0.f};
    for (int k = 0; k < F1; k += 4) {
        float w0 = g_Wc[k * 32 + c];
        float w1 = g_Wc[(k + 1) * 32 + c];
        float w2 = g_Wc[(k + 2) * 32 + c];
        float w3 = g_Wc[(k + 3) * 32 + c];
#pragma unroll
        for (int rr = 0; rr < 4; rr++) {
            float4 hv = *(const float4*)&hs[g * 4 + rr][k];
            acc[rr] += hv.x * w0 + hv.y * w1 + hv.z * w2 + hv.w * w3;
        }
    }
    float a2 = (c < 16) ? al2[c] : 0.f;
    float r2v = (c < 16) ? ar2[c] : 0.f;
#pragma unroll
    for (int rr = 0; rr < 4; rr++) {
        int row = row0 + g * 4 + rr;
        if (row < n) {
            if (c < 16) g_ft2h[row * 16 + c] = __float2half(acc[rr]);
            else        g_res[row * 16 + (c - 16)] = acc[rr];
        }
        float el = acc[rr] * a2, er = acc[rr] * r2v;
#pragma unroll
        for (int o = 8; o; o >>= 1) {
            el += __shfl_xor_sync(FULL, el, o);
            er += __shfl_xor_sync(FULL, er, o);
        }
        if (c == 0 && row < n) {
            g_el2[row] = el;
            g_er2[row] = er;
        }
    }
}

// -------- layer-2 agg: two nodes per warp, ONE pass (no max subtract) ------
__global__ void agg2_kernel(const float* __restrict__ b2,
                            float* __restrict__ out,
                            float* __restrict__ out_alpha,
                            int n, int write_alpha) {
    int warp = (blockIdx.x * blockDim.x + threadIdx.x) >> 5;
    int lane = threadIdx.x & 31;
    int half = lane >> 4;
    int l = lane & 15;
    int node = warp * 2 + half;
    if (node >= n) return;
    unsigned mask = 0xFFFFu << (half * 16);
    int beg = g_rowptr[node], end = g_rowptr[node + 1];
    float er = g_er2[node];

    float acc = 0.f, ssum = 0.f;
    for (int base = beg; base < end; base += 16) {
        int k = base + l;
        int sidx = 0;
        float ex = 0.f;
        if (k < end) {
            sidx = g_edge[k].x;
            ex = expf(lrelu(g_el2[sidx] + er));
            ssum += ex;
        }
        int cnt = min(16, end - base);
        if (cnt == 16) {
#pragma unroll 4
            for (int j = 0; j < 16; j++) {
                float x = __shfl_sync(mask, ex, j, 16);
                int  sj = __shfl_sync(mask, sidx, j, 16);
                acc += x * __half2float(g_ft2h[sj * 16 + l]);
            }
        } else {
            for (int j = 0; j < cnt; j++) {
                float x = __shfl_sync(mask, ex, j, 16);
                int  sj = __shfl_sync(mask, sidx, j, 16);
                acc += x * __half2float(g_ft2h[sj * 16 + l]);
            }
        }
    }
#pragma unroll
    for (int o = 8; o; o >>= 1) ssum += __shfl_xor_sync(mask, ssum, o);
    float inv = (ssum > 0.f) ? 1.f / ssum : 0.f;
    out[node * 16 + l] = acc * inv + b2[l] + g_res[node * 16 + l];
    if (write_alpha) {
        for (int k = beg + l; k < end; k += 16) {
            int2 epk = g_edge[k];
            float ex = expf(lrelu(g_el2[epk.x] + er));
            out_alpha[epk.y] = ex * inv;
        }
    }
}

// ---------------- launcher ----------------
extern "C" void kernel_launch(void* const* d_in, const int* in_sizes, int n_in,
                              void* d_out, int out_size) {
    const float* h    = (const float*)d_in[0];
    const int*   src  = (const int*)  d_in[1];
    const int*   dst  = (const int*)  d_in[2];
    const float* W1   = (const float*)d_in[3];
    const float* al1  = (const float*)d_in[4];
    const float* ar1  = (const float*)d_in[5];
    const float* b1   = (const float*)d_in[6];
    const float* W2   = (const float*)d_in[7];
    const float* al2  = (const float*)d_in[8];
    const float* ar2  = (const float*)d_in[9];
    const float* b2   = (const float*)d_in[10];
    const float* Wres = (const float*)d_in[11];
    float* out = (float*)d_out;

    int n = in_sizes[0] / F1;
    int e = in_sizes[1];
    if (n > N_MAX || e > E_MAX) return;

    const int T = 256;
    int write_alpha = (out_size >= n * 16 + e) ? 1 : 0;

    static cudaStream_t s_side = nullptr;
    static cudaEvent_t ev_fork = nullptr, ev_join = nullptr;
    if (s_side == nullptr) {
        cudaStreamCreateWithFlags(&s_side, cudaStreamNonBlocking);
        cudaEventCreateWithFlags(&ev_fork, cudaEventDisableTiming);
        cudaEventCreateWithFlags(&ev_join, cudaEventDisableTiming);
    }

    // fork: gemm1 on side stream (independent of CSR build)
    cudaEventRecord(ev_fork, 0);
    cudaStreamWaitEvent(s_side, ev_fork, 0);
    gemm1_kernel<<<(n + 15) / 16, 128, 0, s_side>>>(h, W1, al1, ar1, n);
    cudaEventRecord(ev_join, s_side);

    // main chain: CSR build
    int nb = (n + SCAN_B - 1) / SCAN_B;
    prep_kernel<<<(max(n, F1 * 32) + T - 1) / T, T>>>(W2, Wres, n);
    deg_kernel<<<(e + 8 * T - 1) / (8 * T), T>>>(dst, e);
    scan_local<<<nb, SCAN_B>>>(n);
    scan_tops<<<1, 128>>>(nb);
    scan_add<<<(n + 1 + T - 1) / T, T>>>(n, e);
    scatter_kernel<<<(e + 8 * T - 1) / (8 * T), T>>>(src, dst, e);

    // join, then dependent chain
    cudaStreamWaitEvent(0, ev_join, 0);
    agg1_kernel<<<((long long)n * 32 + T - 1) / T, T>>>(b1, n);
    gemm2_kernel<<<(n + 15) / 16, 128>>>(al2, ar2, n);
    agg2_kernel<<<((long long)((n + 1) / 2) * 32 + T - 1) / T, T>>>(
        b2, out, out + n * 16, n, write_alpha);
}

// round 8
// speedup vs baseline: 1.9970x; 1.0072x over previous
#include <cuda_runtime.h>
#include <cuda_fp16.h>
#include <math_constants.h>

#define N_MAX 50000
#define E_MAX 800000
#define F1 128
#define SLOPE 0.2f
#define FULL 0xffffffffu
#define SCAN_B 512

// ---------------- scratch ----------------
__device__ __half2 g_ft1h[N_MAX * 64];   // layer-1 features, fp16 pairs
__device__ float2 g_el1[N_MAX];
__device__ float2 g_er1[N_MAX];
__device__ __half g_ft2h[N_MAX * 16];    // layer-2 features (gathered), fp16
__device__ float g_res[N_MAX * 16];      // residual
__device__ float g_el2[N_MAX];
__device__ float g_er2[N_MAX];
__device__ float g_Wc[F1 * 32];          // [W2 | Wres]
__device__ int g_deg[N_MAX];
__device__ int g_rowptr[N_MAX + 1];
__device__ int g_cursor[N_MAX];
__device__ int g_blocksum[128];
__device__ int2 g_edge[E_MAX];           // (src, orig_edge_idx) sorted by dst

__device__ __forceinline__ float lrelu(float x) { return x > 0.f ? x : SLOPE * x; }
__device__ __forceinline__ float eluf(float x)  { return x > 0.f ? x : expf(x) - 1.f; }

// ---------------- CSR build ----------------
__global__ void prep_kernel(const float* __restrict__ W2,
                            const float* __restrict__ Wres, int n) {
    int i = blockIdx.x * blockDim.x + threadIdx.x;
    if (i < n) g_deg[i] = 0;
    if (i < F1 * 32) {
        int k = i >> 5, c = i & 31;
        g_Wc[i] = (c < 16) ? W2[k * 16 + c] : Wres[k * 16 + (c - 16)];
    }
}

__global__ void deg_kernel(const int* __restrict__ dst, int e) {
    int base = (blockIdx.x * blockDim.x + threadIdx.x) * 8;
    if (base + 8 <= e) {
        int4 a = *(const int4*)(dst + base);
        int4 b = *(const int4*)(dst + base + 4);
        atomicAdd(&g_deg[a.x], 1); atomicAdd(&g_deg[a.y], 1);
        atomicAdd(&g_deg[a.z], 1); atomicAdd(&g_deg[a.w], 1);
        atomicAdd(&g_deg[b.x], 1); atomicAdd(&g_deg[b.y], 1);
        atomicAdd(&g_deg[b.z], 1); atomicAdd(&g_deg[b.w], 1);
    } else {
        for (int k = base; k < e; k++) atomicAdd(&g_deg[dst[k]], 1);
    }
}

__global__ void scan_local(int n) {
    __shared__ int sm[SCAN_B];
    int t = threadIdx.x;
    int i = blockIdx.x * SCAN_B + t;
    int v = (i < n) ? g_deg[i] : 0;
    sm[t] = v;
    __syncthreads();
    for (int off = 1; off < SCAN_B; off <<= 1) {
        int u = (t >= off) ? sm[t - off] : 0;
        __syncthreads();
        sm[t] += u;
        __syncthreads();
    }
    if (i < n) g_rowptr[i] = sm[t] - v;
    if (t == SCAN_B - 1) g_blocksum[blockIdx.x] = sm[t];
}

// scan_add with the 98-entry top-level scan inlined (replaces scan_tops)
__global__ void scan_add(int n, int e, int nb) {
    __shared__ int bs[128];
    int t = threadIdx.x;
    if (t < 128) bs[t] = (t < nb) ? g_blocksum[t] : 0;
    __syncthreads();
    for (int off = 1; off < 128; off <<= 1) {
        int u = 0;
        if (t < 128 && t >= off) u = bs[t - off];
        __syncthreads();
        if (t < 128) bs[t] += u;
        __syncthreads();
    }
    int i = blockIdx.x * blockDim.x + t;
    if (i < n) {
        int b = i / SCAN_B;
        int v = g_rowptr[i] + ((b == 0) ? 0 : bs[b - 1]);
        g_rowptr[i] = v;
        g_cursor[i] = v;
    }
    if (i == n) g_rowptr[n] = e;
}

__global__ void scatter_kernel(const int* __restrict__ src,
                               const int* __restrict__ dst, int e) {
    int base = (blockIdx.x * blockDim.x + threadIdx.x) * 8;
    if (base + 8 <= e) {
        int4 d0 = *(const int4*)(dst + base);
        int4 d1 = *(const int4*)(dst + base + 4);
        int4 s0 = *(const int4*)(src + base);
        int4 s1 = *(const int4*)(src + base + 4);
        int p0 = atomicAdd(&g_cursor[d0.x], 1);
        int p1 = atomicAdd(&g_cursor[d0.y], 1);
        int p2 = atomicAdd(&g_cursor[d0.z], 1);
        int p3 = atomicAdd(&g_cursor[d0.w], 1);
        int p4 = atomicAdd(&g_cursor[d1.x], 1);
        int p5 = atomicAdd(&g_cursor[d1.y], 1);
        int p6 = atomicAdd(&g_cursor[d1.z], 1);
        int p7 = atomicAdd(&g_cursor[d1.w], 1);
        g_edge[p0] = make_int2(s0.x, base);
        g_edge[p1] = make_int2(s0.y, base + 1);
        g_edge[p2] = make_int2(s0.z, base + 2);
        g_edge[p3] = make_int2(s0.w, base + 3);
        g_edge[p4] = make_int2(s1.x, base + 4);
        g_edge[p5] = make_int2(s1.y, base + 5);
        g_edge[p6] = make_int2(s1.z, base + 6);
        g_edge[p7] = make_int2(s1.w, base + 7);
    } else {
        for (int k = base; k < e; k++) {
            int pos = atomicAdd(&g_cursor[dst[k]], 1);
            g_edge[pos] = make_int2(src[k], k);
        }
    }
}

// ---------------- GEMM1 + fused el1/er1, fp16 ft1 output ----------------
__global__ void gemm1_kernel(const float* __restrict__ h,
                             const float* __restrict__ W1,
                             const float* __restrict__ al1,
                             const float* __restrict__ ar1, int n) {
    __shared__ float hs[16][F1];
    int t = threadIdx.x;
    int row0 = blockIdx.x * 16;
    for (int i = t; i < 512; i += 128) {
        int r = i >> 5, j4 = i & 31;
        int row = row0 + r;
        float4 v = make_float4(0.f, 0.f, 0.f, 0.f);
        if (row < n) v = *(const float4*)(h + row * F1 + j4 * 4);
        *(float4*)&hs[r][j4 * 4] = v;
    }
    __syncthreads();
    float acc[16];
#pragma unroll
    for (int r = 0; r < 16; r++) acc[r] = 0.f;
    for (int k = 0; k < F1; k += 4) {
        float w0 = __ldg(&W1[k * F1 + t]);
        float w1 = __ldg(&W1[(k + 1) * F1 + t]);
        float w2 = __ldg(&W1[(k + 2) * F1 + t]);
        float w3 = __ldg(&W1[(k + 3) * F1 + t]);
#pragma unroll
        for (int r = 0; r < 16; r++) {
            float4 hv = *(const float4*)&hs[r][k];
            acc[r] += hv.x * w0 + hv.y * w1 + hv.z * w2 + hv.w * w3;
        }
    }
    __syncthreads();
#pragma unroll
    for (int r = 0; r < 16; r++) hs[r][t] = acc[r];
    __syncthreads();
    for (int i = t; i < 16 * 64; i += 128) {
        int r = i >> 6, c2 = i & 63;
        int row = row0 + r;
        if (row < n)
            g_ft1h[row * 64 + c2] = __floats2half2_rn(hs[r][c2 * 2], hs[r][c2 * 2 + 1]);
    }
    int lane = t & 31, w = t >> 5;
    float a0 = al1[lane], a1 = al1[lane + 32], a2 = al1[lane + 64], a3 = al1[lane + 96];
    float r0 = ar1[lane], r1 = ar1[lane + 32], r2 = ar1[lane + 64], r3 = ar1[lane + 96];
#pragma unroll
    for (int rr = 0; rr < 4; rr++) {
        int r = w * 4 + rr;
        int row = row0 + r;
        float f0 = hs[r][lane], f1 = hs[r][lane + 32];
        float f2 = hs[r][lane + 64], f3 = hs[r][lane + 96];
        float el0 = f0 * a0 + f1 * a1, er0 = f0 * r0 + f1 * r1;
        float el1v = f2 * a2 + f3 * a3, er1v = f2 * r2 + f3 * r3;
#pragma unroll
        for (int o = 16; o; o >>= 1) {
            el0  += __shfl_xor_sync(FULL, el0, o);
            er0  += __shfl_xor_sync(FULL, er0, o);
            el1v += __shfl_xor_sync(FULL, el1v, o);
            er1v += __shfl_xor_sync(FULL, er1v, o);
        }
        if (lane == 0 && row < n) {
            g_el1[row] = make_float2(el0, el1v);
            g_er1[row] = make_float2(er0, er1v);
        }
    }
}

// ------ FUSED: layer-1 aggregation (agg1) + GEMM2 + el2/er2 ------
// Block = 128 threads handles 16 nodes. Phase A: each warp aggregates 4
// nodes into smem h1 rows. Phase B: gemm2 on the smem tile.
__global__ void l2_fused_kernel(const float* __restrict__ b1,
                                const float* __restrict__ al2,
                                const float* __restrict__ ar2, int n) {
    __shared__ float hs[16][F1];
    int t = threadIdx.x;
    int lane = t & 31, w = t >> 5;
    int row0 = blockIdx.x * 16;

    float4 bv = *(const float4*)(b1 + lane * 4);

    // ---- phase A: aggregate 4 nodes per warp ----
#pragma unroll
    for (int rr = 0; rr < 4; rr++) {
        int r = w * 4 + rr;
        int node = row0 + r;
        if (node >= n) {
            *(float4*)&hs[r][lane * 4] = make_float4(0.f, 0.f, 0.f, 0.f);
            continue;
        }
        int beg = g_rowptr[node], end = g_rowptr[node + 1];
        float2 er = g_er1[node];
        float4 acc = make_float4(0.f, 0.f, 0.f, 0.f);
        float s0 = 0.f, s1 = 0.f;
        for (int base = beg; base < end; base += 32) {
            int k = base + lane;
            int sidx = 0;
            float ex0 = 0.f, ex1 = 0.f;
            if (k < end) {
                sidx = g_edge[k].x;
                float2 el = g_el1[sidx];
                ex0 = expf(lrelu(el.x + er.x));
                ex1 = expf(lrelu(el.y + er.y));
                s0 += ex0;
                s1 += ex1;
            }
            int cnt = min(32, end - base);
            if (cnt == 32) {
#pragma unroll 4
                for (int j = 0; j < 32; j++) {
                    float x0 = __shfl_sync(FULL, ex0, j);
                    float x1 = __shfl_sync(FULL, ex1, j);
                    int   sj = __shfl_sync(FULL, sidx, j);
                    float myex = (lane < 16) ? x0 : x1;
                    uint2 raw = *(const uint2*)(g_ft1h + sj * 64 + lane * 2);
                    float2 f01 = __half22float2(*reinterpret_cast<__half2*>(&raw.x));
                    float2 f23 = __half22float2(*reinterpret_cast<__half2*>(&raw.y));
                    acc.x += myex * f01.x;
                    acc.y += myex * f01.y;
                    acc.z += myex * f23.x;
                    acc.w += myex * f23.y;
                }
            } else {
                for (int j = 0; j < cnt; j++) {
                    float x0 = __shfl_sync(FULL, ex0, j);
                    float x1 = __shfl_sync(FULL, ex1, j);
                    int   sj = __shfl_sync(FULL, sidx, j);
                    float myex = (lane < 16) ? x0 : x1;
                    uint2 raw = *(const uint2*)(g_ft1h + sj * 64 + lane * 2);
                    float2 f01 = __half22float2(*reinterpret_cast<__half2*>(&raw.x));
                    float2 f23 = __half22float2(*reinterpret_cast<__half2*>(&raw.y));
                    acc.x += myex * f01.x;
                    acc.y += myex * f01.y;
                    acc.z += myex * f23.x;
                    acc.w += myex * f23.y;
                }
            }
        }
#pragma unroll
        for (int o = 16; o; o >>= 1) {
            s0 += __shfl_xor_sync(FULL, s0, o);
            s1 += __shfl_xor_sync(FULL, s1, o);
        }
        float inv0 = (s0 > 0.f) ? 1.f / s0 : 0.f;
        float inv1 = (s1 > 0.f) ? 1.f / s1 : 0.f;
        float inv = (lane < 16) ? inv0 : inv1;
        float4 o4;
        o4.x = eluf(acc.x * inv + bv.x);
        o4.y = eluf(acc.y * inv + bv.y);
        o4.z = eluf(acc.z * inv + bv.z);
        o4.w = eluf(acc.w * inv + bv.w);
        *(float4*)&hs[r][lane * 4] = o4;
    }
    __syncthreads();

    // ---- phase B: gemm2 ([ft2 | res] = h1 @ [W2 | Wres]) + eler2 ----
    int c = t & 31, g = t >> 5;
    float acc2[4] = {0.f, 0.f, 0.f, 0.f};
    for (int k = 0; k < F1; k += 4) {
        float w0 = g_Wc[k * 32 + c];
        float w1 = g_Wc[(k + 1) * 32 + c];
        float w2 = g_Wc[(k + 2) * 32 + c];
        float w3 = g_Wc[(k + 3) * 32 + c];
#pragma unroll
        for (int rr = 0; rr < 4; rr++) {
            float4 hv = *(const float4*)&hs[g * 4 + rr][k];
            acc2[rr] += hv.x * w0 + hv.y * w1 + hv.z * w2 + hv.w * w3;
        }
    }
    float a2 = (c < 16) ? al2[c] : 0.f;
    float r2v = (c < 16) ? ar2[c] : 0.f;
#pragma unroll
    for (int rr = 0; rr < 4; rr++) {
        int row = row0 + g * 4 + rr;
        if (row < n) {
            if (c < 16) g_ft2h[row * 16 + c] = __float2half(acc2[rr]);
            else        g_res[row * 16 + (c - 16)] = acc2[rr];
        }
        float el = acc2[rr] * a2, er = acc2[rr] * r2v;
#pragma unroll
        for (int o = 8; o; o >>= 1) {
            el += __shfl_xor_sync(FULL, el, o);
            er += __shfl_xor_sync(FULL, er, o);
        }
        if (c == 0 && row < n) {
            g_el2[row] = el;
            g_er2[row] = er;
        }
    }
}

// -------- layer-2 agg: two nodes per warp, one pass --------
__global__ void agg2_kernel(const float* __restrict__ b2,
                            float* __restrict__ out,
                            float* __restrict__ out_alpha,
                            int n, int write_alpha) {
    int warp = (blockIdx.x * blockDim.x + threadIdx.x) >> 5;
    int lane = threadIdx.x & 31;
    int half = lane >> 4;
    int l = lane & 15;
    int node = warp * 2 + half;
    if (node >= n) return;
    unsigned mask = 0xFFFFu << (half * 16);
    int beg = g_rowptr[node], end = g_rowptr[node + 1];
    float er = g_er2[node];

    float acc = 0.f, ssum = 0.f;
    for (int base = beg; base < end; base += 16) {
        int k = base + l;
        int sidx = 0;
        float ex = 0.f;
        if (k < end) {
            sidx = g_edge[k].x;
            ex = expf(lrelu(g_el2[sidx] + er));
            ssum += ex;
        }
        int cnt = min(16, end - base);
        if (cnt == 16) {
#pragma unroll 4
            for (int j = 0; j < 16; j++) {
                float x = __shfl_sync(mask, ex, j, 16);
                int  sj = __shfl_sync(mask, sidx, j, 16);
                acc += x * __half2float(g_ft2h[sj * 16 + l]);
            }
        } else {
            for (int j = 0; j < cnt; j++) {
                float x = __shfl_sync(mask, ex, j, 16);
                int  sj = __shfl_sync(mask, sidx, j, 16);
                acc += x * __half2float(g_ft2h[sj * 16 + l]);
            }
        }
    }
#pragma unroll
    for (int o = 8; o; o >>= 1) ssum += __shfl_xor_sync(mask, ssum, o);
    float inv = (ssum > 0.f) ? 1.f / ssum : 0.f;
    out[node * 16 + l] = acc * inv + b2[l] + g_res[node * 16 + l];
    if (write_alpha) {
        for (int k = beg + l; k < end; k += 16) {
            int2 epk = g_edge[k];
            float ex = expf(lrelu(g_el2[epk.x] + er));
            out_alpha[epk.y] = ex * inv;
        }
    }
}

// ---------------- launcher ----------------
extern "C" void kernel_launch(void* const* d_in, const int* in_sizes, int n_in,
                              void* d_out, int out_size) {
    const float* h    = (const float*)d_in[0];
    const int*   src  = (const int*)  d_in[1];
    const int*   dst  = (const int*)  d_in[2];
    const float* W1   = (const float*)d_in[3];
    const float* al1  = (const float*)d_in[4];
    const float* ar1  = (const float*)d_in[5];
    const float* b1   = (const float*)d_in[6];
    const float* W2   = (const float*)d_in[7];
    const float* al2  = (const float*)d_in[8];
    const float* ar2  = (const float*)d_in[9];
    const float* b2   = (const float*)d_in[10];
    const float* Wres = (const float*)d_in[11];
    float* out = (float*)d_out;

    int n = in_sizes[0] / F1;
    int e = in_sizes[1];
    if (n > N_MAX || e > E_MAX) return;

    const int T = 256;
    int write_alpha = (out_size >= n * 16 + e) ? 1 : 0;

    static cudaStream_t s_side = nullptr;
    static cudaEvent_t ev_fork = nullptr, ev_join = nullptr;
    if (s_side == nullptr) {
        cudaStreamCreateWithFlags(&s_side, cudaStreamNonBlocking);
        cudaEventCreateWithFlags(&ev_fork, cudaEventDisableTiming);
        cudaEventCreateWithFlags(&ev_join, cudaEventDisableTiming);
    }

    // fork: gemm1 on side stream (independent of CSR build)
    cudaEventRecord(ev_fork, 0);
    cudaStreamWaitEvent(s_side, ev_fork, 0);
    gemm1_kernel<<<(n + 15) / 16, 128, 0, s_side>>>(h, W1, al1, ar1, n);
    cudaEventRecord(ev_join, s_side);

    // main chain: CSR build
    int nb = (n + SCAN_B - 1) / SCAN_B;
    prep_kernel<<<(max(n, F1 * 32) + T - 1) / T, T>>>(W2, Wres, n);
    deg_kernel<<<(e + 8 * T - 1) / (8 * T), T>>>(dst, e);
    scan_local<<<nb, SCAN_B>>>(n);
    scan_add<<<(n + 1 + T - 1) / T, T>>>(n, e, nb);
    scatter_kernel<<<(e + 8 * T - 1) / (8 * T), T>>>(src, dst, e);

    // join, then dependent chain
    cudaStreamWaitEvent(0, ev_join, 0);
    l2_fused_kernel<<<(n + 15) / 16, 128>>>(b1, al2, ar2, n);
    agg2_kernel<<<((long long)((n + 1) / 2) * 32 + T - 1) / T, T>>>(
        b2, out, out + n * 16, n, write_alpha);
}

// round 9
// speedup vs baseline: 2.0724x; 1.0378x over previous
#include <cuda_runtime.h>
#include <cuda_fp16.h>
#include <math_constants.h>

#define N_MAX 50000
#define E_MAX 800000
#define F1 128
#define SLOPE 0.2f
#define FULL 0xffffffffu
#define SCAN_B 512

// ---------------- scratch ----------------
__device__ __half2 g_ft1h[N_MAX * 64];   // layer-1 features, fp16 pairs
__device__ float2 g_el1[N_MAX];
__device__ float2 g_er1[N_MAX];
__device__ __half g_ft2h[N_MAX * 16];    // layer-2 features (gathered), fp16
__device__ float g_res[N_MAX * 16];      // residual
__device__ float g_el2[N_MAX];
__device__ float g_er2[N_MAX];
__device__ float g_Wc[F1 * 32];          // [W2 | Wres]
__device__ int g_deg[N_MAX];
__device__ int g_rowptr[N_MAX + 1];
__device__ int g_cursor[N_MAX];
__device__ int g_blocksum[128];
__device__ int2 g_edge[E_MAX];           // (src, orig_edge_idx) sorted by dst

__device__ __forceinline__ float lrelu(float x) { return x > 0.f ? x : SLOPE * x; }
__device__ __forceinline__ float eluf(float x)  { return x > 0.f ? x : __expf(x) - 1.f; }

// ---------------- CSR build ----------------
__global__ void prep_kernel(const float* __restrict__ W2,
                            const float* __restrict__ Wres, int n) {
    int i = blockIdx.x * blockDim.x + threadIdx.x;
    if (i < n) g_deg[i] = 0;
    if (i < F1 * 32) {
        int k = i >> 5, c = i & 31;
        g_Wc[i] = (c < 16) ? W2[k * 16 + c] : Wres[k * 16 + (c - 16)];
    }
}

__global__ void deg_kernel(const int* __restrict__ dst, int e) {
    int base = (blockIdx.x * blockDim.x + threadIdx.x) * 8;
    if (base + 8 <= e) {
        int4 a = *(const int4*)(dst + base);
        int4 b = *(const int4*)(dst + base + 4);
        atomicAdd(&g_deg[a.x], 1); atomicAdd(&g_deg[a.y], 1);
        atomicAdd(&g_deg[a.z], 1); atomicAdd(&g_deg[a.w], 1);
        atomicAdd(&g_deg[b.x], 1); atomicAdd(&g_deg[b.y], 1);
        atomicAdd(&g_deg[b.z], 1); atomicAdd(&g_deg[b.w], 1);
    } else {
        for (int k = base; k < e; k++) atomicAdd(&g_deg[dst[k]], 1);
    }
}

__global__ void scan_local(int n) {
    __shared__ int sm[SCAN_B];
    int t = threadIdx.x;
    int i = blockIdx.x * SCAN_B + t;
    int v = (i < n) ? g_deg[i] : 0;
    sm[t] = v;
    __syncthreads();
    for (int off = 1; off < SCAN_B; off <<= 1) {
        int u = (t >= off) ? sm[t - off] : 0;
        __syncthreads();
        sm[t] += u;
        __syncthreads();
    }
    if (i < n) g_rowptr[i] = sm[t] - v;
    if (t == SCAN_B - 1) g_blocksum[blockIdx.x] = sm[t];
}

__global__ void scan_add(int n, int e, int nb) {
    __shared__ int bs[128];
    int t = threadIdx.x;
    if (t < 128) bs[t] = (t < nb) ? g_blocksum[t] : 0;
    __syncthreads();
    for (int off = 1; off < 128; off <<= 1) {
        int u = 0;
        if (t < 128 && t >= off) u = bs[t - off];
        __syncthreads();
        if (t < 128) bs[t] += u;
        __syncthreads();
    }
    int i = blockIdx.x * blockDim.x + t;
    if (i < n) {
        int b = i / SCAN_B;
        int v = g_rowptr[i] + ((b == 0) ? 0 : bs[b - 1]);
        g_rowptr[i] = v;
        g_cursor[i] = v;
    }
    if (i == n) g_rowptr[n] = e;
}

__global__ void scatter_kernel(const int* __restrict__ src,
                               const int* __restrict__ dst, int e) {
    int base = (blockIdx.x * blockDim.x + threadIdx.x) * 8;
    if (base + 8 <= e) {
        int4 d0 = *(const int4*)(dst + base);
        int4 d1 = *(const int4*)(dst + base + 4);
        int4 s0 = *(const int4*)(src + base);
        int4 s1 = *(const int4*)(src + base + 4);
        int p0 = atomicAdd(&g_cursor[d0.x], 1);
        int p1 = atomicAdd(&g_cursor[d0.y], 1);
        int p2 = atomicAdd(&g_cursor[d0.z], 1);
        int p3 = atomicAdd(&g_cursor[d0.w], 1);
        int p4 = atomicAdd(&g_cursor[d1.x], 1);
        int p5 = atomicAdd(&g_cursor[d1.y], 1);
        int p6 = atomicAdd(&g_cursor[d1.z], 1);
        int p7 = atomicAdd(&g_cursor[d1.w], 1);
        g_edge[p0] = make_int2(s0.x, base);
        g_edge[p1] = make_int2(s0.y, base + 1);
        g_edge[p2] = make_int2(s0.z, base + 2);
        g_edge[p3] = make_int2(s0.w, base + 3);
        g_edge[p4] = make_int2(s1.x, base + 4);
        g_edge[p5] = make_int2(s1.y, base + 5);
        g_edge[p6] = make_int2(s1.z, base + 6);
        g_edge[p7] = make_int2(s1.w, base + 7);
    } else {
        for (int k = base; k < e; k++) {
            int pos = atomicAdd(&g_cursor[dst[k]], 1);
            g_edge[pos] = make_int2(src[k], k);
        }
    }
}

// ---------------- GEMM1 + fused el1/er1, fp16 ft1 output ----------------
__global__ void gemm1_kernel(const float* __restrict__ h,
                             const float* __restrict__ W1,
                             const float* __restrict__ al1,
                             const float* __restrict__ ar1, int n) {
    __shared__ float hs[16][F1];
    int t = threadIdx.x;
    int row0 = blockIdx.x * 16;
    for (int i = t; i < 512; i += 128) {
        int r = i >> 5, j4 = i & 31;
        int row = row0 + r;
        float4 v = make_float4(0.f, 0.f, 0.f, 0.f);
        if (row < n) v = *(const float4*)(h + row * F1 + j4 * 4);
        *(float4*)&hs[r][j4 * 4] = v;
    }
    __syncthreads();
    float acc[16];
#pragma unroll
    for (int r = 0; r < 16; r++) acc[r] = 0.f;
    for (int k = 0; k < F1; k += 4) {
        float w0 = __ldg(&W1[k * F1 + t]);
        float w1 = __ldg(&W1[(k + 1) * F1 + t]);
        float w2 = __ldg(&W1[(k + 2) * F1 + t]);
        float w3 = __ldg(&W1[(k + 3) * F1 + t]);
#pragma unroll
        for (int r = 0; r < 16; r++) {
            float4 hv = *(const float4*)&hs[r][k];
            acc[r] += hv.x * w0 + hv.y * w1 + hv.z * w2 + hv.w * w3;
        }
    }
    __syncthreads();
#pragma unroll
    for (int r = 0; r < 16; r++) hs[r][t] = acc[r];
    __syncthreads();
    for (int i = t; i < 16 * 64; i += 128) {
        int r = i >> 6, c2 = i & 63;
        int row = row0 + r;
        if (row < n)
            g_ft1h[row * 64 + c2] = __floats2half2_rn(hs[r][c2 * 2], hs[r][c2 * 2 + 1]);
    }
    int lane = t & 31, w = t >> 5;
    float a0 = al1[lane], a1 = al1[lane + 32], a2 = al1[lane + 64], a3 = al1[lane + 96];
    float r0 = ar1[lane], r1 = ar1[lane + 32], r2 = ar1[lane + 64], r3 = ar1[lane + 96];
#pragma unroll
    for (int rr = 0; rr < 4; rr++) {
        int r = w * 4 + rr;
        int row = row0 + r;
        float f0 = hs[r][lane], f1 = hs[r][lane + 32];
        float f2 = hs[r][lane + 64], f3 = hs[r][lane + 96];
        float el0 = f0 * a0 + f1 * a1, er0 = f0 * r0 + f1 * r1;
        float el1v = f2 * a2 + f3 * a3, er1v = f2 * r2 + f3 * r3;
#pragma unroll
        for (int o = 16; o; o >>= 1) {
            el0  += __shfl_xor_sync(FULL, el0, o);
            er0  += __shfl_xor_sync(FULL, er0, o);
            el1v += __shfl_xor_sync(FULL, el1v, o);
            er1v += __shfl_xor_sync(FULL, er1v, o);
        }
        if (lane == 0 && row < n) {
            g_el1[row] = make_float2(el0, el1v);
            g_er1[row] = make_float2(er0, er1v);
        }
    }
}

// ------ FUSED: layer-1 aggregation (agg1) + GEMM2 + el2/er2 ------
__global__ void l2_fused_kernel(const float* __restrict__ b1,
                                const float* __restrict__ al2,
                                const float* __restrict__ ar2, int n) {
    __shared__ float hs[16][F1];
    int t = threadIdx.x;
    int lane = t & 31, w = t >> 5;
    int row0 = blockIdx.x * 16;

    float4 bv = *(const float4*)(b1 + lane * 4);

    // ---- phase A: aggregate 4 nodes per warp ----
#pragma unroll
    for (int rr = 0; rr < 4; rr++) {
        int r = w * 4 + rr;
        int node = row0 + r;
        if (node >= n) {
            *(float4*)&hs[r][lane * 4] = make_float4(0.f, 0.f, 0.f, 0.f);
            continue;
        }
        int beg = g_rowptr[node], end = g_rowptr[node + 1];
        float2 er = g_er1[node];
        float4 acc = make_float4(0.f, 0.f, 0.f, 0.f);
        float s0 = 0.f, s1 = 0.f;
        for (int base = beg; base < end; base += 32) {
            int k = base + lane;
            int sidx = 0;
            float ex0 = 0.f, ex1 = 0.f;
            if (k < end) {
                sidx = g_edge[k].x;
                float2 el = g_el1[sidx];
                ex0 = __expf(lrelu(el.x + er.x));
                ex1 = __expf(lrelu(el.y + er.y));
                s0 += ex0;
                s1 += ex1;
            }
            int cnt = min(32, end - base);
#pragma unroll 4
            for (int j = 0; j < cnt; j++) {
                float x0 = __shfl_sync(FULL, ex0, j);
                float x1 = __shfl_sync(FULL, ex1, j);
                int   sj = __shfl_sync(FULL, sidx, j);
                float myex = (lane < 16) ? x0 : x1;
                uint2 raw = *(const uint2*)(g_ft1h + sj * 64 + lane * 2);
                float2 f01 = __half22float2(*reinterpret_cast<__half2*>(&raw.x));
                float2 f23 = __half22float2(*reinterpret_cast<__half2*>(&raw.y));
                acc.x += myex * f01.x;
                acc.y += myex * f01.y;
                acc.z += myex * f23.x;
                acc.w += myex * f23.y;
            }
        }
#pragma unroll
        for (int o = 16; o; o >>= 1) {
            s0 += __shfl_xor_sync(FULL, s0, o);
            s1 += __shfl_xor_sync(FULL, s1, o);
        }
        float inv0 = (s0 > 0.f) ? 1.f / s0 : 0.f;
        float inv1 = (s1 > 0.f) ? 1.f / s1 : 0.f;
        float inv = (lane < 16) ? inv0 : inv1;
        float4 o4;
        o4.x = eluf(acc.x * inv + bv.x);
        o4.y = eluf(acc.y * inv + bv.y);
        o4.z = eluf(acc.z * inv + bv.z);
        o4.w = eluf(acc.w * inv + bv.w);
        *(float4*)&hs[r][lane * 4] = o4;
    }
    __syncthreads();

    // ---- phase B: gemm2 ([ft2 | res] = h1 @ [W2 | Wres]) + eler2 ----
    int c = t & 31, g = t >> 5;
    float acc2[4] = {0.f, 0.f, 0.f, 0.f};
    for (int k = 0; k < F1; k += 4) {
        float w0 = g_Wc[k * 32 + c];
        float w1 = g_Wc[(k + 1) * 32 + c];
        float w2 = g_Wc[(k + 2) * 32 + c];
        float w3 = g_Wc[(k + 3) * 32 + c];
#pragma unroll
        for (int rr = 0; rr < 4; rr++) {
            float4 hv = *(const float4*)&hs[g * 4 + rr][k];
            acc2[rr] += hv.x * w0 + hv.y * w1 + hv.z * w2 + hv.w * w3;
        }
    }
    float a2 = (c < 16) ? al2[c] : 0.f;
    float r2v = (c < 16) ? ar2[c] : 0.f;
#pragma unroll
    for (int rr = 0; rr < 4; rr++) {
        int row = row0 + g * 4 + rr;
        if (row < n) {
            if (c < 16) g_ft2h[row * 16 + c] = __float2half(acc2[rr]);
            else        g_res[row * 16 + (c - 16)] = acc2[rr];
        }
        float el = acc2[rr] * a2, er = acc2[rr] * r2v;
#pragma unroll
        for (int o = 8; o; o >>= 1) {
            el += __shfl_xor_sync(FULL, el, o);
            er += __shfl_xor_sync(FULL, er, o);
        }
        if (c == 0 && row < n) {
            g_el2[row] = el;
            g_er2[row] = er;
        }
    }
}

// -------- layer-2 agg: two nodes per warp, one pass, ex cached ------
__global__ void agg2_kernel(const float* __restrict__ b2,
                            float* __restrict__ out,
                            float* __restrict__ out_alpha,
                            int n, int write_alpha) {
    int warp = (blockIdx.x * blockDim.x + threadIdx.x) >> 5;
    int lane = threadIdx.x & 31;
    int half = lane >> 4;
    int l = lane & 15;
    int node = warp * 2 + half;
    if (node >= n) return;
    unsigned mask = 0xFFFFu << (half * 16);
    int beg = g_rowptr[node], end = g_rowptr[node + 1];
    float er = g_er2[node];

    float acc = 0.f, ssum = 0.f;
    float exc0 = 0.f, exc1 = 0.f;   // cached ex for chunks 0,1 (deg<=32)
    int c = 0;
    for (int base = beg; base < end; base += 16, c++) {
        int k = base + l;
        int sidx = 0;
        float ex = 0.f;
        if (k < end) {
            sidx = g_edge[k].x;
            ex = __expf(lrelu(g_el2[sidx] + er));
            ssum += ex;
        }
        if (c == 0) exc0 = ex; else if (c == 1) exc1 = ex;
        int cnt = min(16, end - base);
#pragma unroll 4
        for (int j = 0; j < cnt; j++) {
            float x = __shfl_sync(mask, ex, j, 16);
            int  sj = __shfl_sync(mask, sidx, j, 16);
            acc += x * __half2float(g_ft2h[sj * 16 + l]);
        }
    }
#pragma unroll
    for (int o = 8; o; o >>= 1) ssum += __shfl_xor_sync(mask, ssum, o);
    float inv = (ssum > 0.f) ? 1.f / ssum : 0.f;
    out[node * 16 + l] = acc * inv + b2[l] + g_res[node * 16 + l];
    if (write_alpha) {
        c = 0;
        for (int base = beg; base < end; base += 16, c++) {
            int k = base + l;
            if (k < end) {
                float ex;
                if (c == 0)      ex = exc0;
                else if (c == 1) ex = exc1;
                else             ex = __expf(lrelu(g_el2[g_edge[k].x] + er));
                out_alpha[g_edge[k].y] = ex * inv;
            }
        }
    }
}

// ---------------- launcher ----------------
extern "C" void kernel_launch(void* const* d_in, const int* in_sizes, int n_in,
                              void* d_out, int out_size) {
    const float* h    = (const float*)d_in[0];
    const int*   src  = (const int*)  d_in[1];
    const int*   dst  = (const int*)  d_in[2];
    const float* W1   = (const float*)d_in[3];
    const float* al1  = (const float*)d_in[4];
    const float* ar1  = (const float*)d_in[5];
    const float* b1   = (const float*)d_in[6];
    const float* W2   = (const float*)d_in[7];
    const float* al2  = (const float*)d_in[8];
    const float* ar2  = (const float*)d_in[9];
    const float* b2   = (const float*)d_in[10];
    const float* Wres = (const float*)d_in[11];
    float* out = (float*)d_out;

    int n = in_sizes[0] / F1;
    int e = in_sizes[1];
    if (n > N_MAX || e > E_MAX) return;

    const int T = 256;
    int write_alpha = (out_size >= n * 16 + e) ? 1 : 0;

    static cudaStream_t s_side = nullptr;
    static cudaEvent_t ev_fork = nullptr, ev_join = nullptr;
    if (s_side == nullptr) {
        cudaStreamCreateWithFlags(&s_side, cudaStreamNonBlocking);
        cudaEventCreateWithFlags(&ev_fork, cudaEventDisableTiming);
        cudaEventCreateWithFlags(&ev_join, cudaEventDisableTiming);
    }

    // fork: gemm1 on side stream (independent of CSR build)
    cudaEventRecord(ev_fork, 0);
    cudaStreamWaitEvent(s_side, ev_fork, 0);
    gemm1_kernel<<<(n + 15) / 16, 128, 0, s_side>>>(h, W1, al1, ar1, n);
    cudaEventRecord(ev_join, s_side);

    // main chain: CSR build
    int nb = (n + SCAN_B - 1) / SCAN_B;
    prep_kernel<<<(max(n, F1 * 32) + T - 1) / T, T>>>(W2, Wres, n);
    deg_kernel<<<(e + 8 * T - 1) / (8 * T), T>>>(dst, e);
    scan_local<<<nb, SCAN_B>>>(n);
    scan_add<<<(n + 1 + T - 1) / T, T>>>(n, e, nb);
    scatter_kernel<<<(e + 8 * T - 1) / (8 * T), T>>>(src, dst, e);

    // join, then dependent chain
    cudaStreamWaitEvent(0, ev_join, 0);
    l2_fused_kernel<<<(n + 15) / 16, 128>>>(b1, al2, ar2, n);
    agg2_kernel<<<((long long)((n + 1) / 2) * 32 + T - 1) / T, T>>>(
        b2, out, out + n * 16, n, write_alpha);
}

// round 10
// speedup vs baseline: 2.1155x; 1.0208x over previous
#include <cuda_runtime.h>
#include <cuda_fp16.h>
#include <math_constants.h>
#include <mma.h>

using namespace nvcuda;

#define N_MAX 50000
#define E_MAX 800000
#define F1 128
#define SLOPE 0.2f
#define FULL 0xffffffffu
#define SCAN_B 512

// ---------------- scratch ----------------
__device__ __half2 g_ft1h[N_MAX * 64];   // layer-1 features, fp16 pairs
__device__ float2 g_el1[N_MAX];
__device__ float2 g_er1[N_MAX];
__device__ __half g_ft2h[N_MAX * 16];    // layer-2 features (gathered), fp16
__device__ float g_res[N_MAX * 16];      // residual
__device__ float g_el2[N_MAX];
__device__ float g_er2[N_MAX];
__device__ float g_Wc[F1 * 32];          // [W2 | Wres]
__device__ __half g_W1h[F1 * F1];        // W1 in fp16 (k-major [k][n])
__device__ int g_deg[N_MAX];             // zero-initialized at load; re-zeroed by scan_add
__device__ int g_rowptr[N_MAX + 1];
__device__ int g_cursor[N_MAX];
__device__ int g_blocksum[128];
__device__ int2 g_edge[E_MAX];           // (src, orig_edge_idx) sorted by dst

__device__ __forceinline__ float lrelu(float x) { return x > 0.f ? x : SLOPE * x; }
__device__ __forceinline__ float eluf(float x)  { return x > 0.f ? x : __expf(x) - 1.f; }

// ---------------- side-stream pack: Wc + W1->fp16 ----------------
__global__ void pack_kernel(const float* __restrict__ W1,
                            const float* __restrict__ W2,
                            const float* __restrict__ Wres) {
    int i = blockIdx.x * blockDim.x + threadIdx.x;
    if (i < F1 * F1) g_W1h[i] = __float2half(W1[i]);
    if (i < F1 * 32) {
        int k = i >> 5, c = i & 31;
        g_Wc[i] = (c < 16) ? W2[k * 16 + c] : Wres[k * 16 + (c - 16)];
    }
}

// ---------------- CSR build ----------------
__global__ void deg_kernel(const int* __restrict__ dst, int e) {
    int base = (blockIdx.x * blockDim.x + threadIdx.x) * 8;
    if (base + 8 <= e) {
        int4 a = *(const int4*)(dst + base);
        int4 b = *(const int4*)(dst + base + 4);
        atomicAdd(&g_deg[a.x], 1); atomicAdd(&g_deg[a.y], 1);
        atomicAdd(&g_deg[a.z], 1); atomicAdd(&g_deg[a.w], 1);
        atomicAdd(&g_deg[b.x], 1); atomicAdd(&g_deg[b.y], 1);
        atomicAdd(&g_deg[b.z], 1); atomicAdd(&g_deg[b.w], 1);
    } else {
        for (int k = base; k < e; k++) atomicAdd(&g_deg[dst[k]], 1);
    }
}

__global__ void scan_local(int n) {
    __shared__ int sm[SCAN_B];
    int t = threadIdx.x;
    int i = blockIdx.x * SCAN_B + t;
    int v = (i < n) ? g_deg[i] : 0;
    sm[t] = v;
    __syncthreads();
    for (int off = 1; off < SCAN_B; off <<= 1) {
        int u = (t >= off) ? sm[t - off] : 0;
        __syncthreads();
        sm[t] += u;
        __syncthreads();
    }
    if (i < n) g_rowptr[i] = sm[t] - v;
    if (t == SCAN_B - 1) g_blocksum[blockIdx.x] = sm[t];
}

// top-level scan inlined; also re-zeroes g_deg for the next replay
__global__ void scan_add(int n, int e, int nb) {
    __shared__ int bs[128];
    int t = threadIdx.x;
    if (t < 128) bs[t] = (t < nb) ? g_blocksum[t] : 0;
    __syncthreads();
    for (int off = 1; off < 128; off <<= 1) {
        int u = 0;
        if (t < 128 && t >= off) u = bs[t - off];
        __syncthreads();
        if (t < 128) bs[t] += u;
        __syncthreads();
    }
    int i = blockIdx.x * blockDim.x + t;
    if (i < n) {
        int b = i / SCAN_B;
        int v = g_rowptr[i] + ((b == 0) ? 0 : bs[b - 1]);
        g_rowptr[i] = v;
        g_cursor[i] = v;
        g_deg[i] = 0;          // ready for next graph replay
    }
    if (i == n) g_rowptr[n] = e;
}

__global__ void scatter_kernel(const int* __restrict__ src,
                               const int* __restrict__ dst, int e) {
    int base = (blockIdx.x * blockDim.x + threadIdx.x) * 8;
    if (base + 8 <= e) {
        int4 d0 = *(const int4*)(dst + base);
        int4 d1 = *(const int4*)(dst + base + 4);
        int4 s0 = *(const int4*)(src + base);
        int4 s1 = *(const int4*)(src + base + 4);
        int p0 = atomicAdd(&g_cursor[d0.x], 1);
        int p1 = atomicAdd(&g_cursor[d0.y], 1);
        int p2 = atomicAdd(&g_cursor[d0.z], 1);
        int p3 = atomicAdd(&g_cursor[d0.w], 1);
        int p4 = atomicAdd(&g_cursor[d1.x], 1);
        int p5 = atomicAdd(&g_cursor[d1.y], 1);
        int p6 = atomicAdd(&g_cursor[d1.z], 1);
        int p7 = atomicAdd(&g_cursor[d1.w], 1);
        g_edge[p0] = make_int2(s0.x, base);
        g_edge[p1] = make_int2(s0.y, base + 1);
        g_edge[p2] = make_int2(s0.z, base + 2);
        g_edge[p3] = make_int2(s0.w, base + 3);
        g_edge[p4] = make_int2(s1.x, base + 4);
        g_edge[p5] = make_int2(s1.y, base + 5);
        g_edge[p6] = make_int2(s1.z, base + 6);
        g_edge[p7] = make_int2(s1.w, base + 7);
    } else {
        for (int k = base; k < e; k++) {
            int pos = atomicAdd(&g_cursor[dst[k]], 1);
            g_edge[pos] = make_int2(src[k], k);
        }
    }
}

// ---------------- GEMM1 via WMMA fp16 + fused el1/er1 ----------------
// Block: 256 threads (8 warps), 32 output rows. Warp w handles rows
// (w>>2)*16, cols (w&3)*32 as two 16x16 tiles.
__global__ void gemm1_wmma(const float* __restrict__ h,
                           const float* __restrict__ al1,
                           const float* __restrict__ ar1, int n) {
    __shared__ __half a_sm[32][F1];
    __shared__ float c_sm[32][F1];
    int t = threadIdx.x;
    int warp = t >> 5, lane = t & 31;
    int row0 = blockIdx.x * 32;

    // load h rows -> fp16 smem (32 x 128; 1024 float4 groups)
    for (int i = t; i < 1024; i += 256) {
        int r = i >> 5, j4 = i & 31;
        int row = row0 + r;
        float4 v = make_float4(0.f, 0.f, 0.f, 0.f);
        if (row < n) v = *(const float4*)(h + row * F1 + j4 * 4);
        *(__half2*)&a_sm[r][j4 * 4]     = __floats2half2_rn(v.x, v.y);
        *(__half2*)&a_sm[r][j4 * 4 + 2] = __floats2half2_rn(v.z, v.w);
    }
    __syncthreads();

    wmma::fragment<wmma::accumulator, 16, 16, 16, float> c0, c1;
    wmma::fill_fragment(c0, 0.f);
    wmma::fill_fragment(c1, 0.f);
    int trow = (warp >> 2) * 16;
    int tcol = (warp & 3) * 32;
#pragma unroll
    for (int k = 0; k < F1; k += 16) {
        wmma::fragment<wmma::matrix_a, 16, 16, 16, __half, wmma::row_major> a;
        wmma::load_matrix_sync(a, &a_sm[trow][k], F1);
        wmma::fragment<wmma::matrix_b, 16, 16, 16, __half, wmma::row_major> b;
        wmma::load_matrix_sync(b, &g_W1h[k * F1 + tcol], F1);
        wmma::mma_sync(c0, a, b, c0);
        wmma::load_matrix_sync(b, &g_W1h[k * F1 + tcol + 16], F1);
        wmma::mma_sync(c1, a, b, c1);
    }
    wmma::store_matrix_sync(&c_sm[trow][tcol], c0, F1, wmma::mem_row_major);
    wmma::store_matrix_sync(&c_sm[trow][tcol + 16], c1, F1, wmma::mem_row_major);
    __syncthreads();

    // fp16 feature store: 32 rows x 64 half2
    for (int i = t; i < 32 * 64; i += 256) {
        int r = i >> 6, c2 = i & 63;
        int row = row0 + r;
        if (row < n)
            g_ft1h[row * 64 + c2] = __floats2half2_rn(c_sm[r][c2 * 2], c_sm[r][c2 * 2 + 1]);
    }
    // fused eler1: 8 warps x 4 rows
    float a0 = al1[lane], a1 = al1[lane + 32], a2 = al1[lane + 64], a3 = al1[lane + 96];
    float r0 = ar1[lane], r1 = ar1[lane + 32], r2 = ar1[lane + 64], r3 = ar1[lane + 96];
#pragma unroll
    for (int rr = 0; rr < 4; rr++) {
        int r = warp * 4 + rr;
        int row = row0 + r;
        float f0 = c_sm[r][lane], f1 = c_sm[r][lane + 32];
        float f2 = c_sm[r][lane + 64], f3 = c_sm[r][lane + 96];
        float el0 = f0 * a0 + f1 * a1, er0 = f0 * r0 + f1 * r1;
        float el1v = f2 * a2 + f3 * a3, er1v = f2 * r2 + f3 * r3;
#pragma unroll
        for (int o = 16; o; o >>= 1) {
            el0  += __shfl_xor_sync(FULL, el0, o);
            er0  += __shfl_xor_sync(FULL, er0, o);
            el1v += __shfl_xor_sync(FULL, el1v, o);
            er1v += __shfl_xor_sync(FULL, er1v, o);
        }
        if (lane == 0 && row < n) {
            g_el1[row] = make_float2(el0, el1v);
            g_er1[row] = make_float2(er0, er1v);
        }
    }
}

// ------ FUSED: layer-1 aggregation (agg1) + GEMM2 + el2/er2 ------
__global__ void l2_fused_kernel(const float* __restrict__ b1,
                                const float* __restrict__ al2,
                                const float* __restrict__ ar2, int n) {
    __shared__ float hs[16][F1];
    int t = threadIdx.x;
    int lane = t & 31, w = t >> 5;
    int row0 = blockIdx.x * 16;

    float4 bv = *(const float4*)(b1 + lane * 4);

    // ---- phase A: aggregate 4 nodes per warp ----
#pragma unroll
    for (int rr = 0; rr < 4; rr++) {
        int r = w * 4 + rr;
        int node = row0 + r;
        if (node >= n) {
            *(float4*)&hs[r][lane * 4] = make_float4(0.f, 0.f, 0.f, 0.f);
            continue;
        }
        int beg = g_rowptr[node], end = g_rowptr[node + 1];
        float2 er = g_er1[node];
        float4 acc = make_float4(0.f, 0.f, 0.f, 0.f);
        float s0 = 0.f, s1 = 0.f;
        for (int base = beg; base < end; base += 32) {
            int k = base + lane;
            int sidx = 0;
            float ex0 = 0.f, ex1 = 0.f;
            if (k < end) {
                sidx = g_edge[k].x;
                float2 el = g_el1[sidx];
                ex0 = __expf(lrelu(el.x + er.x));
                ex1 = __expf(lrelu(el.y + er.y));
                s0 += ex0;
                s1 += ex1;
            }
            int cnt = min(32, end - base);
#pragma unroll 4
            for (int j = 0; j < cnt; j++) {
                float x0 = __shfl_sync(FULL, ex0, j);
                float x1 = __shfl_sync(FULL, ex1, j);
                int   sj = __shfl_sync(FULL, sidx, j);
                float myex = (lane < 16) ? x0 : x1;
                uint2 raw = *(const uint2*)(g_ft1h + sj * 64 + lane * 2);
                float2 f01 = __half22float2(*reinterpret_cast<__half2*>(&raw.x));
                float2 f23 = __half22float2(*reinterpret_cast<__half2*>(&raw.y));
                acc.x += myex * f01.x;
                acc.y += myex * f01.y;
                acc.z += myex * f23.x;
                acc.w += myex * f23.y;
            }
        }
#pragma unroll
        for (int o = 16; o; o >>= 1) {
            s0 += __shfl_xor_sync(FULL, s0, o);
            s1 += __shfl_xor_sync(FULL, s1, o);
        }
        float inv0 = (s0 > 0.f) ? 1.f / s0 : 0.f;
        float inv1 = (s1 > 0.f) ? 1.f / s1 : 0.f;
        float inv = (lane < 16) ? inv0 : inv1;
        float4 o4;
        o4.x = eluf(acc.x * inv + bv.x);
        o4.y = eluf(acc.y * inv + bv.y);
        o4.z = eluf(acc.z * inv + bv.z);
        o4.w = eluf(acc.w * inv + bv.w);
        *(float4*)&hs[r][lane * 4] = o4;
    }
    __syncthreads();

    // ---- phase B: gemm2 ([ft2 | res] = h1 @ [W2 | Wres]) + eler2 ----
    int c = t & 31, g = t >> 5;
    float acc2[4] = {0.f, 0.f, 0.f, 0.f};
    for (int k = 0; k < F1; k += 4) {
        float w0 = g_Wc[k * 32 + c];
        float w1 = g_Wc[(k + 1) * 32 + c];
        float w2 = g_Wc[(k + 2) * 32 + c];
        float w3 = g_Wc[(k + 3) * 32 + c];
#pragma unroll
        for (int rr = 0; rr < 4; rr++) {
            float4 hv = *(const float4*)&hs[g * 4 + rr][k];
            acc2[rr] += hv.x * w0 + hv.y * w1 + hv.z * w2 + hv.w * w3;
        }
    }
    float a2 = (c < 16) ? al2[c] : 0.f;
    float r2v = (c < 16) ? ar2[c] : 0.f;
#pragma unroll
    for (int rr = 0; rr < 4; rr++) {
        int row = row0 + g * 4 + rr;
        if (row < n) {
            if (c < 16) g_ft2h[row * 16 + c] = __float2half(acc2[rr]);
            else        g_res[row * 16 + (c - 16)] = acc2[rr];
        }
        float el = acc2[rr] * a2, er = acc2[rr] * r2v;
#pragma unroll
        for (int o = 8; o; o >>= 1) {
            el += __shfl_xor_sync(FULL, el, o);
            er += __shfl_xor_sync(FULL, er, o);
        }
        if (c == 0 && row < n) {
            g_el2[row] = el;
            g_er2[row] = er;
        }
    }
}

// -------- layer-2 agg: two nodes per warp, one pass, ex cached ------
__global__ void agg2_kernel(const float* __restrict__ b2,
                            float* __restrict__ out,
                            float* __restrict__ out_alpha,
                            int n, int write_alpha) {
    int warp = (blockIdx.x * blockDim.x + threadIdx.x) >> 5;
    int lane = threadIdx.x & 31;
    int half = lane >> 4;
    int l = lane & 15;
    int node = warp * 2 + half;
    if (node >= n) return;
    unsigned mask = 0xFFFFu << (half * 16);
    int beg = g_rowptr[node], end = g_rowptr[node + 1];
    float er = g_er2[node];

    float acc = 0.f, ssum = 0.f;
    float exc0 = 0.f, exc1 = 0.f;
    int c = 0;
    for (int base = beg; base < end; base += 16, c++) {
        int k = base + l;
        int sidx = 0;
        float ex = 0.f;
        if (k < end) {
            sidx = g_edge[k].x;
            ex = __expf(lrelu(g_el2[sidx] + er));
            ssum += ex;
        }
        if (c == 0) exc0 = ex; else if (c == 1) exc1 = ex;
        int cnt = min(16, end - base);
#pragma unroll 4
        for (int j = 0; j < cnt; j++) {
            float x = __shfl_sync(mask, ex, j, 16);
            int  sj = __shfl_sync(mask, sidx, j, 16);
            acc += x * __half2float(g_ft2h[sj * 16 + l]);
        }
    }
#pragma unroll
    for (int o = 8; o; o >>= 1) ssum += __shfl_xor_sync(mask, ssum, o);
    float inv = (ssum > 0.f) ? 1.f / ssum : 0.f;
    out[node * 16 + l] = acc * inv + b2[l] + g_res[node * 16 + l];
    if (write_alpha) {
        c = 0;
        for (int base = beg; base < end; base += 16, c++) {
            int k = base + l;
            if (k < end) {
                float ex;
                if (c == 0)      ex = exc0;
                else if (c == 1) ex = exc1;
                else             ex = __expf(lrelu(g_el2[g_edge[k].x] + er));
                out_alpha[g_edge[k].y] = ex * inv;
            }
        }
    }
}

// ---------------- launcher ----------------
extern "C" void kernel_launch(void* const* d_in, const int* in_sizes, int n_in,
                              void* d_out, int out_size) {
    const float* h    = (const float*)d_in[0];
    const int*   src  = (const int*)  d_in[1];
    const int*   dst  = (const int*)  d_in[2];
    const float* W1   = (const float*)d_in[3];
    const float* al1  = (const float*)d_in[4];
    const float* ar1  = (const float*)d_in[5];
    const float* b1   = (const float*)d_in[6];
    const float* W2   = (const float*)d_in[7];
    const float* al2  = (const float*)d_in[8];
    const float* ar2  = (const float*)d_in[9];
    const float* b2   = (const float*)d_in[10];
    const float* Wres = (const float*)d_in[11];
    float* out = (float*)d_out;

    int n = in_sizes[0] / F1;
    int e = in_sizes[1];
    if (n > N_MAX || e > E_MAX) return;

    const int T = 256;
    int write_alpha = (out_size >= n * 16 + e) ? 1 : 0;

    static cudaStream_t s_side = nullptr;
    static cudaEvent_t ev_fork = nullptr, ev_join = nullptr;
    if (s_side == nullptr) {
        cudaStreamCreateWithFlags(&s_side, cudaStreamNonBlocking);
        cudaEventCreateWithFlags(&ev_fork, cudaEventDisableTiming);
        cudaEventCreateWithFlags(&ev_join, cudaEventDisableTiming);
    }

    // fork: pack + gemm1 on side stream (independent of CSR build)
    cudaEventRecord(ev_fork, 0);
    cudaStreamWaitEvent(s_side, ev_fork, 0);
    pack_kernel<<<(F1 * F1 + T - 1) / T, T, 0, s_side>>>(W1, W2, Wres);
    gemm1_wmma<<<(n + 31) / 32, 256, 0, s_side>>>(h, al1, ar1, n);
    cudaEventRecord(ev_join, s_side);

    // main chain: CSR build
    int nb = (n + SCAN_B - 1) / SCAN_B;
    deg_kernel<<<(e + 8 * T - 1) / (8 * T), T>>>(dst, e);
    scan_local<<<nb, SCAN_B>>>(n);
    scan_add<<<(n + 1 + T - 1) / T, T>>>(n, e, nb);
    scatter_kernel<<<(e + 8 * T - 1) / (8 * T), T>>>(src, dst, e);

    // join, then dependent chain
    cudaStreamWaitEvent(0, ev_join, 0);
    l2_fused_kernel<<<(n + 15) / 16, 128>>>(b1, al2, ar2, n);
    agg2_kernel<<<((long long)((n + 1) / 2) * 32 + T - 1) / T, T>>>(
        b2, out, out + n * 16, n, write_alpha);
}

// round 11
// speedup vs baseline: 2.1162x; 1.0004x over previous
#include <cuda_runtime.h>
#include <cuda_fp16.h>
#include <math_constants.h>
#include <mma.h>

using namespace nvcuda;

#define N_MAX 50000
#define E_MAX 800000
#define F1 128
#define SLOPE 0.2f
#define FULL 0xffffffffu
#define SCAN_B 512

// ---------------- scratch ----------------
__device__ __half2 g_ft1h[N_MAX * 64];   // layer-1 features, fp16 pairs
__device__ float2 g_el1[N_MAX];
__device__ float2 g_er1[N_MAX];
__device__ __half g_ft2h[N_MAX * 16];    // layer-2 features (gathered), fp16
__device__ float g_res[N_MAX * 16];      // residual
__device__ float g_el2[N_MAX];
__device__ float g_er2[N_MAX];
__device__ float g_Wc[F1 * 32];          // [W2 | Wres]
__device__ __half g_W1h[F1 * F1];        // W1 in fp16 (k-major [k][n])
__device__ int g_deg[N_MAX];             // zeroed at load; re-zeroed by scan_add
__device__ int g_rowptr[N_MAX + 1];
__device__ int g_cursor[N_MAX];
__device__ int g_blocksum[128];
__device__ int2 g_edge[E_MAX];           // (src, orig_edge_idx) sorted by dst

__device__ __forceinline__ float lrelu(float x) { return x > 0.f ? x : SLOPE * x; }
__device__ __forceinline__ float eluf(float x)  { return x > 0.f ? x : __expf(x) - 1.f; }

// ---------------- side-stream pack: Wc + W1->fp16 ----------------
__global__ void pack_kernel(const float* __restrict__ W1,
                            const float* __restrict__ W2,
                            const float* __restrict__ Wres) {
    int i = blockIdx.x * blockDim.x + threadIdx.x;
    if (i < F1 * F1) g_W1h[i] = __float2half(W1[i]);
    if (i < F1 * 32) {
        int k = i >> 5, c = i & 31;
        g_Wc[i] = (c < 16) ? W2[k * 16 + c] : Wres[k * 16 + (c - 16)];
    }
}

// ---------------- CSR build ----------------
// 4 edges/thread: one int4 load, 4 independent atomic chains, 782 blocks
__global__ void deg_kernel(const int* __restrict__ dst, int e) {
    int base = (blockIdx.x * blockDim.x + threadIdx.x) * 4;
    if (base + 4 <= e) {
        int4 a = *(const int4*)(dst + base);
        atomicAdd(&g_deg[a.x], 1); atomicAdd(&g_deg[a.y], 1);
        atomicAdd(&g_deg[a.z], 1); atomicAdd(&g_deg[a.w], 1);
    } else {
        for (int k = base; k < e; k++) atomicAdd(&g_deg[dst[k]], 1);
    }
}

__global__ void scan_local(int n) {
    __shared__ int sm[SCAN_B];
    int t = threadIdx.x;
    int i = blockIdx.x * SCAN_B + t;
    int v = (i < n) ? g_deg[i] : 0;
    sm[t] = v;
    __syncthreads();
    for (int off = 1; off < SCAN_B; off <<= 1) {
        int u = (t >= off) ? sm[t - off] : 0;
        __syncthreads();
        sm[t] += u;
        __syncthreads();
    }
    if (i < n) g_rowptr[i] = sm[t] - v;
    if (t == SCAN_B - 1) g_blocksum[blockIdx.x] = sm[t];
}

// top-level scan inlined; also re-zeroes g_deg for the next replay
__global__ void scan_add(int n, int e, int nb) {
    __shared__ int bs[128];
    int t = threadIdx.x;
    if (t < 128) bs[t] = (t < nb) ? g_blocksum[t] : 0;
    __syncthreads();
    for (int off = 1; off < 128; off <<= 1) {
        int u = 0;
        if (t < 128 && t >= off) u = bs[t - off];
        __syncthreads();
        if (t < 128) bs[t] += u;
        __syncthreads();
    }
    int i = blockIdx.x * blockDim.x + t;
    if (i < n) {
        int b = i / SCAN_B;
        int v = g_rowptr[i] + ((b == 0) ? 0 : bs[b - 1]);
        g_rowptr[i] = v;
        g_cursor[i] = v;
        g_deg[i] = 0;
    }
    if (i == n) g_rowptr[n] = e;
}

// 2 edges/thread: 1563 blocks -> enough resident warps to hide atomic latency
__global__ void scatter_kernel(const int* __restrict__ src,
                               const int* __restrict__ dst, int e) {
    int base = (blockIdx.x * blockDim.x + threadIdx.x) * 2;
    if (base + 2 <= e) {
        int2 d = *(const int2*)(dst + base);
        int2 s = *(const int2*)(src + base);
        int p0 = atomicAdd(&g_cursor[d.x], 1);
        int p1 = atomicAdd(&g_cursor[d.y], 1);
        g_edge[p0] = make_int2(s.x, base);
        g_edge[p1] = make_int2(s.y, base + 1);
    } else {
        for (int k = base; k < e; k++) {
            int pos = atomicAdd(&g_cursor[dst[k]], 1);
            g_edge[pos] = make_int2(src[k], k);
        }
    }
}

// ---------------- GEMM1 via WMMA fp16 + fused el1/er1 ----------------
__global__ void gemm1_wmma(const float* __restrict__ h,
                           const float* __restrict__ al1,
                           const float* __restrict__ ar1, int n) {
    __shared__ __half a_sm[32][F1];
    __shared__ float c_sm[32][F1];
    int t = threadIdx.x;
    int warp = t >> 5, lane = t & 31;
    int row0 = blockIdx.x * 32;

    for (int i = t; i < 1024; i += 256) {
        int r = i >> 5, j4 = i & 31;
        int row = row0 + r;
        float4 v = make_float4(0.f, 0.f, 0.f, 0.f);
        if (row < n) v = *(const float4*)(h + row * F1 + j4 * 4);
        *(__half2*)&a_sm[r][j4 * 4]     = __floats2half2_rn(v.x, v.y);
        *(__half2*)&a_sm[r][j4 * 4 + 2] = __floats2half2_rn(v.z, v.w);
    }
    __syncthreads();

    wmma::fragment<wmma::accumulator, 16, 16, 16, float> c0, c1;
    wmma::fill_fragment(c0, 0.f);
    wmma::fill_fragment(c1, 0.f);
    int trow = (warp >> 2) * 16;
    int tcol = (warp & 3) * 32;
#pragma unroll
    for (int k = 0; k < F1; k += 16) {
        wmma::fragment<wmma::matrix_a, 16, 16, 16, __half, wmma::row_major> a;
        wmma::load_matrix_sync(a, &a_sm[trow][k], F1);
        wmma::fragment<wmma::matrix_b, 16, 16, 16, __half, wmma::row_major> b;
        wmma::load_matrix_sync(b, &g_W1h[k * F1 + tcol], F1);
        wmma::mma_sync(c0, a, b, c0);
        wmma::load_matrix_sync(b, &g_W1h[k * F1 + tcol + 16], F1);
        wmma::mma_sync(c1, a, b, c1);
    }
    wmma::store_matrix_sync(&c_sm[trow][tcol], c0, F1, wmma::mem_row_major);
    wmma::store_matrix_sync(&c_sm[trow][tcol + 16], c1, F1, wmma::mem_row_major);
    __syncthreads();

    for (int i = t; i < 32 * 64; i += 256) {
        int r = i >> 6, c2 = i & 63;
        int row = row0 + r;
        if (row < n)
            g_ft1h[row * 64 + c2] = __floats2half2_rn(c_sm[r][c2 * 2], c_sm[r][c2 * 2 + 1]);
    }
    float a0 = al1[lane], a1 = al1[lane + 32], a2 = al1[lane + 64], a3 = al1[lane + 96];
    float r0 = ar1[lane], r1 = ar1[lane + 32], r2 = ar1[lane + 64], r3 = ar1[lane + 96];
#pragma unroll
    for (int rr = 0; rr < 4; rr++) {
        int r = warp * 4 + rr;
        int row = row0 + r;
        float f0 = c_sm[r][lane], f1 = c_sm[r][lane + 32];
        float f2 = c_sm[r][lane + 64], f3 = c_sm[r][lane + 96];
        float el0 = f0 * a0 + f1 * a1, er0 = f0 * r0 + f1 * r1;
        float el1v = f2 * a2 + f3 * a3, er1v = f2 * r2 + f3 * r3;
#pragma unroll
        for (int o = 16; o; o >>= 1) {
            el0  += __shfl_xor_sync(FULL, el0, o);
            er0  += __shfl_xor_sync(FULL, er0, o);
            el1v += __shfl_xor_sync(FULL, el1v, o);
            er1v += __shfl_xor_sync(FULL, er1v, o);
        }
        if (lane == 0 && row < n) {
            g_el1[row] = make_float2(el0, el1v);
            g_er1[row] = make_float2(er0, er1v);
        }
    }
}

// ------ FUSED: layer-1 aggregation (agg1) + GEMM2 + el2/er2 ------
__global__ void l2_fused_kernel(const float* __restrict__ b1,
                                const float* __restrict__ al2,
                                const float* __restrict__ ar2, int n) {
    __shared__ float hs[16][F1];
    int t = threadIdx.x;
    int lane = t & 31, w = t >> 5;
    int row0 = blockIdx.x * 16;

    float4 bv = *(const float4*)(b1 + lane * 4);

    // ---- phase A: aggregate 4 nodes per warp ----
#pragma unroll
    for (int rr = 0; rr < 4; rr++) {
        int r = w * 4 + rr;
        int node = row0 + r;
        if (node >= n) {
            *(float4*)&hs[r][lane * 4] = make_float4(0.f, 0.f, 0.f, 0.f);
            continue;
        }
        int beg = g_rowptr[node], end = g_rowptr[node + 1];
        float2 er = g_er1[node];
        float4 acc = make_float4(0.f, 0.f, 0.f, 0.f);
        float s0 = 0.f, s1 = 0.f;
        for (int base = beg; base < end; base += 32) {
            int k = base + lane;
            int sidx = 0;
            float ex0 = 0.f, ex1 = 0.f;
            if (k < end) {
                sidx = g_edge[k].x;
                float2 el = g_el1[sidx];
                ex0 = __expf(lrelu(el.x + er.x));
                ex1 = __expf(lrelu(el.y + er.y));
                s0 += ex0;
                s1 += ex1;
            }
            int cnt = min(32, end - base);
#pragma unroll 8
            for (int j = 0; j < cnt; j++) {
                float x0 = __shfl_sync(FULL, ex0, j);
                float x1 = __shfl_sync(FULL, ex1, j);
                int   sj = __shfl_sync(FULL, sidx, j);
                float myex = (lane < 16) ? x0 : x1;
                uint2 raw = *(const uint2*)(g_ft1h + sj * 64 + lane * 2);
                float2 f01 = __half22float2(*reinterpret_cast<__half2*>(&raw.x));
                float2 f23 = __half22float2(*reinterpret_cast<__half2*>(&raw.y));
                acc.x += myex * f01.x;
                acc.y += myex * f01.y;
                acc.z += myex * f23.x;
                acc.w += myex * f23.y;
            }
        }
#pragma unroll
        for (int o = 16; o; o >>= 1) {
            s0 += __shfl_xor_sync(FULL, s0, o);
            s1 += __shfl_xor_sync(FULL, s1, o);
        }
        float inv0 = (s0 > 0.f) ? 1.f / s0 : 0.f;
        float inv1 = (s1 > 0.f) ? 1.f / s1 : 0.f;
        float inv = (lane < 16) ? inv0 : inv1;
        float4 o4;
        o4.x = eluf(acc.x * inv + bv.x);
        o4.y = eluf(acc.y * inv + bv.y);
        o4.z = eluf(acc.z * inv + bv.z);
        o4.w = eluf(acc.w * inv + bv.w);
        *(float4*)&hs[r][lane * 4] = o4;
    }
    __syncthreads();

    // ---- phase B: gemm2 ([ft2 | res] = h1 @ [W2 | Wres]) + eler2 ----
    int c = t & 31, g = t >> 5;
    float acc2[4] = {0.f, 0.f, 0.f, 0.f};
    for (int k = 0; k < F1; k += 4) {
        float w0 = g_Wc[k * 32 + c];
        float w1 = g_Wc[(k + 1) * 32 + c];
        float w2 = g_Wc[(k + 2) * 32 + c];
        float w3 = g_Wc[(k + 3) * 32 + c];
#pragma unroll
        for (int rr = 0; rr < 4; rr++) {
            float4 hv = *(const float4*)&hs[g * 4 + rr][k];
            acc2[rr] += hv.x * w0 + hv.y * w1 + hv.z * w2 + hv.w * w3;
        }
    }
    float a2 = (c < 16) ? al2[c] : 0.f;
    float r2v = (c < 16) ? ar2[c] : 0.f;
#pragma unroll
    for (int rr = 0; rr < 4; rr++) {
        int row = row0 + g * 4 + rr;
        if (row < n) {
            if (c < 16) g_ft2h[row * 16 + c] = __float2half(acc2[rr]);
            else        g_res[row * 16 + (c - 16)] = acc2[rr];
        }
        float el = acc2[rr] * a2, er = acc2[rr] * r2v;
#pragma unroll
        for (int o = 8; o; o >>= 1) {
            el += __shfl_xor_sync(FULL, el, o);
            er += __shfl_xor_sync(FULL, er, o);
        }
        if (c == 0 && row < n) {
            g_el2[row] = el;
            g_er2[row] = er;
        }
    }
}

// -------- layer-2 agg: two nodes per warp, one pass, ex cached ------
__global__ void agg2_kernel(const float* __restrict__ b2,
                            float* __restrict__ out,
                            float* __restrict__ out_alpha,
                            int n, int write_alpha) {
    int warp = (blockIdx.x * blockDim.x + threadIdx.x) >> 5;
    int lane = threadIdx.x & 31;
    int half = lane >> 4;
    int l = lane & 15;
    int node = warp * 2 + half;
    if (node >= n) return;
    unsigned mask = 0xFFFFu << (half * 16);
    int beg = g_rowptr[node], end = g_rowptr[node + 1];
    float er = g_er2[node];

    float acc = 0.f, ssum = 0.f;
    float exc0 = 0.f, exc1 = 0.f;
    int c = 0;
    for (int base = beg; base < end; base += 16, c++) {
        int k = base + l;
        int sidx = 0;
        float ex = 0.f;
        if (k < end) {
            sidx = g_edge[k].x;
            ex = __expf(lrelu(g_el2[sidx] + er));
            ssum += ex;
        }
        if (c == 0) exc0 = ex; else if (c == 1) exc1 = ex;
        int cnt = min(16, end - base);
#pragma unroll 8
        for (int j = 0; j < cnt; j++) {
            float x = __shfl_sync(mask, ex, j, 16);
            int  sj = __shfl_sync(mask, sidx, j, 16);
            acc += x * __half2float(g_ft2h[sj * 16 + l]);
        }
    }
#pragma unroll
    for (int o = 8; o; o >>= 1) ssum += __shfl_xor_sync(mask, ssum, o);
    float inv = (ssum > 0.f) ? 1.f / ssum : 0.f;
    out[node * 16 + l] = acc * inv + b2[l] + g_res[node * 16 + l];
    if (write_alpha) {
        c = 0;
        for (int base = beg; base < end; base += 16, c++) {
            int k = base + l;
            if (k < end) {
                float ex;
                if (c == 0)      ex = exc0;
                else if (c == 1) ex = exc1;
                else             ex = __expf(lrelu(g_el2[g_edge[k].x] + er));
                out_alpha[g_edge[k].y] = ex * inv;
            }
        }
    }
}

// ---------------- launcher ----------------
extern "C" void kernel_launch(void* const* d_in, const int* in_sizes, int n_in,
                              void* d_out, int out_size) {
    const float* h    = (const float*)d_in[0];
    const int*   src  = (const int*)  d_in[1];
    const int*   dst  = (const int*)  d_in[2];
    const float* W1   = (const float*)d_in[3];
    const float* al1  = (const float*)d_in[4];
    const float* ar1  = (const float*)d_in[5];
    const float* b1   = (const float*)d_in[6];
    const float* W2   = (const float*)d_in[7];
    const float* al2  = (const float*)d_in[8];
    const float* ar2  = (const float*)d_in[9];
    const float* b2   = (const float*)d_in[10];
    const float* Wres = (const float*)d_in[11];
    float* out = (float*)d_out;

    int n = in_sizes[0] / F1;
    int e = in_sizes[1];
    if (n > N_MAX || e > E_MAX) return;

    const int T = 256;
    int write_alpha = (out_size >= n * 16 + e) ? 1 : 0;

    static cudaStream_t s_side = nullptr;
    static cudaEvent_t ev_fork = nullptr, ev_join = nullptr;
    if (s_side == nullptr) {
        cudaStreamCreateWithFlags(&s_side, cudaStreamNonBlocking);
        cudaEventCreateWithFlags(&ev_fork, cudaEventDisableTiming);
        cudaEventCreateWithFlags(&ev_join, cudaEventDisableTiming);
    }

    // fork: pack + gemm1 on side stream (independent of CSR build)
    cudaEventRecord(ev_fork, 0);
    cudaStreamWaitEvent(s_side, ev_fork, 0);
    pack_kernel<<<(F1 * F1 + T - 1) / T, T, 0, s_side>>>(W1, W2, Wres);
    gemm1_wmma<<<(n + 31) / 32, 256, 0, s_side>>>(h, al1, ar1, n);
    cudaEventRecord(ev_join, s_side);

    // main chain: CSR build
    int nb = (n + SCAN_B - 1) / SCAN_B;
    deg_kernel<<<(e + 4 * T - 1) / (4 * T), T>>>(dst, e);
    scan_local<<<nb, SCAN_B>>>(n);
    scan_add<<<(n + 1 + T - 1) / T, T>>>(n, e, nb);
    scatter_kernel<<<(e + 2 * T - 1) / (2 * T), T>>>(src, dst, e);

    // join, then dependent chain
    cudaStreamWaitEvent(0, ev_join, 0);
    l2_fused_kernel<<<(n + 15) / 16, 128>>>(b1, al2, ar2, n);
    agg2_kernel<<<((long long)((n + 1) / 2) * 32 + T - 1) / T, T>>>(
        b2, out, out + n * 16, n, write_alpha);
}

// round 12
// speedup vs baseline: 2.3797x; 1.1245x over previous
#include <cuda_runtime.h>
#include <cuda_fp16.h>
#include <math_constants.h>
#include <mma.h>

using namespace nvcuda;

#define N_MAX 50000
#define E_MAX 800000
#define F1 128
#define SLOPE 0.2f
#define FULL 0xffffffffu
#define SCAN_B 512

// ---------------- scratch ----------------
__device__ __half2 g_ft1h[N_MAX * 64];   // layer-1 features, fp16 pairs
__device__ float2 g_el1[N_MAX];
__device__ float2 g_er1[N_MAX];
__device__ __half g_ft2h[N_MAX * 16];    // layer-2 features (gathered), fp16
__device__ float g_res[N_MAX * 16];      // residual
__device__ float g_el2[N_MAX];
__device__ float g_er2[N_MAX];
__device__ float g_Wc[F1 * 32];          // [W2 | Wres]
__device__ __half g_W1h[F1 * F1];        // W1 in fp16 (k-major [k][n])
__device__ int g_deg[N_MAX];             // zeroed at load; re-zeroed by scan_add
__device__ int g_rowptr[N_MAX + 1];
__device__ int g_cursor[N_MAX];
__device__ int g_blocksum[128];
__device__ int2 g_edge[E_MAX];           // (src, orig_edge_idx) sorted by dst

__device__ __forceinline__ float lrelu(float x) { return x > 0.f ? x : SLOPE * x; }
__device__ __forceinline__ float eluf(float x)  { return x > 0.f ? x : __expf(x) - 1.f; }

// ---------------- side-stream pack: Wc + W1->fp16 ----------------
__global__ void pack_kernel(const float* __restrict__ W1,
                            const float* __restrict__ W2,
                            const float* __restrict__ Wres) {
    int i = blockIdx.x * blockDim.x + threadIdx.x;
    if (i < F1 * F1) g_W1h[i] = __float2half(W1[i]);
    if (i < F1 * 32) {
        int k = i >> 5, c = i & 31;
        g_Wc[i] = (c < 16) ? W2[k * 16 + c] : Wres[k * 16 + (c - 16)];
    }
}

// ---------------- CSR build ----------------
__global__ void deg_kernel(const int* __restrict__ dst, int e) {
    int base = (blockIdx.x * blockDim.x + threadIdx.x) * 4;
    if (base + 4 <= e) {
        int4 a = *(const int4*)(dst + base);
        atomicAdd(&g_deg[a.x], 1); atomicAdd(&g_deg[a.y], 1);
        atomicAdd(&g_deg[a.z], 1); atomicAdd(&g_deg[a.w], 1);
    } else {
        for (int k = base; k < e; k++) atomicAdd(&g_deg[dst[k]], 1);
    }
}

__global__ void scan_local(int n) {
    __shared__ int sm[SCAN_B];
    int t = threadIdx.x;
    int i = blockIdx.x * SCAN_B + t;
    int v = (i < n) ? g_deg[i] : 0;
    sm[t] = v;
    __syncthreads();
    for (int off = 1; off < SCAN_B; off <<= 1) {
        int u = (t >= off) ? sm[t - off] : 0;
        __syncthreads();
        sm[t] += u;
        __syncthreads();
    }
    if (i < n) g_rowptr[i] = sm[t] - v;
    if (t == SCAN_B - 1) g_blocksum[blockIdx.x] = sm[t];
}

__global__ void scan_add(int n, int e, int nb) {
    __shared__ int bs[128];
    int t = threadIdx.x;
    if (t < 128) bs[t] = (t < nb) ? g_blocksum[t] : 0;
    __syncthreads();
    for (int off = 1; off < 128; off <<= 1) {
        int u = 0;
        if (t < 128 && t >= off) u = bs[t - off];
        __syncthreads();
        if (t < 128) bs[t] += u;
        __syncthreads();
    }
    int i = blockIdx.x * blockDim.x + t;
    if (i < n) {
        int b = i / SCAN_B;
        int v = g_rowptr[i] + ((b == 0) ? 0 : bs[b - 1]);
        g_rowptr[i] = v;
        g_cursor[i] = v;
        g_deg[i] = 0;
    }
    if (i == n) g_rowptr[n] = e;
}

__global__ void scatter_kernel(const int* __restrict__ src,
                               const int* __restrict__ dst, int e) {
    int base = (blockIdx.x * blockDim.x + threadIdx.x) * 2;
    if (base + 2 <= e) {
        int2 d = *(const int2*)(dst + base);
        int2 s = *(const int2*)(src + base);
        int p0 = atomicAdd(&g_cursor[d.x], 1);
        int p1 = atomicAdd(&g_cursor[d.y], 1);
        g_edge[p0] = make_int2(s.x, base);
        g_edge[p1] = make_int2(s.y, base + 1);
    } else {
        for (int k = base; k < e; k++) {
            int pos = atomicAdd(&g_cursor[dst[k]], 1);
            g_edge[pos] = make_int2(src[k], k);
        }
    }
}

// ---------------- GEMM1 via WMMA fp16 + fused el1/er1 ----------------
__global__ void gemm1_wmma(const float* __restrict__ h,
                           const float* __restrict__ al1,
                           const float* __restrict__ ar1, int n) {
    __shared__ __half a_sm[32][F1];
    __shared__ float c_sm[32][F1];
    int t = threadIdx.x;
    int warp = t >> 5, lane = t & 31;
    int row0 = blockIdx.x * 32;

    for (int i = t; i < 1024; i += 256) {
        int r = i >> 5, j4 = i & 31;
        int row = row0 + r;
        float4 v = make_float4(0.f, 0.f, 0.f, 0.f);
        if (row < n) v = *(const float4*)(h + row * F1 + j4 * 4);
        *(__half2*)&a_sm[r][j4 * 4]     = __floats2half2_rn(v.x, v.y);
        *(__half2*)&a_sm[r][j4 * 4 + 2] = __floats2half2_rn(v.z, v.w);
    }
    __syncthreads();

    wmma::fragment<wmma::accumulator, 16, 16, 16, float> c0, c1;
    wmma::fill_fragment(c0, 0.f);
    wmma::fill_fragment(c1, 0.f);
    int trow = (warp >> 2) * 16;
    int tcol = (warp & 3) * 32;
#pragma unroll
    for (int k = 0; k < F1; k += 16) {
        wmma::fragment<wmma::matrix_a, 16, 16, 16, __half, wmma::row_major> a;
        wmma::load_matrix_sync(a, &a_sm[trow][k], F1);
        wmma::fragment<wmma::matrix_b, 16, 16, 16, __half, wmma::row_major> b;
        wmma::load_matrix_sync(b, &g_W1h[k * F1 + tcol], F1);
        wmma::mma_sync(c0, a, b, c0);
        wmma::load_matrix_sync(b, &g_W1h[k * F1 + tcol + 16], F1);
        wmma::mma_sync(c1, a, b, c1);
    }
    wmma::store_matrix_sync(&c_sm[trow][tcol], c0, F1, wmma::mem_row_major);
    wmma::store_matrix_sync(&c_sm[trow][tcol + 16], c1, F1, wmma::mem_row_major);
    __syncthreads();

    for (int i = t; i < 32 * 64; i += 256) {
        int r = i >> 6, c2 = i & 63;
        int row = row0 + r;
        if (row < n)
            g_ft1h[row * 64 + c2] = __floats2half2_rn(c_sm[r][c2 * 2], c_sm[r][c2 * 2 + 1]);
    }
    float a0 = al1[lane], a1 = al1[lane + 32], a2 = al1[lane + 64], a3 = al1[lane + 96];
    float r0 = ar1[lane], r1 = ar1[lane + 32], r2 = ar1[lane + 64], r3 = ar1[lane + 96];
#pragma unroll
    for (int rr = 0; rr < 4; rr++) {
        int r = warp * 4 + rr;
        int row = row0 + r;
        float f0 = c_sm[r][lane], f1 = c_sm[r][lane + 32];
        float f2 = c_sm[r][lane + 64], f3 = c_sm[r][lane + 96];
        float el0 = f0 * a0 + f1 * a1, er0 = f0 * r0 + f1 * r1;
        float el1v = f2 * a2 + f3 * a3, er1v = f2 * r2 + f3 * r3;
#pragma unroll
        for (int o = 16; o; o >>= 1) {
            el0  += __shfl_xor_sync(FULL, el0, o);
            er0  += __shfl_xor_sync(FULL, er0, o);
            el1v += __shfl_xor_sync(FULL, el1v, o);
            er1v += __shfl_xor_sync(FULL, er1v, o);
        }
        if (lane == 0 && row < n) {
            g_el1[row] = make_float2(el0, el1v);
            g_er1[row] = make_float2(er0, er1v);
        }
    }
}

// ------ FUSED: layer-1 aggregation + GEMM2 + el2/er2 (2 shfls/edge) ------
__global__ void l2_fused_kernel(const float* __restrict__ b1,
                                const float* __restrict__ al2,
                                const float* __restrict__ ar2, int n) {
    __shared__ float hs[16][F1];
    int t = threadIdx.x;
    int lane = t & 31, w = t >> 5;
    int row0 = blockIdx.x * 16;

    float4 bv = *(const float4*)(b1 + lane * 4);

    // ---- phase A: aggregate 4 nodes per warp ----
#pragma unroll
    for (int rr = 0; rr < 4; rr++) {
        int r = w * 4 + rr;
        int node = row0 + r;
        if (node >= n) {
            *(float4*)&hs[r][lane * 4] = make_float4(0.f, 0.f, 0.f, 0.f);
            continue;
        }
        int beg = g_rowptr[node], end = g_rowptr[node + 1];
        float2 er = g_er1[node];
        float4 acc = make_float4(0.f, 0.f, 0.f, 0.f);
        float s0 = 0.f, s1 = 0.f;
        for (int base = beg; base < end; base += 32) {
            int k = base + lane;
            int sidx = 0;
            unsigned exh = 0;
            if (k < end) {
                sidx = g_edge[k].x;
                float2 el = g_el1[sidx];
                float ex0 = __expf(lrelu(el.x + er.x));
                float ex1 = __expf(lrelu(el.y + er.y));
                s0 += ex0;
                s1 += ex1;
                __half2 p = __floats2half2_rn(ex0, ex1);
                exh = *reinterpret_cast<unsigned*>(&p);
            }
            int cnt = min(32, end - base);
#pragma unroll 8
            for (int j = 0; j < cnt; j++) {
                unsigned xh = __shfl_sync(FULL, exh, j);
                int      sj = __shfl_sync(FULL, sidx, j);
                __half2 hx = *reinterpret_cast<__half2*>(&xh);
                float myex = (lane < 16) ? __low2float(hx) : __high2float(hx);
                uint2 raw = *(const uint2*)(g_ft1h + sj * 64 + lane * 2);
                float2 f01 = __half22float2(*reinterpret_cast<__half2*>(&raw.x));
                float2 f23 = __half22float2(*reinterpret_cast<__half2*>(&raw.y));
                acc.x += myex * f01.x;
                acc.y += myex * f01.y;
                acc.z += myex * f23.x;
                acc.w += myex * f23.y;
            }
        }
#pragma unroll
        for (int o = 16; o; o >>= 1) {
            s0 += __shfl_xor_sync(FULL, s0, o);
            s1 += __shfl_xor_sync(FULL, s1, o);
        }
        float inv0 = (s0 > 0.f) ? 1.f / s0 : 0.f;
        float inv1 = (s1 > 0.f) ? 1.f / s1 : 0.f;
        float inv = (lane < 16) ? inv0 : inv1;
        float4 o4;
        o4.x = eluf(acc.x * inv + bv.x);
        o4.y = eluf(acc.y * inv + bv.y);
        o4.z = eluf(acc.z * inv + bv.z);
        o4.w = eluf(acc.w * inv + bv.w);
        *(float4*)&hs[r][lane * 4] = o4;
    }
    __syncthreads();

    // ---- phase B: gemm2 ([ft2 | res] = h1 @ [W2 | Wres]) + eler2 ----
    int c = t & 31, g = t >> 5;
    float acc2[4] = {0.f, 0.f, 0.f, 0.f};
    for (int k = 0; k < F1; k += 4) {
        float w0 = g_Wc[k * 32 + c];
        float w1 = g_Wc[(k + 1) * 32 + c];
        float w2 = g_Wc[(k + 2) * 32 + c];
        float w3 = g_Wc[(k + 3) * 32 + c];
#pragma unroll
        for (int rr = 0; rr < 4; rr++) {
            float4 hv = *(const float4*)&hs[g * 4 + rr][k];
            acc2[rr] += hv.x * w0 + hv.y * w1 + hv.z * w2 + hv.w * w3;
        }
    }
    float a2 = (c < 16) ? al2[c] : 0.f;
    float r2v = (c < 16) ? ar2[c] : 0.f;
#pragma unroll
    for (int rr = 0; rr < 4; rr++) {
        int row = row0 + g * 4 + rr;
        if (row < n) {
            if (c < 16) g_ft2h[row * 16 + c] = __float2half(acc2[rr]);
            else        g_res[row * 16 + (c - 16)] = acc2[rr];
        }
        float el = acc2[rr] * a2, er = acc2[rr] * r2v;
#pragma unroll
        for (int o = 8; o; o >>= 1) {
            el += __shfl_xor_sync(FULL, el, o);
            er += __shfl_xor_sync(FULL, er, o);
        }
        if (c == 0 && row < n) {
            g_el2[row] = el;
            g_er2[row] = er;
        }
    }
}

// -------- layer-2 agg: two nodes per warp, ONE shfl per edge ------
// Pack: low 16 bits = sidx (requires n < 65536), high 16 = ex as fp16.
__global__ void agg2_kernel(const float* __restrict__ b2,
                            float* __restrict__ out,
                            float* __restrict__ out_alpha,
                            int n, int write_alpha) {
    int warp = (blockIdx.x * blockDim.x + threadIdx.x) >> 5;
    int lane = threadIdx.x & 31;
    int half = lane >> 4;
    int l = lane & 15;
    int node = warp * 2 + half;
    if (node >= n) return;
    unsigned mask = 0xFFFFu << (half * 16);
    int beg = g_rowptr[node], end = g_rowptr[node + 1];
    float er = g_er2[node];

    float acc = 0.f, ssum = 0.f;
    float exc0 = 0.f, exc1 = 0.f;
    int c = 0;
    for (int base = beg; base < end; base += 16, c++) {
        int k = base + l;
        unsigned pk = 0;
        float ex = 0.f;
        if (k < end) {
            int sidx = g_edge[k].x;
            ex = __expf(lrelu(g_el2[sidx] + er));
            ssum += ex;
            pk = (unsigned)sidx |
                 ((unsigned)__half_as_ushort(__float2half_rn(ex)) << 16);
        }
        if (c == 0) exc0 = ex; else if (c == 1) exc1 = ex;
        int cnt = min(16, end - base);
#pragma unroll 8
        for (int j = 0; j < cnt; j++) {
            unsigned p = __shfl_sync(mask, pk, j, 16);
            int sj = (int)(p & 0xFFFFu);
            float x = __half2float(__ushort_as_half((unsigned short)(p >> 16)));
            acc += x * __half2float(g_ft2h[sj * 16 + l]);
        }
    }
#pragma unroll
    for (int o = 8; o; o >>= 1) ssum += __shfl_xor_sync(mask, ssum, o);
    float inv = (ssum > 0.f) ? 1.f / ssum : 0.f;
    out[node * 16 + l] = acc * inv + b2[l] + g_res[node * 16 + l];
    if (write_alpha) {
        c = 0;
        for (int base = beg; base < end; base += 16, c++) {
            int k = base + l;
            if (k < end) {
                float ex;
                if (c == 0)      ex = exc0;
                else if (c == 1) ex = exc1;
                else             ex = __expf(lrelu(g_el2[g_edge[k].x] + er));
                out_alpha[g_edge[k].y] = ex * inv;
            }
        }
    }
}

// ---------------- launcher ----------------
extern "C" void kernel_launch(void* const* d_in, const int* in_sizes, int n_in,
                              void* d_out, int out_size) {
    const float* h    = (const float*)d_in[0];
    const int*   src  = (const int*)  d_in[1];
    const int*   dst  = (const int*)  d_in[2];
    const float* W1   = (const float*)d_in[3];
    const float* al1  = (const float*)d_in[4];
    const float* ar1  = (const float*)d_in[5];
    const float* b1   = (const float*)d_in[6];
    const float* W2   = (const float*)d_in[7];
    const float* al2  = (const float*)d_in[8];
    const float* ar2  = (const float*)d_in[9];
    const float* b2   = (const float*)d_in[10];
    const float* Wres = (const float*)d_in[11];
    float* out = (float*)d_out;

    int n = in_sizes[0] / F1;
    int e = in_sizes[1];
    if (n > N_MAX || e > E_MAX) return;

    const int T = 256;
    int write_alpha = (out_size >= n * 16 + e) ? 1 : 0;

    static cudaStream_t s_side = nullptr;
    static cudaEvent_t ev_fork = nullptr, ev_join = nullptr;
    if (s_side == nullptr) {
        cudaStreamCreateWithFlags(&s_side, cudaStreamNonBlocking);
        cudaEventCreateWithFlags(&ev_fork, cudaEventDisableTiming);
        cudaEventCreateWithFlags(&ev_join, cudaEventDisableTiming);
    }

    // fork: pack + gemm1 on side stream (independent of CSR build)
    cudaEventRecord(ev_fork, 0);
    cudaStreamWaitEvent(s_side, ev_fork, 0);
    pack_kernel<<<(F1 * F1 + T - 1) / T, T, 0, s_side>>>(W1, W2, Wres);
    gemm1_wmma<<<(n + 31) / 32, 256, 0, s_side>>>(h, al1, ar1, n);
    cudaEventRecord(ev_join, s_side);

    // main chain: CSR build
    int nb = (n + SCAN_B - 1) / SCAN_B;
    deg_kernel<<<(e + 4 * T - 1) / (4 * T), T>>>(dst, e);
    scan_local<<<nb, SCAN_B>>>(n);
    scan_add<<<(n + 1 + T - 1) / T, T>>>(n, e, nb);
    scatter_kernel<<<(e + 2 * T - 1) / (2 * T), T>>>(src, dst, e);

    // join, then dependent chain
    cudaStreamWaitEvent(0, ev_join, 0);
    l2_fused_kernel<<<(n + 15) / 16, 128>>>(b1, al2, ar2, n);
    agg2_kernel<<<((long long)((n + 1) / 2) * 32 + T - 1) / T, T>>>(
        b2, out, out + n * 16, n, write_alpha);
}

// round 13
// speedup vs baseline: 2.3912x; 1.0048x over previous
#include <cuda_runtime.h>
#include <cuda_fp16.h>
#include <math_constants.h>
#include <mma.h>

using namespace nvcuda;

#define N_MAX 50000
#define E_MAX 800000
#define F1 128
#define SLOPE 0.2f
#define FULL 0xffffffffu
#define SCAN_B 512

// ---------------- scratch ----------------
__device__ __half2 g_ft1h[N_MAX * 64];   // layer-1 features, fp16 pairs
__device__ float2 g_el1[N_MAX];
__device__ float2 g_er1[N_MAX];
__device__ __half g_ft2h[N_MAX * 16];    // layer-2 features (gathered), fp16
__device__ float g_res[N_MAX * 16];      // residual
__device__ float g_el2[N_MAX];
__device__ float g_er2[N_MAX];
__device__ float g_Wc[F1 * 32];          // [W2 | Wres]
__device__ __half g_W1h[F1 * F1];        // W1 in fp16 (k-major [k][n])
__device__ int g_deg[N_MAX];             // zeroed at load; re-zeroed by scan_add
__device__ int g_rowptr[N_MAX + 1];
__device__ int g_cursor[N_MAX];
__device__ int g_blocksum[128];
__device__ int2 g_edge[E_MAX];           // (src, orig_edge_idx) sorted by dst

__device__ __forceinline__ float lrelu(float x) { return x > 0.f ? x : SLOPE * x; }
__device__ __forceinline__ float eluf(float x)  { return x > 0.f ? x : __expf(x) - 1.f; }

// ---------------- side-stream pack: Wc + W1->fp16 ----------------
__global__ void pack_kernel(const float* __restrict__ W1,
                            const float* __restrict__ W2,
                            const float* __restrict__ Wres) {
    int i = blockIdx.x * blockDim.x + threadIdx.x;
    if (i < F1 * F1) g_W1h[i] = __float2half(W1[i]);
    if (i < F1 * 32) {
        int k = i >> 5, c = i & 31;
        g_Wc[i] = (c < 16) ? W2[k * 16 + c] : Wres[k * 16 + (c - 16)];
    }
}

// ---------------- CSR build ----------------
__global__ void deg_kernel(const int* __restrict__ dst, int e) {
    int base = (blockIdx.x * blockDim.x + threadIdx.x) * 4;
    if (base + 4 <= e) {
        int4 a = *(const int4*)(dst + base);
        atomicAdd(&g_deg[a.x], 1); atomicAdd(&g_deg[a.y], 1);
        atomicAdd(&g_deg[a.z], 1); atomicAdd(&g_deg[a.w], 1);
    } else {
        for (int k = base; k < e; k++) atomicAdd(&g_deg[dst[k]], 1);
    }
}

__global__ void scan_local(int n) {
    __shared__ int sm[SCAN_B];
    int t = threadIdx.x;
    int i = blockIdx.x * SCAN_B + t;
    int v = (i < n) ? g_deg[i] : 0;
    sm[t] = v;
    __syncthreads();
    for (int off = 1; off < SCAN_B; off <<= 1) {
        int u = (t >= off) ? sm[t - off] : 0;
        __syncthreads();
        sm[t] += u;
        __syncthreads();
    }
    if (i < n) g_rowptr[i] = sm[t] - v;
    if (t == SCAN_B - 1) g_blocksum[blockIdx.x] = sm[t];
}

__global__ void scan_add(int n, int e, int nb) {
    __shared__ int bs[128];
    int t = threadIdx.x;
    if (t < 128) bs[t] = (t < nb) ? g_blocksum[t] : 0;
    __syncthreads();
    for (int off = 1; off < 128; off <<= 1) {
        int u = 0;
        if (t < 128 && t >= off) u = bs[t - off];
        __syncthreads();
        if (t < 128) bs[t] += u;
        __syncthreads();
    }
    int i = blockIdx.x * blockDim.x + t;
    if (i < n) {
        int b = i / SCAN_B;
        int v = g_rowptr[i] + ((b == 0) ? 0 : bs[b - 1]);
        g_rowptr[i] = v;
        g_cursor[i] = v;
        g_deg[i] = 0;
    }
    if (i == n) g_rowptr[n] = e;
}

__global__ void scatter_kernel(const int* __restrict__ src,
                               const int* __restrict__ dst, int e) {
    int base = (blockIdx.x * blockDim.x + threadIdx.x) * 2;
    if (base + 2 <= e) {
        int2 d = *(const int2*)(dst + base);
        int2 s = *(const int2*)(src + base);
        int p0 = atomicAdd(&g_cursor[d.x], 1);
        int p1 = atomicAdd(&g_cursor[d.y], 1);
        g_edge[p0] = make_int2(s.x, base);
        g_edge[p1] = make_int2(s.y, base + 1);
    } else {
        for (int k = base; k < e; k++) {
            int pos = atomicAdd(&g_cursor[dst[k]], 1);
            g_edge[pos] = make_int2(src[k], k);
        }
    }
}

// ---------------- GEMM1 via WMMA fp16 + fused el1/er1 ----------------
__global__ void gemm1_wmma(const float* __restrict__ h,
                           const float* __restrict__ al1,
                           const float* __restrict__ ar1, int n) {
    __shared__ __half a_sm[32][F1];
    __shared__ float c_sm[32][F1];
    int t = threadIdx.x;
    int warp = t >> 5, lane = t & 31;
    int row0 = blockIdx.x * 32;

    for (int i = t; i < 1024; i += 256) {
        int r = i >> 5, j4 = i & 31;
        int row = row0 + r;
        float4 v = make_float4(0.f, 0.f, 0.f, 0.f);
        if (row < n) v = *(const float4*)(h + row * F1 + j4 * 4);
        *(__half2*)&a_sm[r][j4 * 4]     = __floats2half2_rn(v.x, v.y);
        *(__half2*)&a_sm[r][j4 * 4 + 2] = __floats2half2_rn(v.z, v.w);
    }
    __syncthreads();

    wmma::fragment<wmma::accumulator, 16, 16, 16, float> c0, c1;
    wmma::fill_fragment(c0, 0.f);
    wmma::fill_fragment(c1, 0.f);
    int trow = (warp >> 2) * 16;
    int tcol = (warp & 3) * 32;
#pragma unroll
    for (int k = 0; k < F1; k += 16) {
        wmma::fragment<wmma::matrix_a, 16, 16, 16, __half, wmma::row_major> a;
        wmma::load_matrix_sync(a, &a_sm[trow][k], F1);
        wmma::fragment<wmma::matrix_b, 16, 16, 16, __half, wmma::row_major> b;
        wmma::load_matrix_sync(b, &g_W1h[k * F1 + tcol], F1);
        wmma::mma_sync(c0, a, b, c0);
        wmma::load_matrix_sync(b, &g_W1h[k * F1 + tcol + 16], F1);
        wmma::mma_sync(c1, a, b, c1);
    }
    wmma::store_matrix_sync(&c_sm[trow][tcol], c0, F1, wmma::mem_row_major);
    wmma::store_matrix_sync(&c_sm[trow][tcol + 16], c1, F1, wmma::mem_row_major);
    __syncthreads();

    for (int i = t; i < 32 * 64; i += 256) {
        int r = i >> 6, c2 = i & 63;
        int row = row0 + r;
        if (row < n)
            g_ft1h[row * 64 + c2] = __floats2half2_rn(c_sm[r][c2 * 2], c_sm[r][c2 * 2 + 1]);
    }
    float a0 = al1[lane], a1 = al1[lane + 32], a2 = al1[lane + 64], a3 = al1[lane + 96];
    float r0 = ar1[lane], r1 = ar1[lane + 32], r2 = ar1[lane + 64], r3 = ar1[lane + 96];
#pragma unroll
    for (int rr = 0; rr < 4; rr++) {
        int r = warp * 4 + rr;
        int row = row0 + r;
        float f0 = c_sm[r][lane], f1 = c_sm[r][lane + 32];
        float f2 = c_sm[r][lane + 64], f3 = c_sm[r][lane + 96];
        float el0 = f0 * a0 + f1 * a1, er0 = f0 * r0 + f1 * r1;
        float el1v = f2 * a2 + f3 * a3, er1v = f2 * r2 + f3 * r3;
#pragma unroll
        for (int o = 16; o; o >>= 1) {
            el0  += __shfl_xor_sync(FULL, el0, o);
            er0  += __shfl_xor_sync(FULL, er0, o);
            el1v += __shfl_xor_sync(FULL, el1v, o);
            er1v += __shfl_xor_sync(FULL, er1v, o);
        }
        if (lane == 0 && row < n) {
            g_el1[row] = make_float2(el0, el1v);
            g_er1[row] = make_float2(er0, er1v);
        }
    }
}

// ------ FUSED: layer-1 aggregation + GEMM2 + el2/er2 (ONE shfl/edge) ------
// Half-warp-per-head: lanes l and l+16 process the SAME edge (k = base + l&15),
// each computing only its head's ex. One width-16 shfl delivers
// (sidx16 | ex_fp16<<16) per half -- head 0's ex to lanes 0-15, head 1's to 16-31.
__global__ void l2_fused_kernel(const float* __restrict__ b1,
                                const float* __restrict__ al2,
                                const float* __restrict__ ar2, int n) {
    __shared__ float hs[16][F1];
    int t = threadIdx.x;
    int lane = t & 31, w = t >> 5;
    int halfid = lane >> 4, l16 = lane & 15;
    int row0 = blockIdx.x * 16;

    float4 bv = *(const float4*)(b1 + lane * 4);

    // ---- phase A: aggregate 4 nodes per warp ----
#pragma unroll
    for (int rr = 0; rr < 4; rr++) {
        int r = w * 4 + rr;
        int node = row0 + r;
        if (node >= n) {
            *(float4*)&hs[r][lane * 4] = make_float4(0.f, 0.f, 0.f, 0.f);
            continue;
        }
        int beg = g_rowptr[node], end = g_rowptr[node + 1];
        float2 er = g_er1[node];
        float erh = halfid ? er.y : er.x;
        float4 acc = make_float4(0.f, 0.f, 0.f, 0.f);
        float ssum = 0.f;   // half 0 accumulates s0, half 1 s1
        for (int base = beg; base < end; base += 16) {
            int k = base + l16;
            unsigned pk = 0;
            if (k < end) {
                int sidx = g_edge[k].x;
                float2 el = g_el1[sidx];
                float elh = halfid ? el.y : el.x;
                float ex = __expf(lrelu(elh + erh));
                ssum += ex;
                pk = (unsigned)sidx |
                     ((unsigned)__half_as_ushort(__float2half_rn(ex)) << 16);
            }
            int cnt = min(16, end - base);
#pragma unroll 8
            for (int j = 0; j < cnt; j++) {
                unsigned p = __shfl_sync(FULL, pk, j, 16);
                int sj = (int)(p & 0xFFFFu);
                float x = __half2float(__ushort_as_half((unsigned short)(p >> 16)));
                uint2 raw = *(const uint2*)(g_ft1h + sj * 64 + lane * 2);
                float2 f01 = __half22float2(*reinterpret_cast<__half2*>(&raw.x));
                float2 f23 = __half22float2(*reinterpret_cast<__half2*>(&raw.y));
                acc.x += x * f01.x;
                acc.y += x * f01.y;
                acc.z += x * f23.x;
                acc.w += x * f23.y;
            }
        }
        // reduce ssum within each half (width 16)
#pragma unroll
        for (int o = 8; o; o >>= 1) ssum += __shfl_xor_sync(FULL, ssum, o, 16);
        float inv = (ssum > 0.f) ? 1.f / ssum : 0.f;
        float4 o4;
        o4.x = eluf(acc.x * inv + bv.x);
        o4.y = eluf(acc.y * inv + bv.y);
        o4.z = eluf(acc.z * inv + bv.z);
        o4.w = eluf(acc.w * inv + bv.w);
        *(float4*)&hs[r][lane * 4] = o4;
    }
    __syncthreads();

    // ---- phase B: gemm2 ([ft2 | res] = h1 @ [W2 | Wres]) + eler2 ----
    int c = t & 31, g = t >> 5;
    float acc2[4] = {0.f, 0.f, 0.f, 0.f};
    for (int k = 0; k < F1; k += 4) {
        float w0 = g_Wc[k * 32 + c];
        float w1 = g_Wc[(k + 1) * 32 + c];
        float w2 = g_Wc[(k + 2) * 32 + c];
        float w3 = g_Wc[(k + 3) * 32 + c];
#pragma unroll
        for (int rr = 0; rr < 4; rr++) {
            float4 hv = *(const float4*)&hs[g * 4 + rr][k];
            acc2[rr] += hv.x * w0 + hv.y * w1 + hv.z * w2 + hv.w * w3;
        }
    }
    float a2 = (c < 16) ? al2[c] : 0.f;
    float r2v = (c < 16) ? ar2[c] : 0.f;
#pragma unroll
    for (int rr = 0; rr < 4; rr++) {
        int row = row0 + g * 4 + rr;
        if (row < n) {
            if (c < 16) g_ft2h[row * 16 + c] = __float2half(acc2[rr]);
            else        g_res[row * 16 + (c - 16)] = acc2[rr];
        }
        float el = acc2[rr] * a2, er = acc2[rr] * r2v;
#pragma unroll
        for (int o = 8; o; o >>= 1) {
            el += __shfl_xor_sync(FULL, el, o);
            er += __shfl_xor_sync(FULL, er, o);
        }
        if (c == 0 && row < n) {
            g_el2[row] = el;
            g_er2[row] = er;
        }
    }
}

// -------- layer-2 agg: two nodes per warp, ONE shfl per edge ------
__global__ void agg2_kernel(const float* __restrict__ b2,
                            float* __restrict__ out,
                            float* __restrict__ out_alpha,
                            int n, int write_alpha) {
    int warp = (blockIdx.x * blockDim.x + threadIdx.x) >> 5;
    int lane = threadIdx.x & 31;
    int half = lane >> 4;
    int l = lane & 15;
    int node = warp * 2 + half;
    if (node >= n) return;
    unsigned mask = 0xFFFFu << (half * 16);
    int beg = g_rowptr[node], end = g_rowptr[node + 1];
    float er = g_er2[node];

    float acc = 0.f, ssum = 0.f;
    float exc0 = 0.f, exc1 = 0.f;
    int c = 0;
    for (int base = beg; base < end; base += 16, c++) {
        int k = base + l;
        unsigned pk = 0;
        float ex = 0.f;
        if (k < end) {
            int sidx = g_edge[k].x;
            ex = __expf(lrelu(g_el2[sidx] + er));
            ssum += ex;
            pk = (unsigned)sidx |
                 ((unsigned)__half_as_ushort(__float2half_rn(ex)) << 16);
        }
        if (c == 0) exc0 = ex; else if (c == 1) exc1 = ex;
        int cnt = min(16, end - base);
#pragma unroll 8
        for (int j = 0; j < cnt; j++) {
            unsigned p = __shfl_sync(mask, pk, j, 16);
            int sj = (int)(p & 0xFFFFu);
            float x = __half2float(__ushort_as_half((unsigned short)(p >> 16)));
            acc += x * __half2float(g_ft2h[sj * 16 + l]);
        }
    }
#pragma unroll
    for (int o = 8; o; o >>= 1) ssum += __shfl_xor_sync(mask, ssum, o);
    float inv = (ssum > 0.f) ? 1.f / ssum : 0.f;
    out[node * 16 + l] = acc * inv + b2[l] + g_res[node * 16 + l];
    if (write_alpha) {
        c = 0;
        for (int base = beg; base < end; base += 16, c++) {
            int k = base + l;
            if (k < end) {
                float ex;
                if (c == 0)      ex = exc0;
                else if (c == 1) ex = exc1;
                else             ex = __expf(lrelu(g_el2[g_edge[k].x] + er));
                out_alpha[g_edge[k].y] = ex * inv;
            }
        }
    }
}

// ---------------- launcher ----------------
extern "C" void kernel_launch(void* const* d_in, const int* in_sizes, int n_in,
                              void* d_out, int out_size) {
    const float* h    = (const float*)d_in[0];
    const int*   src  = (const int*)  d_in[1];
    const int*   dst  = (const int*)  d_in[2];
    const float* W1   = (const float*)d_in[3];
    const float* al1  = (const float*)d_in[4];
    const float* ar1  = (const float*)d_in[5];
    const float* b1   = (const float*)d_in[6];
    const float* W2   = (const float*)d_in[7];
    const float* al2  = (const float*)d_in[8];
    const float* ar2  = (const float*)d_in[9];
    const float* b2   = (const float*)d_in[10];
    const float* Wres = (const float*)d_in[11];
    float* out = (float*)d_out;

    int n = in_sizes[0] / F1;
    int e = in_sizes[1];
    if (n > N_MAX || e > E_MAX) return;

    const int T = 256;
    int write_alpha = (out_size >= n * 16 + e) ? 1 : 0;

    static cudaStream_t s_side = nullptr;
    static cudaEvent_t ev_fork = nullptr, ev_join = nullptr;
    if (s_side == nullptr) {
        cudaStreamCreateWithFlags(&s_side, cudaStreamNonBlocking);
        cudaEventCreateWithFlags(&ev_fork, cudaEventDisableTiming);
        cudaEventCreateWithFlags(&ev_join, cudaEventDisableTiming);
    }

    // fork: pack + gemm1 on side stream (independent of CSR build)
    cudaEventRecord(ev_fork, 0);
    cudaStreamWaitEvent(s_side, ev_fork, 0);
    pack_kernel<<<(F1 * F1 + T - 1) / T, T, 0, s_side>>>(W1, W2, Wres);
    gemm1_wmma<<<(n + 31) / 32, 256, 0, s_side>>>(h, al1, ar1, n);
    cudaEventRecord(ev_join, s_side);

    // main chain: CSR build
    int nb = (n + SCAN_B - 1) / SCAN_B;
    deg_kernel<<<(e + 4 * T - 1) / (4 * T), T>>>(dst, e);
    scan_local<<<nb, SCAN_B>>>(n);
    scan_add<<<(n + 1 + T - 1) / T, T>>>(n, e, nb);
    scatter_kernel<<<(e + 2 * T - 1) / (2 * T), T>>>(src, dst, e);

    // join, then dependent chain
    cudaStreamWaitEvent(0, ev_join, 0);
    l2_fused_kernel<<<(n + 15) / 16, 128>>>(b1, al2, ar2, n);
    agg2_kernel<<<((long long)((n + 1) / 2) * 32 + T - 1) / T, T>>>(
        b2, out, out + n * 16, n, write_alpha);
}